// round 3
// baseline (speedup 1.0000x reference)
#include <cuda_runtime.h>
#include <math.h>

#define BB 4
#define SSQ 2048
#define DIM 1024
#define NH 16
#define HD 64
#define MROWS (BB*SSQ)       // 8192
#define NQKV (3*DIM)         // 3072

__device__ float g_qkv[(size_t)MROWS * NQKV];   // 96 MB scratch
__device__ float g_att[(size_t)MROWS * DIM];    // 32 MB scratch
__device__ float g_cos[SSQ * 32];
__device__ float g_sin[SSQ * 32];

// ---------------------------------------------------------------------------
// SGEMM: C[M,N] = A[M,K] @ B[N,K]^T  (kept verbatim from R0 for differential
// diagnosis: this stage is intentionally unchanged this round)
// ---------------------------------------------------------------------------
__global__ __launch_bounds__(256, 1) void sgemm_nt(
    const float* __restrict__ A, const float* __restrict__ Bw,
    float* __restrict__ C, int M, int N, int K)
{
    __shared__ float As[16][132];
    __shared__ float Bs[16][132];
    const int tid = threadIdx.x;
    const int bm = blockIdx.y * 128;
    const int bn = blockIdx.x * 128;
    const int tx = tid & 15;
    const int ty = tid >> 4;

    float acc[8][8];
#pragma unroll
    for (int i = 0; i < 8; i++)
#pragma unroll
        for (int j = 0; j < 8; j++) acc[i][j] = 0.f;

    const float* Ab = A + (size_t)bm * K;
    const float* Bb = Bw + (size_t)bn * K;

    for (int k0 = 0; k0 < K; k0 += 16) {
#pragma unroll
        for (int u = 0; u < 2; u++) {
            int f = u * 256 + tid;
            int row = f >> 2;
            int c4 = (f & 3) * 4;
            float4 va = *(const float4*)(Ab + (size_t)row * K + k0 + c4);
            As[c4 + 0][row] = va.x; As[c4 + 1][row] = va.y;
            As[c4 + 2][row] = va.z; As[c4 + 3][row] = va.w;
            float4 vb = *(const float4*)(Bb + (size_t)row * K + k0 + c4);
            Bs[c4 + 0][row] = vb.x; Bs[c4 + 1][row] = vb.y;
            Bs[c4 + 2][row] = vb.z; Bs[c4 + 3][row] = vb.w;
        }
        __syncthreads();
#pragma unroll
        for (int k = 0; k < 16; k++) {
            float4 a0 = *(const float4*)&As[k][ty * 4];
            float4 a1 = *(const float4*)&As[k][64 + ty * 4];
            float4 b0 = *(const float4*)&Bs[k][tx * 4];
            float4 b1 = *(const float4*)&Bs[k][64 + tx * 4];
            float a[8] = {a0.x, a0.y, a0.z, a0.w, a1.x, a1.y, a1.z, a1.w};
            float b[8] = {b0.x, b0.y, b0.z, b0.w, b1.x, b1.y, b1.z, b1.w};
#pragma unroll
            for (int i = 0; i < 8; i++)
#pragma unroll
                for (int j = 0; j < 8; j++)
                    acc[i][j] = fmaf(a[i], b[j], acc[i][j]);
        }
        __syncthreads();
    }
#pragma unroll
    for (int i = 0; i < 8; i++) {
        int r = bm + ((i < 4) ? (ty * 4 + i) : (64 + ty * 4 + i - 4));
        float4 v0 = make_float4(acc[i][0], acc[i][1], acc[i][2], acc[i][3]);
        float4 v1 = make_float4(acc[i][4], acc[i][5], acc[i][6], acc[i][7]);
        *(float4*)(C + (size_t)r * N + bn + tx * 4) = v0;
        *(float4*)(C + (size_t)r * N + bn + 64 + tx * 4) = v1;
    }
}

// ---------------------------------------------------------------------------
// RoPE tables: angle rounded exactly like the reference (fp32 product),
// cos/sin evaluated in double of that fp32 angle -> <=0.5ulp of ref fp32.
// ---------------------------------------------------------------------------
__global__ void rope_tables()
{
    int idx = blockIdx.x * blockDim.x + threadIdx.x;
    if (idx >= SSQ * 32) return;
    int s = idx >> 5;
    int i = idx & 31;
    double inv_d = exp(-(double)i * (9.210340371976184 / 32.0));
    float  ang_f = (float)s * (float)inv_d;      // fp32 rounding like reference
    double c, sn;
    sincos((double)ang_f, &sn, &c);
    g_cos[idx] = (float)c;
    g_sin[idx] = (float)sn;
}

// Apply: one block per (s, b); 512 threads = 16 heads x 32 pair-indices.
__global__ __launch_bounds__(512) void rope_apply()
{
    int s = blockIdx.x;
    int b = blockIdx.y;
    int h = threadIdx.x >> 5;
    int i = threadIdx.x & 31;

    float c  = g_cos[s * 32 + i];
    float sn = g_sin[s * 32 + i];

    size_t row = ((size_t)(b * SSQ + s)) * NQKV + (size_t)h * HD;
    float q1 = g_qkv[row + i];
    float q2 = g_qkv[row + 32 + i];
    g_qkv[row + i]      = q1 * c - q2 * sn;
    g_qkv[row + 32 + i] = q1 * sn + q2 * c;

    size_t rk = row + DIM;
    float k1 = g_qkv[rk + i];
    float k2 = g_qkv[rk + 32 + i];
    g_qkv[rk + i]      = k1 * c - k2 * sn;
    g_qkv[rk + 32 + i] = k1 * sn + k2 * c;
}

// ---------------------------------------------------------------------------
// Flash attention (causal). Block = 64 queries of one (b,h), 128 threads,
// 2 threads per query (each owns 32 dims). Static smem only (48 KB).
// ---------------------------------------------------------------------------
__global__ __launch_bounds__(128) void attn_kernel()
{
    __shared__ float Ks[64 * 64];
    __shared__ float Vs[64 * 64];
    __shared__ float St[64 * 64];     // St[kk*64 + q_local], transposed scores

    const int tid  = threadIdx.x;
    const int ql   = tid >> 1;        // query within block, 0..63
    const int half = tid & 1;         // which 32-dim half this thread owns
    const int qblk = blockIdx.x;
    const int h    = blockIdx.y;
    const int b    = blockIdx.z;
    const int qi   = qblk * 64 + ql;
    const float* base = g_qkv + (size_t)b * SSQ * NQKV;

    // load this thread's half of q
    float4 q4[8];
    {
        const float4* qp = (const float4*)(base + (size_t)qi * NQKV + h * HD + half * 32);
#pragma unroll
        for (int j = 0; j < 8; j++) q4[j] = qp[j];
    }

    float m = -1e30f, l = 0.f;
    float4 o4[8];
#pragma unroll
    for (int j = 0; j < 8; j++) o4[j] = make_float4(0.f, 0.f, 0.f, 0.f);

    const int ntiles = qblk + 1;      // keys [0, qblk*64 + 64)

    for (int t = 0; t < ntiles; t++) {
        const int k0 = t * 64;
        // load 64x64 K and V tiles: 8 float4 per thread per matrix
#pragma unroll
        for (int r = 0; r < 8; r++) {
            int f = r * 128 + tid;
            int row = f >> 4;
            int c4 = (f & 15) * 4;
            const float* kp = base + (size_t)(k0 + row) * NQKV + DIM + h * HD + c4;
            *(float4*)&Ks[row * 64 + c4] = *(const float4*)kp;
            *(float4*)&Vs[row * 64 + c4] = *(const float4*)(kp + DIM);
        }
        __syncthreads();

        // scores: partial dot over 32 dims, combine across the thread pair
        const float4* K4 = (const float4*)Ks;
        float tmax = -1e30f;
#pragma unroll 4
        for (int kk = 0; kk < 64; kk++) {
            const float4* kr = K4 + kk * 16 + half * 8;
            float c0 = 0.f, c1 = 0.f, c2 = 0.f, c3 = 0.f;
#pragma unroll
            for (int j = 0; j < 8; j++) {
                float4 kv = kr[j];
                c0 = fmaf(q4[j].x, kv.x, c0);
                c1 = fmaf(q4[j].y, kv.y, c1);
                c2 = fmaf(q4[j].z, kv.z, c2);
                c3 = fmaf(q4[j].w, kv.w, c3);
            }
            float part = (c0 + c1) + (c2 + c3);
            float full = part + __shfl_xor_sync(0xFFFFFFFFu, part, 1);
            float sc = full * 0.125f;                 // 1/sqrt(64)
            if (k0 + kk > qi) sc = -1e30f;            // causal
            if (half == 0) St[kk * 64 + ql] = sc;
            tmax = fmaxf(tmax, sc);
        }
        __syncwarp();

        float mnew = fmaxf(m, tmax);
        float corr = __expf(m - mnew);
        l *= corr;
#pragma unroll
        for (int j = 0; j < 8; j++) {
            o4[j].x *= corr; o4[j].y *= corr; o4[j].z *= corr; o4[j].w *= corr;
        }

        const float4* V4 = (const float4*)Vs;
#pragma unroll 4
        for (int kk = 0; kk < 64; kk++) {
            float p = __expf(St[kk * 64 + ql] - mnew);
            l += p;
            const float4* vr = V4 + kk * 16 + half * 8;
#pragma unroll
            for (int j = 0; j < 8; j++) {
                float4 vv = vr[j];
                o4[j].x = fmaf(p, vv.x, o4[j].x);
                o4[j].y = fmaf(p, vv.y, o4[j].y);
                o4[j].z = fmaf(p, vv.z, o4[j].z);
                o4[j].w = fmaf(p, vv.w, o4[j].w);
            }
        }
        m = mnew;
        __syncthreads();
    }

    const float invl = 1.0f / l;
    float4* op = (float4*)(g_att + (size_t)(b * SSQ + qi) * DIM + h * HD + half * 32);
#pragma unroll
    for (int j = 0; j < 8; j++) {
        op[j] = make_float4(o4[j].x * invl, o4[j].y * invl,
                            o4[j].z * invl, o4[j].w * invl);
    }
}

// ---------------------------------------------------------------------------
extern "C" void kernel_launch(void* const* d_in, const int* in_sizes, int n_in,
                              void* d_out, int out_size)
{
    const float* x = nullptr;
    const float* wqkv = nullptr;
    const float* wout = nullptr;
    for (int i = 0; i < n_in; i++) {
        long long n = in_sizes[i];
        if (n == (long long)MROWS * DIM)      x    = (const float*)d_in[i];
        else if (n == (long long)NQKV * DIM)  wqkv = (const float*)d_in[i];
        else if (n == (long long)DIM * DIM)   wout = (const float*)d_in[i];
    }
    if (!x || !wqkv || !wout) return;

    float* qkv = nullptr;
    float* att = nullptr;
    cudaGetSymbolAddress((void**)&qkv, g_qkv);
    cudaGetSymbolAddress((void**)&att, g_att);

    // 1) qkv = x @ Wqkv^T
    dim3 g1(NQKV / 128, MROWS / 128);
    sgemm_nt<<<g1, 256>>>(x, wqkv, qkv, MROWS, NQKV, DIM);

    // 2) RoPE
    rope_tables<<<(SSQ * 32) / 256, 256>>>();
    dim3 gr(SSQ, BB);
    rope_apply<<<gr, 512>>>();

    // 3) flash attention (static smem, no attribute calls)
    dim3 ga(SSQ / 64, NH, BB);
    attn_kernel<<<ga, 128>>>();

    // 4) out = att @ Wout^T
    dim3 g2(DIM / 128, MROWS / 128);
    sgemm_nt<<<g2, 256>>>(att, wout, (float*)d_out, MROWS, DIM, DIM);
}

// round 5
// speedup vs baseline: 2.9510x; 2.9510x over previous
#include <cuda_runtime.h>
#include <cuda_bf16.h>
#include <math.h>
#include <stdint.h>

#define BB 4
#define SSQ 2048
#define DIM 1024
#define NH 16
#define HD 64
#define MROWS (BB*SSQ)       // 8192
#define NQKV (3*DIM)         // 3072

// ---------------- scratch (device globals; allocation-free) ----------------
__device__ float g_qkv[(size_t)MROWS * NQKV];   // 96 MB
__device__ float g_att[(size_t)MROWS * DIM];    // 32 MB
__device__ float g_cos[SSQ * 32];
__device__ float g_sin[SSQ * 32];
__device__ __nv_bfloat16 g_ahi[(size_t)MROWS * DIM];
__device__ __nv_bfloat16 g_alo[(size_t)MROWS * DIM];
__device__ __nv_bfloat16 g_whi[(size_t)NQKV * DIM];
__device__ __nv_bfloat16 g_wlo[(size_t)NQKV * DIM];
__device__ __nv_bfloat16 g_vhi[(size_t)DIM * DIM];
__device__ __nv_bfloat16 g_vlo[(size_t)DIM * DIM];

// ---------------- HMMA helpers (sm_80-era PTX; valid on plain sm_103) ------
__device__ __forceinline__ uint32_t smem_u32(const void* p) {
    uint32_t a;
    asm("{ .reg .u64 t; cvta.to.shared.u64 t, %1; cvt.u32.u64 %0, t; }"
        : "=r"(a) : "l"(p));
    return a;
}
__device__ __forceinline__ void mma16816(float* c, const uint32_t* a, const uint32_t* b) {
    asm volatile(
        "mma.sync.aligned.m16n8k16.row.col.f32.bf16.bf16.f32 "
        "{%0,%1,%2,%3}, {%4,%5,%6,%7}, {%8,%9}, {%0,%1,%2,%3};"
        : "+f"(c[0]), "+f"(c[1]), "+f"(c[2]), "+f"(c[3])
        : "r"(a[0]), "r"(a[1]), "r"(a[2]), "r"(a[3]), "r"(b[0]), "r"(b[1]));
}
__device__ __forceinline__ void ldm4(uint32_t* r, uint32_t addr) {
    asm volatile("ldmatrix.sync.aligned.m8n8.x4.shared.b16 {%0,%1,%2,%3}, [%4];"
                 : "=r"(r[0]), "=r"(r[1]), "=r"(r[2]), "=r"(r[3]) : "r"(addr));
}
__device__ __forceinline__ void ldm4t(uint32_t* r, uint32_t addr) {
    asm volatile("ldmatrix.sync.aligned.m8n8.x4.trans.shared.b16 {%0,%1,%2,%3}, [%4];"
                 : "=r"(r[0]), "=r"(r[1]), "=r"(r[2]), "=r"(r[3]) : "r"(addr));
}
// packs (lo,hi) floats into bf16x2 register: low 16 bits = lo
__device__ __forceinline__ uint32_t pack_bf16x2(float lo, float hi) {
    uint32_t d;
    asm("cvt.rn.bf16x2.f32 %0, %1, %2;" : "=r"(d) : "f"(hi), "f"(lo));
    return d;
}

// ---------------------------------------------------------------------------
// fp32 -> bf16 hi/lo split (4 elems per thread)
// ---------------------------------------------------------------------------
__global__ void cvt_split(const float* __restrict__ in,
                          __nv_bfloat16* __restrict__ hi,
                          __nv_bfloat16* __restrict__ lo, int n4)
{
    int i = blockIdx.x * blockDim.x + threadIdx.x;
    if (i >= n4) return;
    float4 v = ((const float4*)in)[i];
    __nv_bfloat16 hx = __float2bfloat16(v.x);
    __nv_bfloat16 hy = __float2bfloat16(v.y);
    __nv_bfloat16 hz = __float2bfloat16(v.z);
    __nv_bfloat16 hw = __float2bfloat16(v.w);
    __nv_bfloat162* hp = reinterpret_cast<__nv_bfloat162*>(hi);
    __nv_bfloat162* lp = reinterpret_cast<__nv_bfloat162*>(lo);
    hp[2*i]   = __nv_bfloat162(hx, hy);
    hp[2*i+1] = __nv_bfloat162(hz, hw);
    lp[2*i]   = __nv_bfloat162(__float2bfloat16(v.x - __bfloat162float(hx)),
                               __float2bfloat16(v.y - __bfloat162float(hy)));
    lp[2*i+1] = __nv_bfloat162(__float2bfloat16(v.z - __bfloat162float(hz)),
                               __float2bfloat16(v.w - __bfloat162float(hw)));
}

// ---------------------------------------------------------------------------
// HMMA split-3 GEMM: C[M,N] = (Ahi+Alo)[M,K] @ (Bhi+Blo)[N,K]^T (fp32 accum)
// 128x128 tile, 256 threads (8 warps: 4 along M x 2 along N), K-chunk 32.
// smem rows padded to 40 bf16 (80B) -> conflict-free ldmatrix.
// ---------------------------------------------------------------------------
__global__ __launch_bounds__(256, 1) void hgemm_s3(
    const __nv_bfloat16* __restrict__ Ahi, const __nv_bfloat16* __restrict__ Alo,
    const __nv_bfloat16* __restrict__ Bhi, const __nv_bfloat16* __restrict__ Blo,
    float* __restrict__ C, int N, int K)
{
    __shared__ __align__(16) __nv_bfloat16 sA[2][128 * 40];
    __shared__ __align__(16) __nv_bfloat16 sB[2][128 * 40];

    const int tid = threadIdx.x;
    const int lane = tid & 31;
    const int wid = tid >> 5;
    const int wm = wid & 3;          // 0..3 -> 32 rows each
    const int wn = wid >> 2;         // 0..1 -> 64 cols each
    const int bm = blockIdx.y * 128;
    const int bn = blockIdx.x * 128;

    float c[2][8][4];
#pragma unroll
    for (int i = 0; i < 2; i++)
#pragma unroll
        for (int nf = 0; nf < 8; nf++)
#pragma unroll
            for (int e = 0; e < 4; e++) c[i][nf][e] = 0.f;

    const uint32_t sAh = smem_u32(sA[0]);
    const uint32_t sAl = smem_u32(sA[1]);
    const uint32_t sBh = smem_u32(sB[0]);
    const uint32_t sBl = smem_u32(sB[1]);

    for (int ck = 0; ck < K / 32; ck++) {
        // stage 4 matrices: 128 rows x 32 bf16 each (512 uint4 per matrix)
#pragma unroll
        for (int i = 0; i < 8; i++) {
            int g = i * 256 + tid;
            int mat = g >> 9;
            int idx = g & 511;
            int row = idx >> 2;
            int c8 = (idx & 3) * 8;
            const __nv_bfloat16* src =
                (mat == 0) ? (Ahi + (size_t)(bm + row) * K) :
                (mat == 1) ? (Alo + (size_t)(bm + row) * K) :
                (mat == 2) ? (Bhi + (size_t)(bn + row) * K) :
                             (Blo + (size_t)(bn + row) * K);
            uint4 v = *(const uint4*)(src + ck * 32 + c8);
            __nv_bfloat16* dst =
                (mat == 0) ? sA[0] : (mat == 1) ? sA[1] : (mat == 2) ? sB[0] : sB[1];
            *(uint4*)(dst + row * 40 + c8) = v;
        }
        __syncthreads();

#pragma unroll
        for (int ks = 0; ks < 2; ks++) {
            uint32_t ah[2][4], al[2][4];
#pragma unroll
            for (int i = 0; i < 2; i++) {
                int row = wm * 32 + i * 16 + (lane & 15);
                int col = ks * 16 + (lane >> 4) * 8;
                uint32_t off = (uint32_t)(row * 80 + col * 2);
                ldm4(ah[i], sAh + off);
                ldm4(al[i], sAl + off);
            }
#pragma unroll
            for (int nfp = 0; nfp < 4; nfp++) {
                int g = lane >> 3;
                int row = wn * 64 + nfp * 16 + ((g >= 2) ? 8 : 0) + (lane & 7);
                int col = ks * 16 + ((g & 1) ? 8 : 0);
                uint32_t off = (uint32_t)(row * 80 + col * 2);
                uint32_t bh[4], bl[4];
                ldm4(bh, sBh + off);
                ldm4(bl, sBl + off);
#pragma unroll
                for (int i = 0; i < 2; i++) {
                    mma16816(c[i][2*nfp],   ah[i], bh);
                    mma16816(c[i][2*nfp],   ah[i], bl);
                    mma16816(c[i][2*nfp],   al[i], bh);
                    mma16816(c[i][2*nfp+1], ah[i], bh + 2);
                    mma16816(c[i][2*nfp+1], ah[i], bl + 2);
                    mma16816(c[i][2*nfp+1], al[i], bh + 2);
                }
            }
        }
        __syncthreads();
    }

#pragma unroll
    for (int i = 0; i < 2; i++) {
#pragma unroll
        for (int nf = 0; nf < 8; nf++) {
            int row = bm + wm * 32 + i * 16 + (lane >> 2);
            int col = bn + wn * 64 + nf * 8 + (lane & 3) * 2;
            *(float2*)(C + (size_t)row * N + col) = make_float2(c[i][nf][0], c[i][nf][1]);
            *(float2*)(C + (size_t)(row + 8) * N + col) = make_float2(c[i][nf][2], c[i][nf][3]);
        }
    }
}

// ---------------------------------------------------------------------------
// RoPE (verified R2)
// ---------------------------------------------------------------------------
__global__ void rope_tables()
{
    int idx = blockIdx.x * blockDim.x + threadIdx.x;
    if (idx >= SSQ * 32) return;
    int s = idx >> 5;
    int i = idx & 31;
    double inv_d = exp(-(double)i * (9.210340371976184 / 32.0));
    float  ang_f = (float)s * (float)inv_d;
    double c, sn;
    sincos((double)ang_f, &sn, &c);
    g_cos[idx] = (float)c;
    g_sin[idx] = (float)sn;
}

__global__ __launch_bounds__(512) void rope_apply()
{
    int s = blockIdx.x;
    int b = blockIdx.y;
    int h = threadIdx.x >> 5;
    int i = threadIdx.x & 31;

    float c  = g_cos[s * 32 + i];
    float sn = g_sin[s * 32 + i];

    size_t row = ((size_t)(b * SSQ + s)) * NQKV + (size_t)h * HD;
    float q1 = g_qkv[row + i];
    float q2 = g_qkv[row + 32 + i];
    g_qkv[row + i]      = q1 * c - q2 * sn;
    g_qkv[row + 32 + i] = q1 * sn + q2 * c;

    size_t rk = row + DIM;
    float k1 = g_qkv[rk + i];
    float k2 = g_qkv[rk + 32 + i];
    g_qkv[rk + i]      = k1 * c - k2 * sn;
    g_qkv[rk + 32 + i] = k1 * sn + k2 * c;
}

// ---------------------------------------------------------------------------
// HMMA flash attention (causal).
// Block = 128 queries of one (b,h), 256 threads (8 warps x 16 query rows).
// QK^T: bf16 split-3. PV: P split-2 x V split-2 (3 mma terms).
// K/V staged per 64-key tile in smem (rows padded to 72 bf16 = 144B).
// P fragments feed PV mma directly from registers.
// ---------------------------------------------------------------------------
#define AST 72   // padded row stride (bf16 elems)

__global__ __launch_bounds__(256, 1) void attn_tc()
{
    __shared__ __align__(16) char sm[36864];
    // staging overlay: Q phase: Qh @0 (18432), Ql @18432
    //                  KV phase: Kh @0, Kl @9216, Vh @18432, Vl @27648
    __nv_bfloat16* Qh = (__nv_bfloat16*)sm;
    __nv_bfloat16* Ql = (__nv_bfloat16*)(sm + 18432);
    __nv_bfloat16* Kh = (__nv_bfloat16*)sm;
    __nv_bfloat16* Kl = (__nv_bfloat16*)(sm + 9216);
    __nv_bfloat16* Vh = (__nv_bfloat16*)(sm + 18432);
    __nv_bfloat16* Vl = (__nv_bfloat16*)(sm + 27648);

    const int tid  = threadIdx.x;
    const int lane = tid & 31;
    const int wid  = tid >> 5;
    const int qb   = blockIdx.x;          // 0..15
    const int h    = blockIdx.y;
    const int b    = blockIdx.z;
    const float* base = g_qkv + (size_t)b * SSQ * NQKV;

    // ---- stage Q (128 x 64), scaled by 1/sqrt(64), split hi/lo ----
#pragma unroll
    for (int i = 0; i < 8; i++) {
        int g = i * 256 + tid;
        int row = g >> 4;
        int c4 = (g & 15) * 4;
        float4 v = *(const float4*)(base + (size_t)(qb * 128 + row) * NQKV + h * HD + c4);
        v.x *= 0.125f; v.y *= 0.125f; v.z *= 0.125f; v.w *= 0.125f;
        __nv_bfloat16 hx = __float2bfloat16(v.x), hy = __float2bfloat16(v.y);
        __nv_bfloat16 hz = __float2bfloat16(v.z), hw = __float2bfloat16(v.w);
        __nv_bfloat162* qh2 = (__nv_bfloat162*)(Qh + row * AST + c4);
        __nv_bfloat162* ql2 = (__nv_bfloat162*)(Ql + row * AST + c4);
        qh2[0] = __nv_bfloat162(hx, hy);
        qh2[1] = __nv_bfloat162(hz, hw);
        ql2[0] = __nv_bfloat162(__float2bfloat16(v.x - __bfloat162float(hx)),
                                __float2bfloat16(v.y - __bfloat162float(hy)));
        ql2[1] = __nv_bfloat162(__float2bfloat16(v.z - __bfloat162float(hz)),
                                __float2bfloat16(v.w - __bfloat162float(hw)));
    }
    __syncthreads();

    // ---- extract Q fragments (A-frags for 4 k16 steps, hi and lo) ----
    uint32_t qh[4][4], ql[4][4];
    {
        const uint32_t sQh = smem_u32(Qh);
        const uint32_t sQl = smem_u32(Ql);
#pragma unroll
        for (int ks = 0; ks < 4; ks++) {
            int row = wid * 16 + (lane & 15);
            int col = ks * 16 + (lane >> 4) * 8;
            uint32_t off = (uint32_t)(row * (AST * 2) + col * 2);
            ldm4(qh[ks], sQh + off);
            ldm4(ql[ks], sQl + off);
        }
    }

    float m0 = -1e30f, m1 = -1e30f, l0 = 0.f, l1 = 0.f;
    float o[8][4];
#pragma unroll
    for (int df = 0; df < 8; df++)
#pragma unroll
        for (int e = 0; e < 4; e++) o[df][e] = 0.f;

    const int qi0 = qb * 128 + wid * 16 + (lane >> 2);
    const int qi1 = qi0 + 8;
    const int ntiles = 2 * qb + 2;

    const uint32_t sKh = smem_u32(Kh);
    const uint32_t sKl = smem_u32(Kl);
    const uint32_t sVh = smem_u32(Vh);
    const uint32_t sVl = smem_u32(Vl);

    for (int kt = 0; kt < ntiles; kt++) {
        __syncthreads();   // previous tile's ldmatrix reads done (and Q extraction)
        // ---- stage K, V (64 x 64 each), split hi/lo ----
#pragma unroll
        for (int i = 0; i < 4; i++) {
            int g = i * 256 + tid;
            int row = g >> 4;
            int c4 = (g & 15) * 4;
            const float* kp = base + (size_t)(kt * 64 + row) * NQKV + DIM + h * HD + c4;
            float4 kv = *(const float4*)kp;
            float4 vv = *(const float4*)(kp + DIM);
            {
                __nv_bfloat16 hx = __float2bfloat16(kv.x), hy = __float2bfloat16(kv.y);
                __nv_bfloat16 hz = __float2bfloat16(kv.z), hw = __float2bfloat16(kv.w);
                __nv_bfloat162* d2 = (__nv_bfloat162*)(Kh + row * AST + c4);
                __nv_bfloat162* l2 = (__nv_bfloat162*)(Kl + row * AST + c4);
                d2[0] = __nv_bfloat162(hx, hy); d2[1] = __nv_bfloat162(hz, hw);
                l2[0] = __nv_bfloat162(__float2bfloat16(kv.x - __bfloat162float(hx)),
                                       __float2bfloat16(kv.y - __bfloat162float(hy)));
                l2[1] = __nv_bfloat162(__float2bfloat16(kv.z - __bfloat162float(hz)),
                                       __float2bfloat16(kv.w - __bfloat162float(hw)));
            }
            {
                __nv_bfloat16 hx = __float2bfloat16(vv.x), hy = __float2bfloat16(vv.y);
                __nv_bfloat16 hz = __float2bfloat16(vv.z), hw = __float2bfloat16(vv.w);
                __nv_bfloat162* d2 = (__nv_bfloat162*)(Vh + row * AST + c4);
                __nv_bfloat162* l2 = (__nv_bfloat162*)(Vl + row * AST + c4);
                d2[0] = __nv_bfloat162(hx, hy); d2[1] = __nv_bfloat162(hz, hw);
                l2[0] = __nv_bfloat162(__float2bfloat16(vv.x - __bfloat162float(hx)),
                                       __float2bfloat16(vv.y - __bfloat162float(hy)));
                l2[1] = __nv_bfloat162(__float2bfloat16(vv.z - __bfloat162float(hz)),
                                       __float2bfloat16(vv.w - __bfloat162float(hw)));
            }
        }
        __syncthreads();

        // ---- scores: S(16x64) = Q(16x64) @ K(64x64)^T, split-3 ----
        float s[8][4];
#pragma unroll
        for (int nf = 0; nf < 8; nf++)
#pragma unroll
            for (int e = 0; e < 4; e++) s[nf][e] = 0.f;

#pragma unroll
        for (int ks = 0; ks < 4; ks++) {
#pragma unroll
            for (int nfp = 0; nfp < 4; nfp++) {
                int g = lane >> 3;
                int row = nfp * 16 + ((g >= 2) ? 8 : 0) + (lane & 7);   // key index
                int col = ks * 16 + ((g & 1) ? 8 : 0);                  // d index
                uint32_t off = (uint32_t)(row * (AST * 2) + col * 2);
                uint32_t bh[4], bl[4];
                ldm4(bh, sKh + off);
                ldm4(bl, sKl + off);
                mma16816(s[2*nfp],   qh[ks], bh);
                mma16816(s[2*nfp],   qh[ks], bl);
                mma16816(s[2*nfp],   ql[ks], bh);
                mma16816(s[2*nfp+1], qh[ks], bh + 2);
                mma16816(s[2*nfp+1], qh[ks], bl + 2);
                mma16816(s[2*nfp+1], ql[ks], bh + 2);
            }
        }

        // ---- causal mask (only possibly-diagonal tiles) ----
        if (kt >= 2 * qb) {
            int kbase = kt * 64 + (lane & 3) * 2;
#pragma unroll
            for (int nf = 0; nf < 8; nf++) {
                int kj = kbase + nf * 8;
                if (kj     > qi0) s[nf][0] = -1e30f;
                if (kj + 1 > qi0) s[nf][1] = -1e30f;
                if (kj     > qi1) s[nf][2] = -1e30f;
                if (kj + 1 > qi1) s[nf][3] = -1e30f;
            }
        }

        // ---- online softmax on fragments ----
        float rmax0 = -1e30f, rmax1 = -1e30f;
#pragma unroll
        for (int nf = 0; nf < 8; nf++) {
            rmax0 = fmaxf(rmax0, fmaxf(s[nf][0], s[nf][1]));
            rmax1 = fmaxf(rmax1, fmaxf(s[nf][2], s[nf][3]));
        }
        rmax0 = fmaxf(rmax0, __shfl_xor_sync(0xFFFFFFFFu, rmax0, 1));
        rmax0 = fmaxf(rmax0, __shfl_xor_sync(0xFFFFFFFFu, rmax0, 2));
        rmax1 = fmaxf(rmax1, __shfl_xor_sync(0xFFFFFFFFu, rmax1, 1));
        rmax1 = fmaxf(rmax1, __shfl_xor_sync(0xFFFFFFFFu, rmax1, 2));

        float mn0 = fmaxf(m0, rmax0);
        float mn1 = fmaxf(m1, rmax1);
        float corr0 = __expf(m0 - mn0);
        float corr1 = __expf(m1 - mn1);
        m0 = mn0; m1 = mn1;
        l0 *= corr0; l1 *= corr1;
#pragma unroll
        for (int df = 0; df < 8; df++) {
            o[df][0] *= corr0; o[df][1] *= corr0;
            o[df][2] *= corr1; o[df][3] *= corr1;
        }

        // p = exp(s - m), split into bf16 hi/lo, packed as PV A-fragments
        uint32_t ph01[8], ph23[8], pl01[8], pl23[8];
#pragma unroll
        for (int nf = 0; nf < 8; nf++) {
            float p0 = __expf(s[nf][0] - m0);
            float p1 = __expf(s[nf][1] - m0);
            float p2 = __expf(s[nf][2] - m1);
            float p3 = __expf(s[nf][3] - m1);
            l0 += p0 + p1;
            l1 += p2 + p3;
            float h0 = __bfloat162float(__float2bfloat16(p0));
            float h1 = __bfloat162float(__float2bfloat16(p1));
            float h2 = __bfloat162float(__float2bfloat16(p2));
            float h3 = __bfloat162float(__float2bfloat16(p3));
            ph01[nf] = pack_bf16x2(h0, h1);
            ph23[nf] = pack_bf16x2(h2, h3);
            pl01[nf] = pack_bf16x2(p0 - h0, p1 - h1);
            pl23[nf] = pack_bf16x2(p2 - h2, p3 - h3);
        }

        // ---- O += P @ V : P split-2 x V split-2 (drop plo*vlo) ----
#pragma unroll
        for (int ks = 0; ks < 4; ks++) {
            uint32_t aPh[4] = {ph01[2*ks], ph23[2*ks], ph01[2*ks+1], ph23[2*ks+1]};
            uint32_t aPl[4] = {pl01[2*ks], pl23[2*ks], pl01[2*ks+1], pl23[2*ks+1]};
#pragma unroll
            for (int dfp = 0; dfp < 4; dfp++) {
                int g = lane >> 3;
                int row = ks * 16 + ((g & 1) ? 8 : 0) + (lane & 7);    // key index
                int col = dfp * 16 + ((g >= 2) ? 8 : 0);               // d index
                uint32_t off = (uint32_t)(row * (AST * 2) + col * 2);
                uint32_t bv[4], bvl[4];
                ldm4t(bv,  sVh + off);
                ldm4t(bvl, sVl + off);
                mma16816(o[2*dfp],   aPh, bv);
                mma16816(o[2*dfp],   aPh, bvl);
                mma16816(o[2*dfp],   aPl, bv);
                mma16816(o[2*dfp+1], aPh, bv + 2);
                mma16816(o[2*dfp+1], aPh, bvl + 2);
                mma16816(o[2*dfp+1], aPl, bv + 2);
            }
        }
    }

    // ---- finalize: reduce l over quad, normalize, store ----
    l0 += __shfl_xor_sync(0xFFFFFFFFu, l0, 1);
    l0 += __shfl_xor_sync(0xFFFFFFFFu, l0, 2);
    l1 += __shfl_xor_sync(0xFFFFFFFFu, l1, 1);
    l1 += __shfl_xor_sync(0xFFFFFFFFu, l1, 2);
    float inv0 = 1.0f / l0;
    float inv1 = 1.0f / l1;

#pragma unroll
    for (int df = 0; df < 8; df++) {
        int col = h * HD + df * 8 + (lane & 3) * 2;
        *(float2*)(g_att + (size_t)(b * SSQ + qi0) * DIM + col) =
            make_float2(o[df][0] * inv0, o[df][1] * inv0);
        *(float2*)(g_att + (size_t)(b * SSQ + qi1) * DIM + col) =
            make_float2(o[df][2] * inv1, o[df][3] * inv1);
    }
}

// ---------------------------------------------------------------------------
extern "C" void kernel_launch(void* const* d_in, const int* in_sizes, int n_in,
                              void* d_out, int out_size)
{
    const float* x = nullptr;
    const float* wqkv = nullptr;
    const float* wout = nullptr;
    for (int i = 0; i < n_in; i++) {
        long long n = in_sizes[i];
        if (n == (long long)MROWS * DIM)      x    = (const float*)d_in[i];
        else if (n == (long long)NQKV * DIM)  wqkv = (const float*)d_in[i];
        else if (n == (long long)DIM * DIM)   wout = (const float*)d_in[i];
    }
    if (!x || !wqkv || !wout) return;

    float* qkv = nullptr; float* att = nullptr;
    __nv_bfloat16 *ahi, *alo, *whi, *wlo, *vhi, *vlo;
    cudaGetSymbolAddress((void**)&qkv, g_qkv);
    cudaGetSymbolAddress((void**)&att, g_att);
    cudaGetSymbolAddress((void**)&ahi, g_ahi);
    cudaGetSymbolAddress((void**)&alo, g_alo);
    cudaGetSymbolAddress((void**)&whi, g_whi);
    cudaGetSymbolAddress((void**)&wlo, g_wlo);
    cudaGetSymbolAddress((void**)&vhi, g_vhi);
    cudaGetSymbolAddress((void**)&vlo, g_vlo);

    // 0) bf16 hi/lo splits
    cvt_split<<<(MROWS * DIM / 4 + 255) / 256, 256>>>(x, ahi, alo, MROWS * DIM / 4);
    cvt_split<<<(NQKV * DIM / 4 + 255) / 256, 256>>>(wqkv, whi, wlo, NQKV * DIM / 4);
    cvt_split<<<(DIM * DIM / 4 + 255) / 256, 256>>>(wout, vhi, vlo, DIM * DIM / 4);

    // 1) qkv = x @ Wqkv^T  (HMMA split-3)
    dim3 g1(NQKV / 128, MROWS / 128);
    hgemm_s3<<<g1, 256>>>(ahi, alo, whi, wlo, qkv, NQKV, DIM);

    // 2) RoPE
    rope_tables<<<(SSQ * 32) / 256, 256>>>();
    dim3 gr(SSQ, BB);
    rope_apply<<<gr, 512>>>();

    // 3) HMMA flash attention
    dim3 ga(SSQ / 128, NH, BB);
    attn_tc<<<ga, 256>>>();

    // 4) out = att @ Wout^T  (HMMA split-3)
    cvt_split<<<(MROWS * DIM / 4 + 255) / 256, 256>>>(att, ahi, alo, MROWS * DIM / 4);
    dim3 g2(DIM / 128, MROWS / 128);
    hgemm_s3<<<g2, 256>>>(ahi, alo, vhi, vlo, (float*)d_out, DIM, DIM);
}

// round 6
// speedup vs baseline: 3.4212x; 1.1593x over previous
#include <cuda_runtime.h>
#include <cuda_bf16.h>
#include <math.h>
#include <stdint.h>

#define BB 4
#define SSQ 2048
#define DIM 1024
#define NH 16
#define HD 64
#define MROWS (BB*SSQ)       // 8192
#define NQKV (3*DIM)         // 3072
#define HEADS_ELEMS ((size_t)BB * NH * SSQ * HD)   // 8.4M

// ---------------- scratch (device globals; allocation-free) ----------------
__device__ float g_qkv[(size_t)MROWS * NQKV];   // 96 MB (fp32 qkv after GEMM1)
__device__ float g_cos[SSQ * 32];
__device__ float g_sin[SSQ * 32];
__device__ __nv_bfloat16 g_ahi[(size_t)MROWS * DIM];   // GEMM A operand hi/lo
__device__ __nv_bfloat16 g_alo[(size_t)MROWS * DIM];
__device__ __nv_bfloat16 g_whi[(size_t)NQKV * DIM];
__device__ __nv_bfloat16 g_wlo[(size_t)NQKV * DIM];
__device__ __nv_bfloat16 g_vhi[(size_t)DIM * DIM];
__device__ __nv_bfloat16 g_vlo[(size_t)DIM * DIM];
// pre-split, rope'd, head-contiguous q/k/v: [b,h,s,d]
__device__ __nv_bfloat16 g_qh[HEADS_ELEMS], g_ql[HEADS_ELEMS];
__device__ __nv_bfloat16 g_kh[HEADS_ELEMS], g_kl[HEADS_ELEMS];
__device__ __nv_bfloat16 g_vh[HEADS_ELEMS], g_vl[HEADS_ELEMS];

// ---------------- PTX helpers (plain sm_103-safe) ---------------------------
__device__ __forceinline__ uint32_t smem_u32(const void* p) {
    uint32_t a;
    asm("{ .reg .u64 t; cvta.to.shared.u64 t, %1; cvt.u32.u64 %0, t; }"
        : "=r"(a) : "l"(p));
    return a;
}
__device__ __forceinline__ void mma16816(float* c, const uint32_t* a, const uint32_t* b) {
    asm volatile(
        "mma.sync.aligned.m16n8k16.row.col.f32.bf16.bf16.f32 "
        "{%0,%1,%2,%3}, {%4,%5,%6,%7}, {%8,%9}, {%0,%1,%2,%3};"
        : "+f"(c[0]), "+f"(c[1]), "+f"(c[2]), "+f"(c[3])
        : "r"(a[0]), "r"(a[1]), "r"(a[2]), "r"(a[3]), "r"(b[0]), "r"(b[1]));
}
__device__ __forceinline__ void ldm4(uint32_t* r, uint32_t addr) {
    asm volatile("ldmatrix.sync.aligned.m8n8.x4.shared.b16 {%0,%1,%2,%3}, [%4];"
                 : "=r"(r[0]), "=r"(r[1]), "=r"(r[2]), "=r"(r[3]) : "r"(addr));
}
__device__ __forceinline__ void ldm4t(uint32_t* r, uint32_t addr) {
    asm volatile("ldmatrix.sync.aligned.m8n8.x4.trans.shared.b16 {%0,%1,%2,%3}, [%4];"
                 : "=r"(r[0]), "=r"(r[1]), "=r"(r[2]), "=r"(r[3]) : "r"(addr));
}
__device__ __forceinline__ uint32_t pack_bf16x2(float lo, float hi) {
    uint32_t d;
    asm("cvt.rn.bf16x2.f32 %0, %1, %2;" : "=r"(d) : "f"(hi), "f"(lo));
    return d;
}
__device__ __forceinline__ void cpa16(uint32_t dst, const void* src) {
    asm volatile("cp.async.cg.shared.global [%0], [%1], 16;"
                 :: "r"(dst), "l"(src) : "memory");
}
__device__ __forceinline__ void cpa_commit() {
    asm volatile("cp.async.commit_group;" ::: "memory");
}
template <int N>
__device__ __forceinline__ void cpa_wait() {
    asm volatile("cp.async.wait_group %0;" :: "n"(N) : "memory");
}

// ---------------------------------------------------------------------------
// fp32 -> bf16 hi/lo split (4 elems per thread)
// ---------------------------------------------------------------------------
__global__ void cvt_split(const float* __restrict__ in,
                          __nv_bfloat16* __restrict__ hi,
                          __nv_bfloat16* __restrict__ lo, int n4)
{
    int i = blockIdx.x * blockDim.x + threadIdx.x;
    if (i >= n4) return;
    float4 v = ((const float4*)in)[i];
    __nv_bfloat16 hx = __float2bfloat16(v.x);
    __nv_bfloat16 hy = __float2bfloat16(v.y);
    __nv_bfloat16 hz = __float2bfloat16(v.z);
    __nv_bfloat16 hw = __float2bfloat16(v.w);
    __nv_bfloat162* hp = reinterpret_cast<__nv_bfloat162*>(hi);
    __nv_bfloat162* lp = reinterpret_cast<__nv_bfloat162*>(lo);
    hp[2*i]   = __nv_bfloat162(hx, hy);
    hp[2*i+1] = __nv_bfloat162(hz, hw);
    lp[2*i]   = __nv_bfloat162(__float2bfloat16(v.x - __bfloat162float(hx)),
                               __float2bfloat16(v.y - __bfloat162float(hy)));
    lp[2*i+1] = __nv_bfloat162(__float2bfloat16(v.z - __bfloat162float(hz)),
                               __float2bfloat16(v.w - __bfloat162float(hw)));
}

// ---------------------------------------------------------------------------
// HMMA split-3 GEMM, cp.async double-buffered.
// C[M,N] = (Ahi+Alo)[M,K] @ (Bhi+Blo)[N,K]^T (fp32 accum)
// 128x128 tile, 256 threads (8 warps: 4 M x 2 N), K-chunk 32.
// Dynamic smem: 2 stages x 4 matrices x (128 rows x 40 bf16) = 81920 B.
// ---------------------------------------------------------------------------
#define GST 40960   // stage stride bytes
#define GEMM_SMEM (2 * GST)

__global__ __launch_bounds__(256, 1) void hgemm_s3(
    const __nv_bfloat16* __restrict__ Ahi, const __nv_bfloat16* __restrict__ Alo,
    const __nv_bfloat16* __restrict__ Bhi, const __nv_bfloat16* __restrict__ Blo,
    float* __restrict__ C, int N, int K)
{
    extern __shared__ __align__(16) char dsm[];
    const uint32_t sb = smem_u32(dsm);
    const int tid = threadIdx.x;
    const int lane = tid & 31;
    const int wid = tid >> 5;
    const int wm = wid & 3;
    const int wn = wid >> 2;
    const int bm = blockIdx.y * 128;
    const int bn = blockIdx.x * 128;

    float c[2][8][4];
#pragma unroll
    for (int i = 0; i < 2; i++)
#pragma unroll
        for (int nf = 0; nf < 8; nf++)
#pragma unroll
            for (int e = 0; e < 4; e++) c[i][nf][e] = 0.f;

    const __nv_bfloat16* srcs[4] = {Ahi, Alo, Bhi, Blo};
    const int rowbase[4] = {bm, bm, bn, bn};

    const int nch = K / 32;

    // ---- prologue: stage chunk 0 into stage 0 ----
#pragma unroll
    for (int i = 0; i < 8; i++) {
        int g = i * 256 + tid;
        int mat = g >> 9;
        int idx = g & 511;
        int row = idx >> 2;
        int c8 = (idx & 3) * 8;
        cpa16(sb + mat * 10240 + row * 80 + c8 * 2,
              srcs[mat] + (size_t)(rowbase[mat] + row) * K + c8);
    }
    cpa_commit();

    for (int ck = 0; ck < nch; ck++) {
        if (ck + 1 < nch) {
            const uint32_t base = sb + ((ck + 1) & 1) * GST;
#pragma unroll
            for (int i = 0; i < 8; i++) {
                int g = i * 256 + tid;
                int mat = g >> 9;
                int idx = g & 511;
                int row = idx >> 2;
                int c8 = (idx & 3) * 8;
                cpa16(base + mat * 10240 + row * 80 + c8 * 2,
                      srcs[mat] + (size_t)(rowbase[mat] + row) * K + (ck + 1) * 32 + c8);
            }
            cpa_commit();
            cpa_wait<1>();
        } else {
            cpa_wait<0>();
        }
        __syncthreads();

        const uint32_t st = sb + (ck & 1) * GST;
        const uint32_t sAh = st, sAl = st + 10240, sBh = st + 20480, sBl = st + 30720;
#pragma unroll
        for (int ks = 0; ks < 2; ks++) {
            uint32_t ah[2][4], al[2][4];
#pragma unroll
            for (int i = 0; i < 2; i++) {
                int row = wm * 32 + i * 16 + (lane & 15);
                int col = ks * 16 + (lane >> 4) * 8;
                uint32_t off = (uint32_t)(row * 80 + col * 2);
                ldm4(ah[i], sAh + off);
                ldm4(al[i], sAl + off);
            }
#pragma unroll
            for (int nfp = 0; nfp < 4; nfp++) {
                int g = lane >> 3;
                int row = wn * 64 + nfp * 16 + ((g >= 2) ? 8 : 0) + (lane & 7);
                int col = ks * 16 + ((g & 1) ? 8 : 0);
                uint32_t off = (uint32_t)(row * 80 + col * 2);
                uint32_t bh[4], bl[4];
                ldm4(bh, sBh + off);
                ldm4(bl, sBl + off);
#pragma unroll
                for (int i = 0; i < 2; i++) {
                    mma16816(c[i][2*nfp],   ah[i], bh);
                    mma16816(c[i][2*nfp],   ah[i], bl);
                    mma16816(c[i][2*nfp],   al[i], bh);
                    mma16816(c[i][2*nfp+1], ah[i], bh + 2);
                    mma16816(c[i][2*nfp+1], ah[i], bl + 2);
                    mma16816(c[i][2*nfp+1], al[i], bh + 2);
                }
            }
        }
        __syncthreads();
    }

#pragma unroll
    for (int i = 0; i < 2; i++) {
#pragma unroll
        for (int nf = 0; nf < 8; nf++) {
            int row = bm + wm * 32 + i * 16 + (lane >> 2);
            int col = bn + wn * 64 + nf * 8 + (lane & 3) * 2;
            *(float2*)(C + (size_t)row * N + col) = make_float2(c[i][nf][0], c[i][nf][1]);
            *(float2*)(C + (size_t)(row + 8) * N + col) = make_float2(c[i][nf][2], c[i][nf][3]);
        }
    }
}

// ---------------------------------------------------------------------------
// RoPE tables (verified)
// ---------------------------------------------------------------------------
__global__ void rope_tables()
{
    int idx = blockIdx.x * blockDim.x + threadIdx.x;
    if (idx >= SSQ * 32) return;
    int s = idx >> 5;
    int i = idx & 31;
    double inv_d = exp(-(double)i * (9.210340371976184 / 32.0));
    float  ang_f = (float)s * (float)inv_d;
    double c, sn;
    sincos((double)ang_f, &sn, &c);
    g_cos[idx] = (float)c;
    g_sin[idx] = (float)sn;
}

__device__ __forceinline__ void split_store(__nv_bfloat16* hi, __nv_bfloat16* lo,
                                            size_t idx, float v)
{
    __nv_bfloat16 h = __float2bfloat16(v);
    hi[idx] = h;
    lo[idx] = __float2bfloat16(v - __bfloat162float(h));
}

// RoPE + split + relayout to [b,h,s,d]. q pre-scaled by 1/sqrt(64).
__global__ __launch_bounds__(512) void rope_split()
{
    int s = blockIdx.x;
    int b = blockIdx.y;
    int h = threadIdx.x >> 5;
    int i = threadIdx.x & 31;

    float c  = g_cos[s * 32 + i];
    float sn = g_sin[s * 32 + i];

    size_t row  = ((size_t)(b * SSQ + s)) * NQKV + (size_t)h * HD;
    size_t orow = ((size_t)((b * NH + h) * SSQ) + s) * HD;

    float q1 = g_qkv[row + i];
    float q2 = g_qkv[row + 32 + i];
    split_store(g_qh, g_ql, orow + i,      (q1 * c - q2 * sn) * 0.125f);
    split_store(g_qh, g_ql, orow + 32 + i, (q1 * sn + q2 * c) * 0.125f);

    float k1 = g_qkv[row + DIM + i];
    float k2 = g_qkv[row + DIM + 32 + i];
    split_store(g_kh, g_kl, orow + i,      k1 * c - k2 * sn);
    split_store(g_kh, g_kl, orow + 32 + i, k1 * sn + k2 * c);

    split_store(g_vh, g_vl, orow + i,      g_qkv[row + 2 * DIM + i]);
    split_store(g_vh, g_vl, orow + 32 + i, g_qkv[row + 2 * DIM + 32 + i]);
}

// ---------------------------------------------------------------------------
// HMMA flash attention (causal), pre-split bf16 inputs, cp.async 2-stage KV.
// Block = 128 queries of one (b,h), 256 threads (8 warps x 16 query rows).
// Dynamic smem: 2 stages x (Kh|Kl|Vh|Vl each 64x72 bf16) = 73728 B.
// Q staged transiently in stage 0 region.
// ---------------------------------------------------------------------------
#define AST 72        // padded row stride (bf16 elems), 144 B
#define KVST 36864    // KV stage stride bytes
#define ATTN_SMEM (2 * KVST)

__global__ __launch_bounds__(256, 1) void attn_tc()
{
    extern __shared__ __align__(16) char dsm[];
    const uint32_t sb = smem_u32(dsm);

    const int tid  = threadIdx.x;
    const int lane = tid & 31;
    const int wid  = tid >> 5;
    const int qb   = blockIdx.x;          // 0..15
    const int h    = blockIdx.y;
    const int b    = blockIdx.z;

    const size_t head = (size_t)(b * NH + h) * SSQ * HD;
    const __nv_bfloat16* qhg = g_qh + head + (size_t)qb * 128 * HD;
    const __nv_bfloat16* qlg = g_ql + head + (size_t)qb * 128 * HD;

    // ---- stage Q (Qh @ sb, Ql @ sb+18432), 2 x 1024 x 16B chunks ----
#pragma unroll
    for (int i = 0; i < 8; i++) {
        int g = i * 256 + tid;
        int mat = g >> 10;
        int idx = g & 1023;
        int row = idx >> 3;
        int c8 = (idx & 7) * 8;
        cpa16(sb + mat * 18432 + row * 144 + c8 * 2,
              (mat ? qlg : qhg) + row * HD + c8);
    }
    cpa_commit();
    cpa_wait<0>();
    __syncthreads();

    // ---- extract Q fragments ----
    uint32_t qh[4][4], ql[4][4];
#pragma unroll
    for (int ks = 0; ks < 4; ks++) {
        int row = wid * 16 + (lane & 15);
        int col = ks * 16 + (lane >> 4) * 8;
        uint32_t off = (uint32_t)(row * 144 + col * 2);
        ldm4(qh[ks], sb + off);
        ldm4(ql[ks], sb + 18432 + off);
    }
    __syncthreads();   // Q reads done; stage-0 region reusable for KV

    float m0 = -1e30f, m1 = -1e30f, l0 = 0.f, l1 = 0.f;
    float o[8][4];
#pragma unroll
    for (int df = 0; df < 8; df++)
#pragma unroll
        for (int e = 0; e < 4; e++) o[df][e] = 0.f;

    const int qi0 = qb * 128 + wid * 16 + (lane >> 2);
    const int qi1 = qi0 + 8;
    const int ntiles = 2 * qb + 2;

    const __nv_bfloat16* kvg[4] = {g_kh + head, g_kl + head, g_vh + head, g_vl + head};

    // ---- prologue: KV tile 0 into stage 0 ----
#pragma unroll
    for (int i = 0; i < 8; i++) {
        int g = i * 256 + tid;
        int mat = g >> 9;
        int idx = g & 511;
        int row = idx >> 3;
        int c8 = (idx & 7) * 8;
        cpa16(sb + mat * 9216 + row * 144 + c8 * 2, kvg[mat] + row * HD + c8);
    }
    cpa_commit();

    for (int kt = 0; kt < ntiles; kt++) {
        if (kt + 1 < ntiles) {
            const uint32_t base = sb + ((kt + 1) & 1) * KVST;
            const size_t koff = (size_t)(kt + 1) * 64 * HD;
#pragma unroll
            for (int i = 0; i < 8; i++) {
                int g = i * 256 + tid;
                int mat = g >> 9;
                int idx = g & 511;
                int row = idx >> 3;
                int c8 = (idx & 7) * 8;
                cpa16(base + mat * 9216 + row * 144 + c8 * 2,
                      kvg[mat] + koff + row * HD + c8);
            }
            cpa_commit();
            cpa_wait<1>();
        } else {
            cpa_wait<0>();
        }
        __syncthreads();

        const uint32_t st = sb + (kt & 1) * KVST;
        const uint32_t sKh = st, sKl = st + 9216, sVh = st + 18432, sVl = st + 27648;

        // ---- scores: S(16x64) = Q @ K^T, split-3 ----
        float s[8][4];
#pragma unroll
        for (int nf = 0; nf < 8; nf++)
#pragma unroll
            for (int e = 0; e < 4; e++) s[nf][e] = 0.f;

#pragma unroll
        for (int ks = 0; ks < 4; ks++) {
#pragma unroll
            for (int nfp = 0; nfp < 4; nfp++) {
                int g = lane >> 3;
                int row = nfp * 16 + ((g >= 2) ? 8 : 0) + (lane & 7);
                int col = ks * 16 + ((g & 1) ? 8 : 0);
                uint32_t off = (uint32_t)(row * 144 + col * 2);
                uint32_t bh[4], bl[4];
                ldm4(bh, sKh + off);
                ldm4(bl, sKl + off);
                mma16816(s[2*nfp],   qh[ks], bh);
                mma16816(s[2*nfp],   qh[ks], bl);
                mma16816(s[2*nfp],   ql[ks], bh);
                mma16816(s[2*nfp+1], qh[ks], bh + 2);
                mma16816(s[2*nfp+1], qh[ks], bl + 2);
                mma16816(s[2*nfp+1], ql[ks], bh + 2);
            }
        }

        // ---- causal mask ----
        if (kt >= 2 * qb) {
            int kbase = kt * 64 + (lane & 3) * 2;
#pragma unroll
            for (int nf = 0; nf < 8; nf++) {
                int kj = kbase + nf * 8;
                if (kj     > qi0) s[nf][0] = -1e30f;
                if (kj + 1 > qi0) s[nf][1] = -1e30f;
                if (kj     > qi1) s[nf][2] = -1e30f;
                if (kj + 1 > qi1) s[nf][3] = -1e30f;
            }
        }

        // ---- online softmax ----
        float rmax0 = -1e30f, rmax1 = -1e30f;
#pragma unroll
        for (int nf = 0; nf < 8; nf++) {
            rmax0 = fmaxf(rmax0, fmaxf(s[nf][0], s[nf][1]));
            rmax1 = fmaxf(rmax1, fmaxf(s[nf][2], s[nf][3]));
        }
        rmax0 = fmaxf(rmax0, __shfl_xor_sync(0xFFFFFFFFu, rmax0, 1));
        rmax0 = fmaxf(rmax0, __shfl_xor_sync(0xFFFFFFFFu, rmax0, 2));
        rmax1 = fmaxf(rmax1, __shfl_xor_sync(0xFFFFFFFFu, rmax1, 1));
        rmax1 = fmaxf(rmax1, __shfl_xor_sync(0xFFFFFFFFu, rmax1, 2));

        float mn0 = fmaxf(m0, rmax0);
        float mn1 = fmaxf(m1, rmax1);
        float corr0 = __expf(m0 - mn0);
        float corr1 = __expf(m1 - mn1);
        m0 = mn0; m1 = mn1;
        l0 *= corr0; l1 *= corr1;
#pragma unroll
        for (int df = 0; df < 8; df++) {
            o[df][0] *= corr0; o[df][1] *= corr0;
            o[df][2] *= corr1; o[df][3] *= corr1;
        }

        uint32_t ph01[8], ph23[8], pl01[8], pl23[8];
#pragma unroll
        for (int nf = 0; nf < 8; nf++) {
            float p0 = __expf(s[nf][0] - m0);
            float p1 = __expf(s[nf][1] - m0);
            float p2 = __expf(s[nf][2] - m1);
            float p3 = __expf(s[nf][3] - m1);
            l0 += p0 + p1;
            l1 += p2 + p3;
            float h0 = __bfloat162float(__float2bfloat16(p0));
            float h1 = __bfloat162float(__float2bfloat16(p1));
            float h2 = __bfloat162float(__float2bfloat16(p2));
            float h3 = __bfloat162float(__float2bfloat16(p3));
            ph01[nf] = pack_bf16x2(h0, h1);
            ph23[nf] = pack_bf16x2(h2, h3);
            pl01[nf] = pack_bf16x2(p0 - h0, p1 - h1);
            pl23[nf] = pack_bf16x2(p2 - h2, p3 - h3);
        }

        // ---- O += P @ V : split-2 x split-2 (drop plo*vlo) ----
#pragma unroll
        for (int ks = 0; ks < 4; ks++) {
            uint32_t aPh[4] = {ph01[2*ks], ph23[2*ks], ph01[2*ks+1], ph23[2*ks+1]};
            uint32_t aPl[4] = {pl01[2*ks], pl23[2*ks], pl01[2*ks+1], pl23[2*ks+1]};
#pragma unroll
            for (int dfp = 0; dfp < 4; dfp++) {
                int g = lane >> 3;
                int row = ks * 16 + ((g & 1) ? 8 : 0) + (lane & 7);
                int col = dfp * 16 + ((g >= 2) ? 8 : 0);
                uint32_t off = (uint32_t)(row * 144 + col * 2);
                uint32_t bv[4], bvl[4];
                ldm4t(bv,  sVh + off);
                ldm4t(bvl, sVl + off);
                mma16816(o[2*dfp],   aPh, bv);
                mma16816(o[2*dfp],   aPh, bvl);
                mma16816(o[2*dfp],   aPl, bv);
                mma16816(o[2*dfp+1], aPh, bv + 2);
                mma16816(o[2*dfp+1], aPh, bvl + 2);
                mma16816(o[2*dfp+1], aPl, bv + 2);
            }
        }
        __syncthreads();
    }

    // ---- finalize: normalize, split, store to GEMM-A hi/lo ----
    l0 += __shfl_xor_sync(0xFFFFFFFFu, l0, 1);
    l0 += __shfl_xor_sync(0xFFFFFFFFu, l0, 2);
    l1 += __shfl_xor_sync(0xFFFFFFFFu, l1, 1);
    l1 += __shfl_xor_sync(0xFFFFFFFFu, l1, 2);
    float inv0 = 1.0f / l0;
    float inv1 = 1.0f / l1;

#pragma unroll
    for (int df = 0; df < 8; df++) {
        int col = h * HD + df * 8 + (lane & 3) * 2;
        size_t r0 = (size_t)(b * SSQ + qi0) * DIM + col;
        size_t r1 = (size_t)(b * SSQ + qi1) * DIM + col;
        float v0 = o[df][0] * inv0, v1 = o[df][1] * inv0;
        float v2 = o[df][2] * inv1, v3 = o[df][3] * inv1;
        float h0 = __bfloat162float(__float2bfloat16(v0));
        float h1 = __bfloat162float(__float2bfloat16(v1));
        float h2 = __bfloat162float(__float2bfloat16(v2));
        float h3 = __bfloat162float(__float2bfloat16(v3));
        *(uint32_t*)(g_ahi + r0) = pack_bf16x2(h0, h1);
        *(uint32_t*)(g_alo + r0) = pack_bf16x2(v0 - h0, v1 - h1);
        *(uint32_t*)(g_ahi + r1) = pack_bf16x2(h2, h3);
        *(uint32_t*)(g_alo + r1) = pack_bf16x2(v2 - h2, v3 - h3);
    }
}

// ---------------------------------------------------------------------------
extern "C" void kernel_launch(void* const* d_in, const int* in_sizes, int n_in,
                              void* d_out, int out_size)
{
    const float* x = nullptr;
    const float* wqkv = nullptr;
    const float* wout = nullptr;
    for (int i = 0; i < n_in; i++) {
        long long n = in_sizes[i];
        if (n == (long long)MROWS * DIM)      x    = (const float*)d_in[i];
        else if (n == (long long)NQKV * DIM)  wqkv = (const float*)d_in[i];
        else if (n == (long long)DIM * DIM)   wout = (const float*)d_in[i];
    }
    if (!x || !wqkv || !wout) return;

    float* qkv = nullptr;
    __nv_bfloat16 *ahi, *alo, *whi, *wlo, *vhi, *vlo;
    cudaGetSymbolAddress((void**)&qkv, g_qkv);
    cudaGetSymbolAddress((void**)&ahi, g_ahi);
    cudaGetSymbolAddress((void**)&alo, g_alo);
    cudaGetSymbolAddress((void**)&whi, g_whi);
    cudaGetSymbolAddress((void**)&wlo, g_wlo);
    cudaGetSymbolAddress((void**)&vhi, g_vhi);
    cudaGetSymbolAddress((void**)&vlo, g_vlo);

    cudaFuncSetAttribute(hgemm_s3, cudaFuncAttributeMaxDynamicSharedMemorySize,
                         GEMM_SMEM);
    cudaFuncSetAttribute(attn_tc, cudaFuncAttributeMaxDynamicSharedMemorySize,
                         ATTN_SMEM);

    // 0) bf16 hi/lo splits of inputs
    cvt_split<<<(MROWS * DIM / 4 + 255) / 256, 256>>>(x, ahi, alo, MROWS * DIM / 4);
    cvt_split<<<(NQKV * DIM / 4 + 255) / 256, 256>>>(wqkv, whi, wlo, NQKV * DIM / 4);
    cvt_split<<<(DIM * DIM / 4 + 255) / 256, 256>>>(wout, vhi, vlo, DIM * DIM / 4);

    // 1) qkv = x @ Wqkv^T
    dim3 g1(NQKV / 128, MROWS / 128);
    hgemm_s3<<<g1, 256, GEMM_SMEM>>>(ahi, alo, whi, wlo, qkv, NQKV, DIM);

    // 2) RoPE + split + relayout
    rope_tables<<<(SSQ * 32) / 256, 256>>>();
    dim3 gr(SSQ, BB);
    rope_split<<<gr, 512>>>();

    // 3) flash attention (writes g_ahi/g_alo directly)
    dim3 ga(SSQ / 128, NH, BB);
    attn_tc<<<ga, 256, ATTN_SMEM>>>();

    // 4) out = att @ Wout^T
    dim3 g2(DIM / 128, MROWS / 128);
    hgemm_s3<<<g2, 256, GEMM_SMEM>>>(ahi, alo, vhi, vlo, (float*)d_out, DIM, DIM);
}

// round 7
// speedup vs baseline: 3.6799x; 1.0756x over previous
#include <cuda_runtime.h>
#include <cuda_bf16.h>
#include <math.h>
#include <stdint.h>

#define BB 4
#define SSQ 2048
#define DIM 1024
#define NH 16
#define HD 64
#define MROWS (BB*SSQ)       // 8192
#define NQKV (3*DIM)         // 3072
#define HEADS_ELEMS ((size_t)BB * NH * SSQ * HD)   // 8.4M

// ---------------- scratch (device globals; allocation-free) ----------------
__device__ float g_qkv[(size_t)MROWS * NQKV];   // 96 MB (fp32 qkv after GEMM1)
__device__ float g_cos[SSQ * 32];
__device__ float g_sin[SSQ * 32];
__device__ __nv_bfloat16 g_ahi[(size_t)MROWS * DIM];   // GEMM A operand hi/lo
__device__ __nv_bfloat16 g_alo[(size_t)MROWS * DIM];
__device__ __nv_bfloat16 g_whi[(size_t)NQKV * DIM];
__device__ __nv_bfloat16 g_wlo[(size_t)NQKV * DIM];
__device__ __nv_bfloat16 g_vhi[(size_t)DIM * DIM];
__device__ __nv_bfloat16 g_vlo[(size_t)DIM * DIM];
// pre-split, rope'd, head-contiguous q/k/v: [b,h,s,d]
__device__ __nv_bfloat16 g_qh[HEADS_ELEMS], g_ql[HEADS_ELEMS];
__device__ __nv_bfloat16 g_kh[HEADS_ELEMS], g_kl[HEADS_ELEMS];
__device__ __nv_bfloat16 g_vh[HEADS_ELEMS], g_vl[HEADS_ELEMS];

// ---------------- PTX helpers (plain sm_103-safe) ---------------------------
__device__ __forceinline__ uint32_t smem_u32(const void* p) {
    uint32_t a;
    asm("{ .reg .u64 t; cvta.to.shared.u64 t, %1; cvt.u32.u64 %0, t; }"
        : "=r"(a) : "l"(p));
    return a;
}
__device__ __forceinline__ void mma16816(float* c, const uint32_t* a, const uint32_t* b) {
    asm volatile(
        "mma.sync.aligned.m16n8k16.row.col.f32.bf16.bf16.f32 "
        "{%0,%1,%2,%3}, {%4,%5,%6,%7}, {%8,%9}, {%0,%1,%2,%3};"
        : "+f"(c[0]), "+f"(c[1]), "+f"(c[2]), "+f"(c[3])
        : "r"(a[0]), "r"(a[1]), "r"(a[2]), "r"(a[3]), "r"(b[0]), "r"(b[1]));
}
__device__ __forceinline__ void ldm4(uint32_t* r, uint32_t addr) {
    asm volatile("ldmatrix.sync.aligned.m8n8.x4.shared.b16 {%0,%1,%2,%3}, [%4];"
                 : "=r"(r[0]), "=r"(r[1]), "=r"(r[2]), "=r"(r[3]) : "r"(addr));
}
__device__ __forceinline__ void ldm4t(uint32_t* r, uint32_t addr) {
    asm volatile("ldmatrix.sync.aligned.m8n8.x4.trans.shared.b16 {%0,%1,%2,%3}, [%4];"
                 : "=r"(r[0]), "=r"(r[1]), "=r"(r[2]), "=r"(r[3]) : "r"(addr));
}
__device__ __forceinline__ uint32_t pack_bf16x2(float lo, float hi) {
    uint32_t d;
    asm("cvt.rn.bf16x2.f32 %0, %1, %2;" : "=r"(d) : "f"(hi), "f"(lo));
    return d;
}
__device__ __forceinline__ void cpa16(uint32_t dst, const void* src) {
    asm volatile("cp.async.cg.shared.global [%0], [%1], 16;"
                 :: "r"(dst), "l"(src) : "memory");
}
__device__ __forceinline__ void cpa_commit() {
    asm volatile("cp.async.commit_group;" ::: "memory");
}
template <int N>
__device__ __forceinline__ void cpa_wait() {
    asm volatile("cp.async.wait_group %0;" :: "n"(N) : "memory");
}

// ---------------------------------------------------------------------------
// fp32 -> bf16 hi/lo split (4 elems per thread)
// ---------------------------------------------------------------------------
__global__ void cvt_split(const float* __restrict__ in,
                          __nv_bfloat16* __restrict__ hi,
                          __nv_bfloat16* __restrict__ lo, int n4)
{
    int i = blockIdx.x * blockDim.x + threadIdx.x;
    if (i >= n4) return;
    float4 v = ((const float4*)in)[i];
    __nv_bfloat16 hx = __float2bfloat16(v.x);
    __nv_bfloat16 hy = __float2bfloat16(v.y);
    __nv_bfloat16 hz = __float2bfloat16(v.z);
    __nv_bfloat16 hw = __float2bfloat16(v.w);
    __nv_bfloat162* hp = reinterpret_cast<__nv_bfloat162*>(hi);
    __nv_bfloat162* lp = reinterpret_cast<__nv_bfloat162*>(lo);
    hp[2*i]   = __nv_bfloat162(hx, hy);
    hp[2*i+1] = __nv_bfloat162(hz, hw);
    lp[2*i]   = __nv_bfloat162(__float2bfloat16(v.x - __bfloat162float(hx)),
                               __float2bfloat16(v.y - __bfloat162float(hy)));
    lp[2*i+1] = __nv_bfloat162(__float2bfloat16(v.z - __bfloat162float(hz)),
                               __float2bfloat16(v.w - __bfloat162float(hw)));
}

// ---------------------------------------------------------------------------
// HMMA split-3 GEMM, cp.async double-buffered, single sync per chunk.
// C[M,N] = (Ahi+Alo)[M,K] @ (Bhi+Blo)[N,K]^T (fp32 accum)
// 128x256 tile, 512 threads (16 warps: 4 M x 4 N), K-chunk 32.
// Stage: Ahi|Alo (128x40 bf16 each) + Bhi|Blo (256x40 bf16 each) = 61440 B.
// ---------------------------------------------------------------------------
#define GST 61440   // stage stride bytes
#define GEMM_SMEM (2 * GST)

__global__ __launch_bounds__(512, 1) void hgemm_s3(
    const __nv_bfloat16* __restrict__ Ahi, const __nv_bfloat16* __restrict__ Alo,
    const __nv_bfloat16* __restrict__ Bhi, const __nv_bfloat16* __restrict__ Blo,
    float* __restrict__ C, int N, int K)
{
    extern __shared__ __align__(16) char dsm[];
    const uint32_t sb = smem_u32(dsm);
    const int tid = threadIdx.x;
    const int lane = tid & 31;
    const int wid = tid >> 5;
    const int wm = wid & 3;          // 4 M-groups x 32 rows
    const int wn = wid >> 2;         // 4 N-groups x 64 cols
    const int bm = blockIdx.y * 128;
    const int bn = blockIdx.x * 256;

    float c[2][8][4];
#pragma unroll
    for (int i = 0; i < 2; i++)
#pragma unroll
        for (int nf = 0; nf < 8; nf++)
#pragma unroll
            for (int e = 0; e < 4; e++) c[i][nf][e] = 0.f;

    const int nch = K / 32;

    // loader: 3072 x 16B chunks per stage, 6 per thread
    // i=0: Ahi(512) | i=1: Alo(512) | i=2,3: Bhi(1024) | i=4,5: Blo(1024)
#define GEMM_STAGE_LOAD(stbase, kk)                                            \
    {                                                                          \
        const uint32_t _b = (stbase);                                          \
        const int _k8 = (kk) * 32;                                             \
        { int idx = tid;        int row = idx >> 2, c8 = (idx & 3) * 8;        \
          cpa16(_b + row * 80 + c8 * 2,                                        \
                Ahi + (size_t)(bm + row) * K + _k8 + c8); }                    \
        { int idx = tid;        int row = idx >> 2, c8 = (idx & 3) * 8;        \
          cpa16(_b + 10240 + row * 80 + c8 * 2,                                \
                Alo + (size_t)(bm + row) * K + _k8 + c8); }                    \
        { int idx = tid;        int row = idx >> 2, c8 = (idx & 3) * 8;        \
          cpa16(_b + 20480 + row * 80 + c8 * 2,                                \
                Bhi + (size_t)(bn + row) * K + _k8 + c8); }                    \
        { int idx = 512 + tid;  int row = idx >> 2, c8 = (idx & 3) * 8;        \
          cpa16(_b + 20480 + row * 80 + c8 * 2,                                \
                Bhi + (size_t)(bn + row) * K + _k8 + c8); }                    \
        { int idx = tid;        int row = idx >> 2, c8 = (idx & 3) * 8;        \
          cpa16(_b + 40960 + row * 80 + c8 * 2,                                \
                Blo + (size_t)(bn + row) * K + _k8 + c8); }                    \
        { int idx = 512 + tid;  int row = idx >> 2, c8 = (idx & 3) * 8;        \
          cpa16(_b + 40960 + row * 80 + c8 * 2,                                \
                Blo + (size_t)(bn + row) * K + _k8 + c8); }                    \
    }

    // prologue: chunk 0 -> stage 0
    GEMM_STAGE_LOAD(sb, 0);
    cpa_commit();

    for (int ck = 0; ck < nch; ck++) {
        cpa_wait<0>();
        __syncthreads();
        if (ck + 1 < nch) {
            GEMM_STAGE_LOAD(sb + ((ck + 1) & 1) * GST, ck + 1);
            cpa_commit();
        }

        const uint32_t st = sb + (ck & 1) * GST;
        const uint32_t sAh = st, sAl = st + 10240, sBh = st + 20480, sBl = st + 40960;
#pragma unroll
        for (int ks = 0; ks < 2; ks++) {
            uint32_t ah[2][4], al[2][4];
#pragma unroll
            for (int i = 0; i < 2; i++) {
                int row = wm * 32 + i * 16 + (lane & 15);
                int col = ks * 16 + (lane >> 4) * 8;
                uint32_t off = (uint32_t)(row * 80 + col * 2);
                ldm4(ah[i], sAh + off);
                ldm4(al[i], sAl + off);
            }
#pragma unroll
            for (int nfp = 0; nfp < 4; nfp++) {
                int g = lane >> 3;
                int row = wn * 64 + nfp * 16 + ((g >= 2) ? 8 : 0) + (lane & 7);
                int col = ks * 16 + ((g & 1) ? 8 : 0);
                uint32_t off = (uint32_t)(row * 80 + col * 2);
                uint32_t bh[4], bl[4];
                ldm4(bh, sBh + off);
                ldm4(bl, sBl + off);
#pragma unroll
                for (int i = 0; i < 2; i++) {
                    mma16816(c[i][2*nfp],   ah[i], bh);
                    mma16816(c[i][2*nfp],   ah[i], bl);
                    mma16816(c[i][2*nfp],   al[i], bh);
                    mma16816(c[i][2*nfp+1], ah[i], bh + 2);
                    mma16816(c[i][2*nfp+1], ah[i], bl + 2);
                    mma16816(c[i][2*nfp+1], al[i], bh + 2);
                }
            }
        }
    }

#pragma unroll
    for (int i = 0; i < 2; i++) {
#pragma unroll
        for (int nf = 0; nf < 8; nf++) {
            int row = bm + wm * 32 + i * 16 + (lane >> 2);
            int col = bn + wn * 64 + nf * 8 + (lane & 3) * 2;
            *(float2*)(C + (size_t)row * N + col) = make_float2(c[i][nf][0], c[i][nf][1]);
            *(float2*)(C + (size_t)(row + 8) * N + col) = make_float2(c[i][nf][2], c[i][nf][3]);
        }
    }
}

// ---------------------------------------------------------------------------
// RoPE tables (verified)
// ---------------------------------------------------------------------------
__global__ void rope_tables()
{
    int idx = blockIdx.x * blockDim.x + threadIdx.x;
    if (idx >= SSQ * 32) return;
    int s = idx >> 5;
    int i = idx & 31;
    double inv_d = exp(-(double)i * (9.210340371976184 / 32.0));
    float  ang_f = (float)s * (float)inv_d;
    double c, sn;
    sincos((double)ang_f, &sn, &c);
    g_cos[idx] = (float)c;
    g_sin[idx] = (float)sn;
}

__device__ __forceinline__ void split_store(__nv_bfloat16* hi, __nv_bfloat16* lo,
                                            size_t idx, float v)
{
    __nv_bfloat16 h = __float2bfloat16(v);
    hi[idx] = h;
    lo[idx] = __float2bfloat16(v - __bfloat162float(h));
}

// RoPE + split + relayout to [b,h,s,d]. q pre-scaled by 1/sqrt(64).
__global__ __launch_bounds__(512) void rope_split()
{
    int s = blockIdx.x;
    int b = blockIdx.y;
    int h = threadIdx.x >> 5;
    int i = threadIdx.x & 31;

    float c  = g_cos[s * 32 + i];
    float sn = g_sin[s * 32 + i];

    size_t row  = ((size_t)(b * SSQ + s)) * NQKV + (size_t)h * HD;
    size_t orow = ((size_t)((b * NH + h) * SSQ) + s) * HD;

    float q1 = g_qkv[row + i];
    float q2 = g_qkv[row + 32 + i];
    split_store(g_qh, g_ql, orow + i,      (q1 * c - q2 * sn) * 0.125f);
    split_store(g_qh, g_ql, orow + 32 + i, (q1 * sn + q2 * c) * 0.125f);

    float k1 = g_qkv[row + DIM + i];
    float k2 = g_qkv[row + DIM + 32 + i];
    split_store(g_kh, g_kl, orow + i,      k1 * c - k2 * sn);
    split_store(g_kh, g_kl, orow + 32 + i, k1 * sn + k2 * c);

    split_store(g_vh, g_vl, orow + i,      g_qkv[row + 2 * DIM + i]);
    split_store(g_vh, g_vl, orow + 32 + i, g_qkv[row + 2 * DIM + 32 + i]);
}

// ---------------------------------------------------------------------------
// HMMA flash attention (causal), pre-split bf16 inputs, cp.async 2-stage KV,
// single sync per KV tile.
// Block = 128 queries of one (b,h), 256 threads (8 warps x 16 query rows).
// Dynamic smem: 2 stages x (Kh|Kl|Vh|Vl each 64x72 bf16) = 73728 B.
// ---------------------------------------------------------------------------
#define KVST 36864    // KV stage stride bytes
#define ATTN_SMEM (2 * KVST)

__global__ __launch_bounds__(256, 1) void attn_tc()
{
    extern __shared__ __align__(16) char dsm[];
    const uint32_t sb = smem_u32(dsm);

    const int tid  = threadIdx.x;
    const int lane = tid & 31;
    const int wid  = tid >> 5;
    const int qb   = blockIdx.x;          // 0..15
    const int h    = blockIdx.y;
    const int b    = blockIdx.z;

    const size_t head = (size_t)(b * NH + h) * SSQ * HD;
    const __nv_bfloat16* qhg = g_qh + head + (size_t)qb * 128 * HD;
    const __nv_bfloat16* qlg = g_ql + head + (size_t)qb * 128 * HD;

    // ---- stage Q (Qh @ sb, Ql @ sb+18432) ----
#pragma unroll
    for (int i = 0; i < 8; i++) {
        int g = i * 256 + tid;
        int mat = g >> 10;
        int idx = g & 1023;
        int row = idx >> 3;
        int c8 = (idx & 7) * 8;
        cpa16(sb + mat * 18432 + row * 144 + c8 * 2,
              (mat ? qlg : qhg) + row * HD + c8);
    }
    cpa_commit();
    cpa_wait<0>();
    __syncthreads();

    // ---- extract Q fragments ----
    uint32_t qh[4][4], ql[4][4];
#pragma unroll
    for (int ks = 0; ks < 4; ks++) {
        int row = wid * 16 + (lane & 15);
        int col = ks * 16 + (lane >> 4) * 8;
        uint32_t off = (uint32_t)(row * 144 + col * 2);
        ldm4(qh[ks], sb + off);
        ldm4(ql[ks], sb + 18432 + off);
    }
    __syncthreads();   // Q reads done; stage-0 region reusable for KV

    float m0 = -1e30f, m1 = -1e30f, l0 = 0.f, l1 = 0.f;
    float o[8][4];
#pragma unroll
    for (int df = 0; df < 8; df++)
#pragma unroll
        for (int e = 0; e < 4; e++) o[df][e] = 0.f;

    const int qi0 = qb * 128 + wid * 16 + (lane >> 2);
    const int qi1 = qi0 + 8;
    const int ntiles = 2 * qb + 2;

    const __nv_bfloat16* kvg[4] = {g_kh + head, g_kl + head, g_vh + head, g_vl + head};

    // ---- prologue: KV tile 0 into stage 0 ----
#pragma unroll
    for (int i = 0; i < 8; i++) {
        int g = i * 256 + tid;
        int mat = g >> 9;
        int idx = g & 511;
        int row = idx >> 3;
        int c8 = (idx & 7) * 8;
        cpa16(sb + mat * 9216 + row * 144 + c8 * 2, kvg[mat] + row * HD + c8);
    }
    cpa_commit();

    for (int kt = 0; kt < ntiles; kt++) {
        cpa_wait<0>();
        __syncthreads();
        if (kt + 1 < ntiles) {
            const uint32_t base = sb + ((kt + 1) & 1) * KVST;
            const size_t koff = (size_t)(kt + 1) * 64 * HD;
#pragma unroll
            for (int i = 0; i < 8; i++) {
                int g = i * 256 + tid;
                int mat = g >> 9;
                int idx = g & 511;
                int row = idx >> 3;
                int c8 = (idx & 7) * 8;
                cpa16(base + mat * 9216 + row * 144 + c8 * 2,
                      kvg[mat] + koff + row * HD + c8);
            }
            cpa_commit();
        }

        const uint32_t st = sb + (kt & 1) * KVST;
        const uint32_t sKh = st, sKl = st + 9216, sVh = st + 18432, sVl = st + 27648;

        // ---- scores: S(16x64) = Q @ K^T, split-3 ----
        float s[8][4];
#pragma unroll
        for (int nf = 0; nf < 8; nf++)
#pragma unroll
            for (int e = 0; e < 4; e++) s[nf][e] = 0.f;

#pragma unroll
        for (int ks = 0; ks < 4; ks++) {
#pragma unroll
            for (int nfp = 0; nfp < 4; nfp++) {
                int g = lane >> 3;
                int row = nfp * 16 + ((g >= 2) ? 8 : 0) + (lane & 7);
                int col = ks * 16 + ((g & 1) ? 8 : 0);
                uint32_t off = (uint32_t)(row * 144 + col * 2);
                uint32_t bh[4], bl[4];
                ldm4(bh, sKh + off);
                ldm4(bl, sKl + off);
                mma16816(s[2*nfp],   qh[ks], bh);
                mma16816(s[2*nfp],   qh[ks], bl);
                mma16816(s[2*nfp],   ql[ks], bh);
                mma16816(s[2*nfp+1], qh[ks], bh + 2);
                mma16816(s[2*nfp+1], qh[ks], bl + 2);
                mma16816(s[2*nfp+1], ql[ks], bh + 2);
            }
        }

        // ---- causal mask ----
        if (kt >= 2 * qb) {
            int kbase = kt * 64 + (lane & 3) * 2;
#pragma unroll
            for (int nf = 0; nf < 8; nf++) {
                int kj = kbase + nf * 8;
                if (kj     > qi0) s[nf][0] = -1e30f;
                if (kj + 1 > qi0) s[nf][1] = -1e30f;
                if (kj     > qi1) s[nf][2] = -1e30f;
                if (kj + 1 > qi1) s[nf][3] = -1e30f;
            }
        }

        // ---- online softmax ----
        float rmax0 = -1e30f, rmax1 = -1e30f;
#pragma unroll
        for (int nf = 0; nf < 8; nf++) {
            rmax0 = fmaxf(rmax0, fmaxf(s[nf][0], s[nf][1]));
            rmax1 = fmaxf(rmax1, fmaxf(s[nf][2], s[nf][3]));
        }
        rmax0 = fmaxf(rmax0, __shfl_xor_sync(0xFFFFFFFFu, rmax0, 1));
        rmax0 = fmaxf(rmax0, __shfl_xor_sync(0xFFFFFFFFu, rmax0, 2));
        rmax1 = fmaxf(rmax1, __shfl_xor_sync(0xFFFFFFFFu, rmax1, 1));
        rmax1 = fmaxf(rmax1, __shfl_xor_sync(0xFFFFFFFFu, rmax1, 2));

        float mn0 = fmaxf(m0, rmax0);
        float mn1 = fmaxf(m1, rmax1);
        float corr0 = __expf(m0 - mn0);
        float corr1 = __expf(m1 - mn1);
        m0 = mn0; m1 = mn1;
        l0 *= corr0; l1 *= corr1;
#pragma unroll
        for (int df = 0; df < 8; df++) {
            o[df][0] *= corr0; o[df][1] *= corr0;
            o[df][2] *= corr1; o[df][3] *= corr1;
        }

        uint32_t ph01[8], ph23[8], pl01[8], pl23[8];
#pragma unroll
        for (int nf = 0; nf < 8; nf++) {
            float p0 = __expf(s[nf][0] - m0);
            float p1 = __expf(s[nf][1] - m0);
            float p2 = __expf(s[nf][2] - m1);
            float p3 = __expf(s[nf][3] - m1);
            l0 += p0 + p1;
            l1 += p2 + p3;
            float h0 = __bfloat162float(__float2bfloat16(p0));
            float h1 = __bfloat162float(__float2bfloat16(p1));
            float h2 = __bfloat162float(__float2bfloat16(p2));
            float h3 = __bfloat162float(__float2bfloat16(p3));
            ph01[nf] = pack_bf16x2(h0, h1);
            ph23[nf] = pack_bf16x2(h2, h3);
            pl01[nf] = pack_bf16x2(p0 - h0, p1 - h1);
            pl23[nf] = pack_bf16x2(p2 - h2, p3 - h3);
        }

        // ---- O += P @ V : split-2 x split-2 (drop plo*vlo) ----
#pragma unroll
        for (int ks = 0; ks < 4; ks++) {
            uint32_t aPh[4] = {ph01[2*ks], ph23[2*ks], ph01[2*ks+1], ph23[2*ks+1]};
            uint32_t aPl[4] = {pl01[2*ks], pl23[2*ks], pl01[2*ks+1], pl23[2*ks+1]};
#pragma unroll
            for (int dfp = 0; dfp < 4; dfp++) {
                int g = lane >> 3;
                int row = ks * 16 + ((g & 1) ? 8 : 0) + (lane & 7);
                int col = dfp * 16 + ((g >= 2) ? 8 : 0);
                uint32_t off = (uint32_t)(row * 144 + col * 2);
                uint32_t bv[4], bvl[4];
                ldm4t(bv,  sVh + off);
                ldm4t(bvl, sVl + off);
                mma16816(o[2*dfp],   aPh, bv);
                mma16816(o[2*dfp],   aPh, bvl);
                mma16816(o[2*dfp],   aPl, bv);
                mma16816(o[2*dfp+1], aPh, bv + 2);
                mma16816(o[2*dfp+1], aPh, bvl + 2);
                mma16816(o[2*dfp+1], aPl, bv + 2);
            }
        }
    }

    // ---- finalize: normalize, split, store to GEMM-A hi/lo ----
    l0 += __shfl_xor_sync(0xFFFFFFFFu, l0, 1);
    l0 += __shfl_xor_sync(0xFFFFFFFFu, l0, 2);
    l1 += __shfl_xor_sync(0xFFFFFFFFu, l1, 1);
    l1 += __shfl_xor_sync(0xFFFFFFFFu, l1, 2);
    float inv0 = 1.0f / l0;
    float inv1 = 1.0f / l1;

#pragma unroll
    for (int df = 0; df < 8; df++) {
        int col = h * HD + df * 8 + (lane & 3) * 2;
        size_t r0 = (size_t)(b * SSQ + qi0) * DIM + col;
        size_t r1 = (size_t)(b * SSQ + qi1) * DIM + col;
        float v0 = o[df][0] * inv0, v1 = o[df][1] * inv0;
        float v2 = o[df][2] * inv1, v3 = o[df][3] * inv1;
        float h0 = __bfloat162float(__float2bfloat16(v0));
        float h1 = __bfloat162float(__float2bfloat16(v1));
        float h2 = __bfloat162float(__float2bfloat16(v2));
        float h3 = __bfloat162float(__float2bfloat16(v3));
        *(uint32_t*)(g_ahi + r0) = pack_bf16x2(h0, h1);
        *(uint32_t*)(g_alo + r0) = pack_bf16x2(v0 - h0, v1 - h1);
        *(uint32_t*)(g_ahi + r1) = pack_bf16x2(h2, h3);
        *(uint32_t*)(g_alo + r1) = pack_bf16x2(v2 - h2, v3 - h3);
    }
}

// ---------------------------------------------------------------------------
extern "C" void kernel_launch(void* const* d_in, const int* in_sizes, int n_in,
                              void* d_out, int out_size)
{
    const float* x = nullptr;
    const float* wqkv = nullptr;
    const float* wout = nullptr;
    for (int i = 0; i < n_in; i++) {
        long long n = in_sizes[i];
        if (n == (long long)MROWS * DIM)      x    = (const float*)d_in[i];
        else if (n == (long long)NQKV * DIM)  wqkv = (const float*)d_in[i];
        else if (n == (long long)DIM * DIM)   wout = (const float*)d_in[i];
    }
    if (!x || !wqkv || !wout) return;

    float* qkv = nullptr;
    __nv_bfloat16 *ahi, *alo, *whi, *wlo, *vhi, *vlo;
    cudaGetSymbolAddress((void**)&qkv, g_qkv);
    cudaGetSymbolAddress((void**)&ahi, g_ahi);
    cudaGetSymbolAddress((void**)&alo, g_alo);
    cudaGetSymbolAddress((void**)&whi, g_whi);
    cudaGetSymbolAddress((void**)&wlo, g_wlo);
    cudaGetSymbolAddress((void**)&vhi, g_vhi);
    cudaGetSymbolAddress((void**)&vlo, g_vlo);

    cudaFuncSetAttribute(hgemm_s3, cudaFuncAttributeMaxDynamicSharedMemorySize,
                         GEMM_SMEM);
    cudaFuncSetAttribute(attn_tc, cudaFuncAttributeMaxDynamicSharedMemorySize,
                         ATTN_SMEM);

    // 0) bf16 hi/lo splits of inputs
    cvt_split<<<(MROWS * DIM / 4 + 255) / 256, 256>>>(x, ahi, alo, MROWS * DIM / 4);
    cvt_split<<<(NQKV * DIM / 4 + 255) / 256, 256>>>(wqkv, whi, wlo, NQKV * DIM / 4);
    cvt_split<<<(DIM * DIM / 4 + 255) / 256, 256>>>(wout, vhi, vlo, DIM * DIM / 4);

    // 1) qkv = x @ Wqkv^T
    dim3 g1(NQKV / 256, MROWS / 128);
    hgemm_s3<<<g1, 512, GEMM_SMEM>>>(ahi, alo, whi, wlo, qkv, NQKV, DIM);

    // 2) RoPE + split + relayout
    rope_tables<<<(SSQ * 32) / 256, 256>>>();
    dim3 gr(SSQ, BB);
    rope_split<<<gr, 512>>>();

    // 3) flash attention (writes g_ahi/g_alo directly)
    dim3 ga(SSQ / 128, NH, BB);
    attn_tc<<<ga, 256, ATTN_SMEM>>>();

    // 4) out = att @ Wout^T
    dim3 g2(DIM / 256, MROWS / 128);
    hgemm_s3<<<g2, 512, GEMM_SMEM>>>(ahi, alo, vhi, vlo, (float*)d_out, DIM, DIM);
}

// round 8
// speedup vs baseline: 3.6982x; 1.0050x over previous
#include <cuda_runtime.h>
#include <cuda_bf16.h>
#include <math.h>
#include <stdint.h>

#define BB 4
#define SSQ 2048
#define DIM 1024
#define NH 16
#define HD 64
#define MROWS (BB*SSQ)       // 8192
#define NQKV (3*DIM)         // 3072
#define HEADS_ELEMS ((size_t)BB * NH * SSQ * HD)   // 8.4M

// ---------------- scratch (device globals; allocation-free) ----------------
__device__ float g_qkv[(size_t)MROWS * NQKV];   // 96 MB (fp32 qkv after GEMM1)
__device__ float g_cos[SSQ * 32];
__device__ float g_sin[SSQ * 32];
__device__ __nv_bfloat16 g_ahi[(size_t)MROWS * DIM];   // GEMM A operand hi/lo
__device__ __nv_bfloat16 g_alo[(size_t)MROWS * DIM];
__device__ __nv_bfloat16 g_whi[(size_t)NQKV * DIM];
__device__ __nv_bfloat16 g_wlo[(size_t)NQKV * DIM];
__device__ __nv_bfloat16 g_vhi[(size_t)DIM * DIM];
__device__ __nv_bfloat16 g_vlo[(size_t)DIM * DIM];
// pre-split, rope'd, head-contiguous q/k/v: [b,h,s,d]
__device__ __nv_bfloat16 g_qh[HEADS_ELEMS], g_ql[HEADS_ELEMS];
__device__ __nv_bfloat16 g_kh[HEADS_ELEMS], g_kl[HEADS_ELEMS];
__device__ __nv_bfloat16 g_vh[HEADS_ELEMS], g_vl[HEADS_ELEMS];

// ---------------- PTX helpers (plain sm_103-safe) ---------------------------
__device__ __forceinline__ uint32_t smem_u32(const void* p) {
    uint32_t a;
    asm("{ .reg .u64 t; cvta.to.shared.u64 t, %1; cvt.u32.u64 %0, t; }"
        : "=r"(a) : "l"(p));
    return a;
}
__device__ __forceinline__ void mma16816(float* c, const uint32_t* a, const uint32_t* b) {
    asm volatile(
        "mma.sync.aligned.m16n8k16.row.col.f32.bf16.bf16.f32 "
        "{%0,%1,%2,%3}, {%4,%5,%6,%7}, {%8,%9}, {%0,%1,%2,%3};"
        : "+f"(c[0]), "+f"(c[1]), "+f"(c[2]), "+f"(c[3])
        : "r"(a[0]), "r"(a[1]), "r"(a[2]), "r"(a[3]), "r"(b[0]), "r"(b[1]));
}
__device__ __forceinline__ void ldm4(uint32_t* r, uint32_t addr) {
    asm volatile("ldmatrix.sync.aligned.m8n8.x4.shared.b16 {%0,%1,%2,%3}, [%4];"
                 : "=r"(r[0]), "=r"(r[1]), "=r"(r[2]), "=r"(r[3]) : "r"(addr));
}
__device__ __forceinline__ void ldm4t(uint32_t* r, uint32_t addr) {
    asm volatile("ldmatrix.sync.aligned.m8n8.x4.trans.shared.b16 {%0,%1,%2,%3}, [%4];"
                 : "=r"(r[0]), "=r"(r[1]), "=r"(r[2]), "=r"(r[3]) : "r"(addr));
}
__device__ __forceinline__ uint32_t pack_bf16x2(float lo, float hi) {
    uint32_t d;
    asm("cvt.rn.bf16x2.f32 %0, %1, %2;" : "=r"(d) : "f"(hi), "f"(lo));
    return d;
}
__device__ __forceinline__ void cpa16(uint32_t dst, const void* src) {
    asm volatile("cp.async.cg.shared.global [%0], [%1], 16;"
                 :: "r"(dst), "l"(src) : "memory");
}
__device__ __forceinline__ void cpa_commit() {
    asm volatile("cp.async.commit_group;" ::: "memory");
}
template <int N>
__device__ __forceinline__ void cpa_wait() {
    asm volatile("cp.async.wait_group %0;" :: "n"(N) : "memory");
}

// ---------------------------------------------------------------------------
// fp32 -> bf16 hi/lo split (4 elems per thread)
// ---------------------------------------------------------------------------
__global__ void cvt_split(const float* __restrict__ in,
                          __nv_bfloat16* __restrict__ hi,
                          __nv_bfloat16* __restrict__ lo, int n4)
{
    int i = blockIdx.x * blockDim.x + threadIdx.x;
    if (i >= n4) return;
    float4 v = ((const float4*)in)[i];
    __nv_bfloat16 hx = __float2bfloat16(v.x);
    __nv_bfloat16 hy = __float2bfloat16(v.y);
    __nv_bfloat16 hz = __float2bfloat16(v.z);
    __nv_bfloat16 hw = __float2bfloat16(v.w);
    __nv_bfloat162* hp = reinterpret_cast<__nv_bfloat162*>(hi);
    __nv_bfloat162* lp = reinterpret_cast<__nv_bfloat162*>(lo);
    hp[2*i]   = __nv_bfloat162(hx, hy);
    hp[2*i+1] = __nv_bfloat162(hz, hw);
    lp[2*i]   = __nv_bfloat162(__float2bfloat16(v.x - __bfloat162float(hx)),
                               __float2bfloat16(v.y - __bfloat162float(hy)));
    lp[2*i+1] = __nv_bfloat162(__float2bfloat16(v.z - __bfloat162float(hz)),
                               __float2bfloat16(v.w - __bfloat162float(hw)));
}

// ---------------------------------------------------------------------------
// HMMA split-3 GEMM, cp.async double-buffered, single sync per chunk.
// MMA terms interleaved across 4 independent accumulators (dep distance 4);
// per-accumulator term order hh -> hl -> lh (bit-identical to R6).
// 128x256 tile, 512 threads (16 warps: 4 M x 4 N), K-chunk 32.
// ---------------------------------------------------------------------------
#define GST 61440   // stage stride bytes
#define GEMM_SMEM (2 * GST)

__global__ __launch_bounds__(512, 1) void hgemm_s3(
    const __nv_bfloat16* __restrict__ Ahi, const __nv_bfloat16* __restrict__ Alo,
    const __nv_bfloat16* __restrict__ Bhi, const __nv_bfloat16* __restrict__ Blo,
    float* __restrict__ C, int N, int K)
{
    extern __shared__ __align__(16) char dsm[];
    const uint32_t sb = smem_u32(dsm);
    const int tid = threadIdx.x;
    const int lane = tid & 31;
    const int wid = tid >> 5;
    const int wm = wid & 3;          // 4 M-groups x 32 rows
    const int wn = wid >> 2;         // 4 N-groups x 64 cols
    const int bm = blockIdx.y * 128;
    const int bn = blockIdx.x * 256;

    float c[2][8][4];
#pragma unroll
    for (int i = 0; i < 2; i++)
#pragma unroll
        for (int nf = 0; nf < 8; nf++)
#pragma unroll
            for (int e = 0; e < 4; e++) c[i][nf][e] = 0.f;

    const int nch = K / 32;

#define GEMM_STAGE_LOAD(stbase, kk)                                            \
    {                                                                          \
        const uint32_t _b = (stbase);                                          \
        const int _k8 = (kk) * 32;                                             \
        { int idx = tid;        int row = idx >> 2, c8 = (idx & 3) * 8;        \
          cpa16(_b + row * 80 + c8 * 2,                                        \
                Ahi + (size_t)(bm + row) * K + _k8 + c8); }                    \
        { int idx = tid;        int row = idx >> 2, c8 = (idx & 3) * 8;        \
          cpa16(_b + 10240 + row * 80 + c8 * 2,                                \
                Alo + (size_t)(bm + row) * K + _k8 + c8); }                    \
        { int idx = tid;        int row = idx >> 2, c8 = (idx & 3) * 8;        \
          cpa16(_b + 20480 + row * 80 + c8 * 2,                                \
                Bhi + (size_t)(bn + row) * K + _k8 + c8); }                    \
        { int idx = 512 + tid;  int row = idx >> 2, c8 = (idx & 3) * 8;        \
          cpa16(_b + 20480 + row * 80 + c8 * 2,                                \
                Bhi + (size_t)(bn + row) * K + _k8 + c8); }                    \
        { int idx = tid;        int row = idx >> 2, c8 = (idx & 3) * 8;        \
          cpa16(_b + 40960 + row * 80 + c8 * 2,                                \
                Blo + (size_t)(bn + row) * K + _k8 + c8); }                    \
        { int idx = 512 + tid;  int row = idx >> 2, c8 = (idx & 3) * 8;        \
          cpa16(_b + 40960 + row * 80 + c8 * 2,                                \
                Blo + (size_t)(bn + row) * K + _k8 + c8); }                    \
    }

    GEMM_STAGE_LOAD(sb, 0);
    cpa_commit();

    for (int ck = 0; ck < nch; ck++) {
        cpa_wait<0>();
        __syncthreads();
        if (ck + 1 < nch) {
            GEMM_STAGE_LOAD(sb + ((ck + 1) & 1) * GST, ck + 1);
            cpa_commit();
        }

        const uint32_t st = sb + (ck & 1) * GST;
        const uint32_t sAh = st, sAl = st + 10240, sBh = st + 20480, sBl = st + 40960;
#pragma unroll
        for (int ks = 0; ks < 2; ks++) {
            uint32_t ah[2][4], al[2][4];
#pragma unroll
            for (int i = 0; i < 2; i++) {
                int row = wm * 32 + i * 16 + (lane & 15);
                int col = ks * 16 + (lane >> 4) * 8;
                uint32_t off = (uint32_t)(row * 80 + col * 2);
                ldm4(ah[i], sAh + off);
                ldm4(al[i], sAl + off);
            }
#pragma unroll
            for (int nfp = 0; nfp < 4; nfp++) {
                int g = lane >> 3;
                int row = wn * 64 + nfp * 16 + ((g >= 2) ? 8 : 0) + (lane & 7);
                int col = ks * 16 + ((g & 1) ? 8 : 0);
                uint32_t off = (uint32_t)(row * 80 + col * 2);
                uint32_t bh[4], bl[4];
                ldm4(bh, sBh + off);
                ldm4(bl, sBl + off);
                // term hh across 4 independent accumulators
                mma16816(c[0][2*nfp],   ah[0], bh);
                mma16816(c[1][2*nfp],   ah[1], bh);
                mma16816(c[0][2*nfp+1], ah[0], bh + 2);
                mma16816(c[1][2*nfp+1], ah[1], bh + 2);
                // term hl
                mma16816(c[0][2*nfp],   ah[0], bl);
                mma16816(c[1][2*nfp],   ah[1], bl);
                mma16816(c[0][2*nfp+1], ah[0], bl + 2);
                mma16816(c[1][2*nfp+1], ah[1], bl + 2);
                // term lh
                mma16816(c[0][2*nfp],   al[0], bh);
                mma16816(c[1][2*nfp],   al[1], bh);
                mma16816(c[0][2*nfp+1], al[0], bh + 2);
                mma16816(c[1][2*nfp+1], al[1], bh + 2);
            }
        }
    }

#pragma unroll
    for (int i = 0; i < 2; i++) {
#pragma unroll
        for (int nf = 0; nf < 8; nf++) {
            int row = bm + wm * 32 + i * 16 + (lane >> 2);
            int col = bn + wn * 64 + nf * 8 + (lane & 3) * 2;
            *(float2*)(C + (size_t)row * N + col) = make_float2(c[i][nf][0], c[i][nf][1]);
            *(float2*)(C + (size_t)(row + 8) * N + col) = make_float2(c[i][nf][2], c[i][nf][3]);
        }
    }
}

// ---------------------------------------------------------------------------
// RoPE tables (verified)
// ---------------------------------------------------------------------------
__global__ void rope_tables()
{
    int idx = blockIdx.x * blockDim.x + threadIdx.x;
    if (idx >= SSQ * 32) return;
    int s = idx >> 5;
    int i = idx & 31;
    double inv_d = exp(-(double)i * (9.210340371976184 / 32.0));
    float  ang_f = (float)s * (float)inv_d;
    double c, sn;
    sincos((double)ang_f, &sn, &c);
    g_cos[idx] = (float)c;
    g_sin[idx] = (float)sn;
}

__device__ __forceinline__ void split_store(__nv_bfloat16* hi, __nv_bfloat16* lo,
                                            size_t idx, float v)
{
    __nv_bfloat16 h = __float2bfloat16(v);
    hi[idx] = h;
    lo[idx] = __float2bfloat16(v - __bfloat162float(h));
}

// RoPE + split + relayout to [b,h,s,d]. q pre-scaled by 1/sqrt(64).
__global__ __launch_bounds__(512) void rope_split()
{
    int s = blockIdx.x;
    int b = blockIdx.y;
    int h = threadIdx.x >> 5;
    int i = threadIdx.x & 31;

    float c  = g_cos[s * 32 + i];
    float sn = g_sin[s * 32 + i];

    size_t row  = ((size_t)(b * SSQ + s)) * NQKV + (size_t)h * HD;
    size_t orow = ((size_t)((b * NH + h) * SSQ) + s) * HD;

    float q1 = g_qkv[row + i];
    float q2 = g_qkv[row + 32 + i];
    split_store(g_qh, g_ql, orow + i,      (q1 * c - q2 * sn) * 0.125f);
    split_store(g_qh, g_ql, orow + 32 + i, (q1 * sn + q2 * c) * 0.125f);

    float k1 = g_qkv[row + DIM + i];
    float k2 = g_qkv[row + DIM + 32 + i];
    split_store(g_kh, g_kl, orow + i,      k1 * c - k2 * sn);
    split_store(g_kh, g_kl, orow + 32 + i, k1 * sn + k2 * c);

    split_store(g_vh, g_vl, orow + i,      g_qkv[row + 2 * DIM + i]);
    split_store(g_vh, g_vl, orow + 32 + i, g_qkv[row + 2 * DIM + 32 + i]);
}

// ---------------------------------------------------------------------------
// HMMA flash attention (causal), pre-split bf16 inputs, cp.async 2-stage KV,
// single sync per KV tile; MMA terms interleaved across accumulator pairs.
// Block = 128 queries of one (b,h), 256 threads (8 warps x 16 query rows).
// ---------------------------------------------------------------------------
#define KVST 36864    // KV stage stride bytes
#define ATTN_SMEM (2 * KVST)

__global__ __launch_bounds__(256, 1) void attn_tc()
{
    extern __shared__ __align__(16) char dsm[];
    const uint32_t sb = smem_u32(dsm);

    const int tid  = threadIdx.x;
    const int lane = tid & 31;
    const int wid  = tid >> 5;
    const int qb   = blockIdx.x;          // 0..15
    const int h    = blockIdx.y;
    const int b    = blockIdx.z;

    const size_t head = (size_t)(b * NH + h) * SSQ * HD;
    const __nv_bfloat16* qhg = g_qh + head + (size_t)qb * 128 * HD;
    const __nv_bfloat16* qlg = g_ql + head + (size_t)qb * 128 * HD;

    // ---- stage Q (Qh @ sb, Ql @ sb+18432) ----
#pragma unroll
    for (int i = 0; i < 8; i++) {
        int g = i * 256 + tid;
        int mat = g >> 10;
        int idx = g & 1023;
        int row = idx >> 3;
        int c8 = (idx & 7) * 8;
        cpa16(sb + mat * 18432 + row * 144 + c8 * 2,
              (mat ? qlg : qhg) + row * HD + c8);
    }
    cpa_commit();
    cpa_wait<0>();
    __syncthreads();

    // ---- extract Q fragments ----
    uint32_t qh[4][4], ql[4][4];
#pragma unroll
    for (int ks = 0; ks < 4; ks++) {
        int row = wid * 16 + (lane & 15);
        int col = ks * 16 + (lane >> 4) * 8;
        uint32_t off = (uint32_t)(row * 144 + col * 2);
        ldm4(qh[ks], sb + off);
        ldm4(ql[ks], sb + 18432 + off);
    }
    __syncthreads();   // Q reads done; stage-0 region reusable for KV

    float m0 = -1e30f, m1 = -1e30f, l0 = 0.f, l1 = 0.f;
    float o[8][4];
#pragma unroll
    for (int df = 0; df < 8; df++)
#pragma unroll
        for (int e = 0; e < 4; e++) o[df][e] = 0.f;

    const int qi0 = qb * 128 + wid * 16 + (lane >> 2);
    const int qi1 = qi0 + 8;
    const int ntiles = 2 * qb + 2;

    const __nv_bfloat16* kvg[4] = {g_kh + head, g_kl + head, g_vh + head, g_vl + head};

    // ---- prologue: KV tile 0 into stage 0 ----
#pragma unroll
    for (int i = 0; i < 8; i++) {
        int g = i * 256 + tid;
        int mat = g >> 9;
        int idx = g & 511;
        int row = idx >> 3;
        int c8 = (idx & 7) * 8;
        cpa16(sb + mat * 9216 + row * 144 + c8 * 2, kvg[mat] + row * HD + c8);
    }
    cpa_commit();

    for (int kt = 0; kt < ntiles; kt++) {
        cpa_wait<0>();
        __syncthreads();
        if (kt + 1 < ntiles) {
            const uint32_t base = sb + ((kt + 1) & 1) * KVST;
            const size_t koff = (size_t)(kt + 1) * 64 * HD;
#pragma unroll
            for (int i = 0; i < 8; i++) {
                int g = i * 256 + tid;
                int mat = g >> 9;
                int idx = g & 511;
                int row = idx >> 3;
                int c8 = (idx & 7) * 8;
                cpa16(base + mat * 9216 + row * 144 + c8 * 2,
                      kvg[mat] + koff + row * HD + c8);
            }
            cpa_commit();
        }

        const uint32_t st = sb + (kt & 1) * KVST;
        const uint32_t sKh = st, sKl = st + 9216, sVh = st + 18432, sVl = st + 27648;

        // ---- scores: S(16x64) = Q @ K^T, split-3, interleaved terms ----
        float s[8][4];
#pragma unroll
        for (int nf = 0; nf < 8; nf++)
#pragma unroll
            for (int e = 0; e < 4; e++) s[nf][e] = 0.f;

#pragma unroll
        for (int ks = 0; ks < 4; ks++) {
#pragma unroll
            for (int nfp = 0; nfp < 4; nfp++) {
                int g = lane >> 3;
                int row = nfp * 16 + ((g >= 2) ? 8 : 0) + (lane & 7);
                int col = ks * 16 + ((g & 1) ? 8 : 0);
                uint32_t off = (uint32_t)(row * 144 + col * 2);
                uint32_t bh[4], bl[4];
                ldm4(bh, sKh + off);
                ldm4(bl, sKl + off);
                mma16816(s[2*nfp],   qh[ks], bh);
                mma16816(s[2*nfp+1], qh[ks], bh + 2);
                mma16816(s[2*nfp],   qh[ks], bl);
                mma16816(s[2*nfp+1], qh[ks], bl + 2);
                mma16816(s[2*nfp],   ql[ks], bh);
                mma16816(s[2*nfp+1], ql[ks], bh + 2);
            }
        }

        // ---- causal mask ----
        if (kt >= 2 * qb) {
            int kbase = kt * 64 + (lane & 3) * 2;
#pragma unroll
            for (int nf = 0; nf < 8; nf++) {
                int kj = kbase + nf * 8;
                if (kj     > qi0) s[nf][0] = -1e30f;
                if (kj + 1 > qi0) s[nf][1] = -1e30f;
                if (kj     > qi1) s[nf][2] = -1e30f;
                if (kj + 1 > qi1) s[nf][3] = -1e30f;
            }
        }

        // ---- online softmax ----
        float rmax0 = -1e30f, rmax1 = -1e30f;
#pragma unroll
        for (int nf = 0; nf < 8; nf++) {
            rmax0 = fmaxf(rmax0, fmaxf(s[nf][0], s[nf][1]));
            rmax1 = fmaxf(rmax1, fmaxf(s[nf][2], s[nf][3]));
        }
        rmax0 = fmaxf(rmax0, __shfl_xor_sync(0xFFFFFFFFu, rmax0, 1));
        rmax0 = fmaxf(rmax0, __shfl_xor_sync(0xFFFFFFFFu, rmax0, 2));
        rmax1 = fmaxf(rmax1, __shfl_xor_sync(0xFFFFFFFFu, rmax1, 1));
        rmax1 = fmaxf(rmax1, __shfl_xor_sync(0xFFFFFFFFu, rmax1, 2));

        float mn0 = fmaxf(m0, rmax0);
        float mn1 = fmaxf(m1, rmax1);
        float corr0 = __expf(m0 - mn0);
        float corr1 = __expf(m1 - mn1);
        m0 = mn0; m1 = mn1;
        l0 *= corr0; l1 *= corr1;
#pragma unroll
        for (int df = 0; df < 8; df++) {
            o[df][0] *= corr0; o[df][1] *= corr0;
            o[df][2] *= corr1; o[df][3] *= corr1;
        }

        uint32_t ph01[8], ph23[8], pl01[8], pl23[8];
#pragma unroll
        for (int nf = 0; nf < 8; nf++) {
            float p0 = __expf(s[nf][0] - m0);
            float p1 = __expf(s[nf][1] - m0);
            float p2 = __expf(s[nf][2] - m1);
            float p3 = __expf(s[nf][3] - m1);
            l0 += p0 + p1;
            l1 += p2 + p3;
            float h0 = __bfloat162float(__float2bfloat16(p0));
            float h1 = __bfloat162float(__float2bfloat16(p1));
            float h2 = __bfloat162float(__float2bfloat16(p2));
            float h3 = __bfloat162float(__float2bfloat16(p3));
            ph01[nf] = pack_bf16x2(h0, h1);
            ph23[nf] = pack_bf16x2(h2, h3);
            pl01[nf] = pack_bf16x2(p0 - h0, p1 - h1);
            pl23[nf] = pack_bf16x2(p2 - h2, p3 - h3);
        }

        // ---- O += P @ V : split-2 x split-2 (drop plo*vlo), interleaved ----
#pragma unroll
        for (int ks = 0; ks < 4; ks++) {
            uint32_t aPh[4] = {ph01[2*ks], ph23[2*ks], ph01[2*ks+1], ph23[2*ks+1]};
            uint32_t aPl[4] = {pl01[2*ks], pl23[2*ks], pl01[2*ks+1], pl23[2*ks+1]};
#pragma unroll
            for (int dfp = 0; dfp < 4; dfp++) {
                int g = lane >> 3;
                int row = ks * 16 + ((g & 1) ? 8 : 0) + (lane & 7);
                int col = dfp * 16 + ((g >= 2) ? 8 : 0);
                uint32_t off = (uint32_t)(row * 144 + col * 2);
                uint32_t bv[4], bvl[4];
                ldm4t(bv,  sVh + off);
                ldm4t(bvl, sVl + off);
                mma16816(o[2*dfp],   aPh, bv);
                mma16816(o[2*dfp+1], aPh, bv + 2);
                mma16816(o[2*dfp],   aPh, bvl);
                mma16816(o[2*dfp+1], aPh, bvl + 2);
                mma16816(o[2*dfp],   aPl, bv);
                mma16816(o[2*dfp+1], aPl, bv + 2);
            }
        }
    }

    // ---- finalize: normalize, split, store to GEMM-A hi/lo ----
    l0 += __shfl_xor_sync(0xFFFFFFFFu, l0, 1);
    l0 += __shfl_xor_sync(0xFFFFFFFFu, l0, 2);
    l1 += __shfl_xor_sync(0xFFFFFFFFu, l1, 1);
    l1 += __shfl_xor_sync(0xFFFFFFFFu, l1, 2);
    float inv0 = 1.0f / l0;
    float inv1 = 1.0f / l1;

#pragma unroll
    for (int df = 0; df < 8; df++) {
        int col = h * HD + df * 8 + (lane & 3) * 2;
        size_t r0 = (size_t)(b * SSQ + qi0) * DIM + col;
        size_t r1 = (size_t)(b * SSQ + qi1) * DIM + col;
        float v0 = o[df][0] * inv0, v1 = o[df][1] * inv0;
        float v2 = o[df][2] * inv1, v3 = o[df][3] * inv1;
        float h0 = __bfloat162float(__float2bfloat16(v0));
        float h1 = __bfloat162float(__float2bfloat16(v1));
        float h2 = __bfloat162float(__float2bfloat16(v2));
        float h3 = __bfloat162float(__float2bfloat16(v3));
        *(uint32_t*)(g_ahi + r0) = pack_bf16x2(h0, h1);
        *(uint32_t*)(g_alo + r0) = pack_bf16x2(v0 - h0, v1 - h1);
        *(uint32_t*)(g_ahi + r1) = pack_bf16x2(h2, h3);
        *(uint32_t*)(g_alo + r1) = pack_bf16x2(v2 - h2, v3 - h3);
    }
}

// ---------------------------------------------------------------------------
extern "C" void kernel_launch(void* const* d_in, const int* in_sizes, int n_in,
                              void* d_out, int out_size)
{
    const float* x = nullptr;
    const float* wqkv = nullptr;
    const float* wout = nullptr;
    for (int i = 0; i < n_in; i++) {
        long long n = in_sizes[i];
        if (n == (long long)MROWS * DIM)      x    = (const float*)d_in[i];
        else if (n == (long long)NQKV * DIM)  wqkv = (const float*)d_in[i];
        else if (n == (long long)DIM * DIM)   wout = (const float*)d_in[i];
    }
    if (!x || !wqkv || !wout) return;

    float* qkv = nullptr;
    __nv_bfloat16 *ahi, *alo, *whi, *wlo, *vhi, *vlo;
    cudaGetSymbolAddress((void**)&qkv, g_qkv);
    cudaGetSymbolAddress((void**)&ahi, g_ahi);
    cudaGetSymbolAddress((void**)&alo, g_alo);
    cudaGetSymbolAddress((void**)&whi, g_whi);
    cudaGetSymbolAddress((void**)&wlo, g_wlo);
    cudaGetSymbolAddress((void**)&vhi, g_vhi);
    cudaGetSymbolAddress((void**)&vlo, g_vlo);

    cudaFuncSetAttribute(hgemm_s3, cudaFuncAttributeMaxDynamicSharedMemorySize,
                         GEMM_SMEM);
    cudaFuncSetAttribute(attn_tc, cudaFuncAttributeMaxDynamicSharedMemorySize,
                         ATTN_SMEM);

    // 0) bf16 hi/lo splits of inputs
    cvt_split<<<(MROWS * DIM / 4 + 255) / 256, 256>>>(x, ahi, alo, MROWS * DIM / 4);
    cvt_split<<<(NQKV * DIM / 4 + 255) / 256, 256>>>(wqkv, whi, wlo, NQKV * DIM / 4);
    cvt_split<<<(DIM * DIM / 4 + 255) / 256, 256>>>(wout, vhi, vlo, DIM * DIM / 4);

    // 1) qkv = x @ Wqkv^T
    dim3 g1(NQKV / 256, MROWS / 128);
    hgemm_s3<<<g1, 512, GEMM_SMEM>>>(ahi, alo, whi, wlo, qkv, NQKV, DIM);

    // 2) RoPE + split + relayout
    rope_tables<<<(SSQ * 32) / 256, 256>>>();
    dim3 gr(SSQ, BB);
    rope_split<<<gr, 512>>>();

    // 3) flash attention (writes g_ahi/g_alo directly)
    dim3 ga(SSQ / 128, NH, BB);
    attn_tc<<<ga, 256, ATTN_SMEM>>>();

    // 4) out = att @ Wout^T
    dim3 g2(DIM / 256, MROWS / 128);
    hgemm_s3<<<g2, 512, GEMM_SMEM>>>(ahi, alo, vhi, vlo, (float*)d_out, DIM, DIM);
}

// round 9
// speedup vs baseline: 3.7092x; 1.0030x over previous
#include <cuda_runtime.h>
#include <cuda_bf16.h>
#include <math.h>
#include <stdint.h>

#define BB 4
#define SSQ 2048
#define DIM 1024
#define NH 16
#define HD 64
#define MROWS (BB*SSQ)       // 8192
#define NQKV (3*DIM)         // 3072
#define HEADS_ELEMS ((size_t)BB * NH * SSQ * HD)   // 8.4M

// ---------------- scratch (device globals; allocation-free) ----------------
__device__ float g_qkv[(size_t)MROWS * NQKV];   // 96 MB (fp32 qkv after GEMM1)
__device__ float g_cos[SSQ * 32];
__device__ float g_sin[SSQ * 32];
__device__ __nv_bfloat16 g_ahi[(size_t)MROWS * DIM];   // GEMM A operand hi/lo
__device__ __nv_bfloat16 g_alo[(size_t)MROWS * DIM];
__device__ __nv_bfloat16 g_whi[(size_t)NQKV * DIM];
__device__ __nv_bfloat16 g_wlo[(size_t)NQKV * DIM];
__device__ __nv_bfloat16 g_vhi[(size_t)DIM * DIM];
__device__ __nv_bfloat16 g_vlo[(size_t)DIM * DIM];
// pre-split, rope'd, head-contiguous q/k/v: [b,h,s,d]
__device__ __nv_bfloat16 g_qh[HEADS_ELEMS], g_ql[HEADS_ELEMS];
__device__ __nv_bfloat16 g_kh[HEADS_ELEMS], g_kl[HEADS_ELEMS];
__device__ __nv_bfloat16 g_vh[HEADS_ELEMS], g_vl[HEADS_ELEMS];

// ---------------- PTX helpers (plain sm_103-safe) ---------------------------
__device__ __forceinline__ uint32_t smem_u32(const void* p) {
    uint32_t a;
    asm("{ .reg .u64 t; cvta.to.shared.u64 t, %1; cvt.u32.u64 %0, t; }"
        : "=r"(a) : "l"(p));
    return a;
}
__device__ __forceinline__ void mma16816(float* c, const uint32_t* a, const uint32_t* b) {
    asm volatile(
        "mma.sync.aligned.m16n8k16.row.col.f32.bf16.bf16.f32 "
        "{%0,%1,%2,%3}, {%4,%5,%6,%7}, {%8,%9}, {%0,%1,%2,%3};"
        : "+f"(c[0]), "+f"(c[1]), "+f"(c[2]), "+f"(c[3])
        : "r"(a[0]), "r"(a[1]), "r"(a[2]), "r"(a[3]), "r"(b[0]), "r"(b[1]));
}
__device__ __forceinline__ void ldm4(uint32_t* r, uint32_t addr) {
    asm volatile("ldmatrix.sync.aligned.m8n8.x4.shared.b16 {%0,%1,%2,%3}, [%4];"
                 : "=r"(r[0]), "=r"(r[1]), "=r"(r[2]), "=r"(r[3]) : "r"(addr));
}
__device__ __forceinline__ void ldm4t(uint32_t* r, uint32_t addr) {
    asm volatile("ldmatrix.sync.aligned.m8n8.x4.trans.shared.b16 {%0,%1,%2,%3}, [%4];"
                 : "=r"(r[0]), "=r"(r[1]), "=r"(r[2]), "=r"(r[3]) : "r"(addr));
}
__device__ __forceinline__ uint32_t pack_bf16x2(float lo, float hi) {
    uint32_t d;
    asm("cvt.rn.bf16x2.f32 %0, %1, %2;" : "=r"(d) : "f"(hi), "f"(lo));
    return d;
}
__device__ __forceinline__ void cpa16(uint32_t dst, const void* src) {
    asm volatile("cp.async.cg.shared.global [%0], [%1], 16;"
                 :: "r"(dst), "l"(src) : "memory");
}
__device__ __forceinline__ void cpa_commit() {
    asm volatile("cp.async.commit_group;" ::: "memory");
}
template <int N>
__device__ __forceinline__ void cpa_wait() {
    asm volatile("cp.async.wait_group %0;" :: "n"(N) : "memory");
}

// ---------------------------------------------------------------------------
// fp32 -> bf16 hi/lo split (4 elems per thread)
// ---------------------------------------------------------------------------
__global__ void cvt_split(const float* __restrict__ in,
                          __nv_bfloat16* __restrict__ hi,
                          __nv_bfloat16* __restrict__ lo, int n4)
{
    int i = blockIdx.x * blockDim.x + threadIdx.x;
    if (i >= n4) return;
    float4 v = ((const float4*)in)[i];
    __nv_bfloat16 hx = __float2bfloat16(v.x);
    __nv_bfloat16 hy = __float2bfloat16(v.y);
    __nv_bfloat16 hz = __float2bfloat16(v.z);
    __nv_bfloat16 hw = __float2bfloat16(v.w);
    __nv_bfloat162* hp = reinterpret_cast<__nv_bfloat162*>(hi);
    __nv_bfloat162* lp = reinterpret_cast<__nv_bfloat162*>(lo);
    hp[2*i]   = __nv_bfloat162(hx, hy);
    hp[2*i+1] = __nv_bfloat162(hz, hw);
    lp[2*i]   = __nv_bfloat162(__float2bfloat16(v.x - __bfloat162float(hx)),
                               __float2bfloat16(v.y - __bfloat162float(hy)));
    lp[2*i+1] = __nv_bfloat162(__float2bfloat16(v.z - __bfloat162float(hz)),
                               __float2bfloat16(v.w - __bfloat162float(hw)));
}

// ---------------------------------------------------------------------------
// HMMA split-3 GEMM, fat-warp layout for smem-BW relief.
// C[M,N] = (Ahi+Alo)[M,K] @ (Bhi+Blo)[N,K]^T (fp32 accum)
// 128x256 tile, 256 threads (8 warps: 2 M-groups x 4 N-groups),
// each warp: 64 rows x 64 cols (4 M-frags x 8 N-frags = 128 accumulators).
// K-chunk 32, 2-stage cp.async. Stage = 61440 B.
// ---------------------------------------------------------------------------
#define GST 61440   // stage stride bytes
#define GEMM_SMEM (2 * GST)

__global__ __launch_bounds__(256, 1) void hgemm_s3(
    const __nv_bfloat16* __restrict__ Ahi, const __nv_bfloat16* __restrict__ Alo,
    const __nv_bfloat16* __restrict__ Bhi, const __nv_bfloat16* __restrict__ Blo,
    float* __restrict__ C, int N, int K)
{
    extern __shared__ __align__(16) char dsm[];
    const uint32_t sb = smem_u32(dsm);
    const int tid = threadIdx.x;
    const int lane = tid & 31;
    const int wid = tid >> 5;
    const int wm = wid & 1;          // 2 M-groups x 64 rows
    const int wn = wid >> 1;         // 4 N-groups x 64 cols
    const int bm = blockIdx.y * 128;
    const int bn = blockIdx.x * 256;

    float c[4][8][4];
#pragma unroll
    for (int i = 0; i < 4; i++)
#pragma unroll
        for (int nf = 0; nf < 8; nf++)
#pragma unroll
            for (int e = 0; e < 4; e++) c[i][nf][e] = 0.f;

    const int nch = K / 32;

    // stage layout: Ahi @0 (128x40x2B), Alo @10240, Bhi @20480 (256x40x2B), Blo @40960
#define GEMM_STAGE_LOAD(stbase, kk)                                            \
    {                                                                          \
        const uint32_t _b = (stbase);                                          \
        const int _k8 = (kk) * 32;                                             \
        _Pragma("unroll")                                                      \
        for (int it = 0; it < 2; it++) {                                       \
            int idx = it * 256 + tid;                                          \
            int row = idx >> 2, c8 = (idx & 3) * 8;                            \
            cpa16(_b + row * 80 + c8 * 2,                                      \
                  Ahi + (size_t)(bm + row) * K + _k8 + c8);                    \
            cpa16(_b + 10240 + row * 80 + c8 * 2,                              \
                  Alo + (size_t)(bm + row) * K + _k8 + c8);                    \
        }                                                                      \
        _Pragma("unroll")                                                      \
        for (int it = 0; it < 4; it++) {                                       \
            int idx = it * 256 + tid;                                          \
            int row = idx >> 2, c8 = (idx & 3) * 8;                            \
            cpa16(_b + 20480 + row * 80 + c8 * 2,                              \
                  Bhi + (size_t)(bn + row) * K + _k8 + c8);                    \
            cpa16(_b + 40960 + row * 80 + c8 * 2,                              \
                  Blo + (size_t)(bn + row) * K + _k8 + c8);                    \
        }                                                                      \
    }

    GEMM_STAGE_LOAD(sb, 0);
    cpa_commit();

    for (int ck = 0; ck < nch; ck++) {
        cpa_wait<0>();
        __syncthreads();
        if (ck + 1 < nch) {
            GEMM_STAGE_LOAD(sb + ((ck + 1) & 1) * GST, ck + 1);
            cpa_commit();
        }

        const uint32_t st = sb + (ck & 1) * GST;
        const uint32_t sAh = st, sAl = st + 10240, sBh = st + 20480, sBl = st + 40960;
#pragma unroll
        for (int ks = 0; ks < 2; ks++) {
            uint32_t ah[4][4], al[4][4];
#pragma unroll
            for (int i = 0; i < 4; i++) {
                int row = wm * 64 + i * 16 + (lane & 15);
                int col = ks * 16 + (lane >> 4) * 8;
                uint32_t off = (uint32_t)(row * 80 + col * 2);
                ldm4(ah[i], sAh + off);
                ldm4(al[i], sAl + off);
            }
#pragma unroll
            for (int nfp = 0; nfp < 4; nfp++) {
                int g = lane >> 3;
                int row = wn * 64 + nfp * 16 + ((g >= 2) ? 8 : 0) + (lane & 7);
                int col = ks * 16 + ((g & 1) ? 8 : 0);
                uint32_t off = (uint32_t)(row * 80 + col * 2);
                uint32_t bh[4], bl[4];
                ldm4(bh, sBh + off);
                ldm4(bl, sBl + off);
                // term hh across 8 independent accumulators
#pragma unroll
                for (int i = 0; i < 4; i++) {
                    mma16816(c[i][2*nfp],   ah[i], bh);
                    mma16816(c[i][2*nfp+1], ah[i], bh + 2);
                }
                // term hl
#pragma unroll
                for (int i = 0; i < 4; i++) {
                    mma16816(c[i][2*nfp],   ah[i], bl);
                    mma16816(c[i][2*nfp+1], ah[i], bl + 2);
                }
                // term lh
#pragma unroll
                for (int i = 0; i < 4; i++) {
                    mma16816(c[i][2*nfp],   al[i], bh);
                    mma16816(c[i][2*nfp+1], al[i], bh + 2);
                }
            }
        }
    }

#pragma unroll
    for (int i = 0; i < 4; i++) {
#pragma unroll
        for (int nf = 0; nf < 8; nf++) {
            int row = bm + wm * 64 + i * 16 + (lane >> 2);
            int col = bn + wn * 64 + nf * 8 + (lane & 3) * 2;
            *(float2*)(C + (size_t)row * N + col) = make_float2(c[i][nf][0], c[i][nf][1]);
            *(float2*)(C + (size_t)(row + 8) * N + col) = make_float2(c[i][nf][2], c[i][nf][3]);
        }
    }
}

// ---------------------------------------------------------------------------
// RoPE tables (verified)
// ---------------------------------------------------------------------------
__global__ void rope_tables()
{
    int idx = blockIdx.x * blockDim.x + threadIdx.x;
    if (idx >= SSQ * 32) return;
    int s = idx >> 5;
    int i = idx & 31;
    double inv_d = exp(-(double)i * (9.210340371976184 / 32.0));
    float  ang_f = (float)s * (float)inv_d;
    double c, sn;
    sincos((double)ang_f, &sn, &c);
    g_cos[idx] = (float)c;
    g_sin[idx] = (float)sn;
}

__device__ __forceinline__ void split_store(__nv_bfloat16* hi, __nv_bfloat16* lo,
                                            size_t idx, float v)
{
    __nv_bfloat16 h = __float2bfloat16(v);
    hi[idx] = h;
    lo[idx] = __float2bfloat16(v - __bfloat162float(h));
}

// RoPE + split + relayout to [b,h,s,d]. q pre-scaled by 1/sqrt(64).
__global__ __launch_bounds__(512) void rope_split()
{
    int s = blockIdx.x;
    int b = blockIdx.y;
    int h = threadIdx.x >> 5;
    int i = threadIdx.x & 31;

    float c  = g_cos[s * 32 + i];
    float sn = g_sin[s * 32 + i];

    size_t row  = ((size_t)(b * SSQ + s)) * NQKV + (size_t)h * HD;
    size_t orow = ((size_t)((b * NH + h) * SSQ) + s) * HD;

    float q1 = g_qkv[row + i];
    float q2 = g_qkv[row + 32 + i];
    split_store(g_qh, g_ql, orow + i,      (q1 * c - q2 * sn) * 0.125f);
    split_store(g_qh, g_ql, orow + 32 + i, (q1 * sn + q2 * c) * 0.125f);

    float k1 = g_qkv[row + DIM + i];
    float k2 = g_qkv[row + DIM + 32 + i];
    split_store(g_kh, g_kl, orow + i,      k1 * c - k2 * sn);
    split_store(g_kh, g_kl, orow + 32 + i, k1 * sn + k2 * c);

    split_store(g_vh, g_vl, orow + i,      g_qkv[row + 2 * DIM + i]);
    split_store(g_vh, g_vl, orow + 32 + i, g_qkv[row + 2 * DIM + 32 + i]);
}

// ---------------------------------------------------------------------------
// HMMA flash attention (causal), pre-split bf16 inputs, cp.async 2-stage KV,
// single sync per KV tile. LPT: heavy (high-qb) blocks launch first.
// Block = 128 queries of one (b,h), 256 threads (8 warps x 16 query rows).
// ---------------------------------------------------------------------------
#define KVST 36864    // KV stage stride bytes
#define ATTN_SMEM (2 * KVST)

__global__ __launch_bounds__(256, 1) void attn_tc()
{
    extern __shared__ __align__(16) char dsm[];
    const uint32_t sb = smem_u32(dsm);

    const int tid  = threadIdx.x;
    const int lane = tid & 31;
    const int wid  = tid >> 5;
    const int qb   = (int)(gridDim.x - 1 - blockIdx.x);   // LPT: big blocks first
    const int h    = blockIdx.y;
    const int b    = blockIdx.z;

    const size_t head = (size_t)(b * NH + h) * SSQ * HD;
    const __nv_bfloat16* qhg = g_qh + head + (size_t)qb * 128 * HD;
    const __nv_bfloat16* qlg = g_ql + head + (size_t)qb * 128 * HD;

    // ---- stage Q (Qh @ sb, Ql @ sb+18432) ----
#pragma unroll
    for (int i = 0; i < 8; i++) {
        int g = i * 256 + tid;
        int mat = g >> 10;
        int idx = g & 1023;
        int row = idx >> 3;
        int c8 = (idx & 7) * 8;
        cpa16(sb + mat * 18432 + row * 144 + c8 * 2,
              (mat ? qlg : qhg) + row * HD + c8);
    }
    cpa_commit();
    cpa_wait<0>();
    __syncthreads();

    // ---- extract Q fragments ----
    uint32_t qh[4][4], ql[4][4];
#pragma unroll
    for (int ks = 0; ks < 4; ks++) {
        int row = wid * 16 + (lane & 15);
        int col = ks * 16 + (lane >> 4) * 8;
        uint32_t off = (uint32_t)(row * 144 + col * 2);
        ldm4(qh[ks], sb + off);
        ldm4(ql[ks], sb + 18432 + off);
    }
    __syncthreads();   // Q reads done; stage-0 region reusable for KV

    float m0 = -1e30f, m1 = -1e30f, l0 = 0.f, l1 = 0.f;
    float o[8][4];
#pragma unroll
    for (int df = 0; df < 8; df++)
#pragma unroll
        for (int e = 0; e < 4; e++) o[df][e] = 0.f;

    const int qi0 = qb * 128 + wid * 16 + (lane >> 2);
    const int qi1 = qi0 + 8;
    const int ntiles = 2 * qb + 2;

    const __nv_bfloat16* kvg[4] = {g_kh + head, g_kl + head, g_vh + head, g_vl + head};

    // ---- prologue: KV tile 0 into stage 0 ----
#pragma unroll
    for (int i = 0; i < 8; i++) {
        int g = i * 256 + tid;
        int mat = g >> 9;
        int idx = g & 511;
        int row = idx >> 3;
        int c8 = (idx & 7) * 8;
        cpa16(sb + mat * 9216 + row * 144 + c8 * 2, kvg[mat] + row * HD + c8);
    }
    cpa_commit();

    for (int kt = 0; kt < ntiles; kt++) {
        cpa_wait<0>();
        __syncthreads();
        if (kt + 1 < ntiles) {
            const uint32_t base = sb + ((kt + 1) & 1) * KVST;
            const size_t koff = (size_t)(kt + 1) * 64 * HD;
#pragma unroll
            for (int i = 0; i < 8; i++) {
                int g = i * 256 + tid;
                int mat = g >> 9;
                int idx = g & 511;
                int row = idx >> 3;
                int c8 = (idx & 7) * 8;
                cpa16(base + mat * 9216 + row * 144 + c8 * 2,
                      kvg[mat] + koff + row * HD + c8);
            }
            cpa_commit();
        }

        const uint32_t st = sb + (kt & 1) * KVST;
        const uint32_t sKh = st, sKl = st + 9216, sVh = st + 18432, sVl = st + 27648;

        // ---- scores: S(16x64) = Q @ K^T, split-3 ----
        float s[8][4];
#pragma unroll
        for (int nf = 0; nf < 8; nf++)
#pragma unroll
            for (int e = 0; e < 4; e++) s[nf][e] = 0.f;

#pragma unroll
        for (int ks = 0; ks < 4; ks++) {
#pragma unroll
            for (int nfp = 0; nfp < 4; nfp++) {
                int g = lane >> 3;
                int row = nfp * 16 + ((g >= 2) ? 8 : 0) + (lane & 7);
                int col = ks * 16 + ((g & 1) ? 8 : 0);
                uint32_t off = (uint32_t)(row * 144 + col * 2);
                uint32_t bh[4], bl[4];
                ldm4(bh, sKh + off);
                ldm4(bl, sKl + off);
                mma16816(s[2*nfp],   qh[ks], bh);
                mma16816(s[2*nfp+1], qh[ks], bh + 2);
                mma16816(s[2*nfp],   qh[ks], bl);
                mma16816(s[2*nfp+1], qh[ks], bl + 2);
                mma16816(s[2*nfp],   ql[ks], bh);
                mma16816(s[2*nfp+1], ql[ks], bh + 2);
            }
        }

        // ---- causal mask ----
        if (kt >= 2 * qb) {
            int kbase = kt * 64 + (lane & 3) * 2;
#pragma unroll
            for (int nf = 0; nf < 8; nf++) {
                int kj = kbase + nf * 8;
                if (kj     > qi0) s[nf][0] = -1e30f;
                if (kj + 1 > qi0) s[nf][1] = -1e30f;
                if (kj     > qi1) s[nf][2] = -1e30f;
                if (kj + 1 > qi1) s[nf][3] = -1e30f;
            }
        }

        // ---- online softmax ----
        float rmax0 = -1e30f, rmax1 = -1e30f;
#pragma unroll
        for (int nf = 0; nf < 8; nf++) {
            rmax0 = fmaxf(rmax0, fmaxf(s[nf][0], s[nf][1]));
            rmax1 = fmaxf(rmax1, fmaxf(s[nf][2], s[nf][3]));
        }
        rmax0 = fmaxf(rmax0, __shfl_xor_sync(0xFFFFFFFFu, rmax0, 1));
        rmax0 = fmaxf(rmax0, __shfl_xor_sync(0xFFFFFFFFu, rmax0, 2));
        rmax1 = fmaxf(rmax1, __shfl_xor_sync(0xFFFFFFFFu, rmax1, 1));
        rmax1 = fmaxf(rmax1, __shfl_xor_sync(0xFFFFFFFFu, rmax1, 2));

        float mn0 = fmaxf(m0, rmax0);
        float mn1 = fmaxf(m1, rmax1);
        float corr0 = __expf(m0 - mn0);
        float corr1 = __expf(m1 - mn1);
        m0 = mn0; m1 = mn1;
        l0 *= corr0; l1 *= corr1;
#pragma unroll
        for (int df = 0; df < 8; df++) {
            o[df][0] *= corr0; o[df][1] *= corr0;
            o[df][2] *= corr1; o[df][3] *= corr1;
        }

        uint32_t ph01[8], ph23[8], pl01[8], pl23[8];
#pragma unroll
        for (int nf = 0; nf < 8; nf++) {
            float p0 = __expf(s[nf][0] - m0);
            float p1 = __expf(s[nf][1] - m0);
            float p2 = __expf(s[nf][2] - m1);
            float p3 = __expf(s[nf][3] - m1);
            l0 += p0 + p1;
            l1 += p2 + p3;
            float h0 = __bfloat162float(__float2bfloat16(p0));
            float h1 = __bfloat162float(__float2bfloat16(p1));
            float h2 = __bfloat162float(__float2bfloat16(p2));
            float h3 = __bfloat162float(__float2bfloat16(p3));
            ph01[nf] = pack_bf16x2(h0, h1);
            ph23[nf] = pack_bf16x2(h2, h3);
            pl01[nf] = pack_bf16x2(p0 - h0, p1 - h1);
            pl23[nf] = pack_bf16x2(p2 - h2, p3 - h3);
        }

        // ---- O += P @ V : split-2 x split-2 (drop plo*vlo) ----
#pragma unroll
        for (int ks = 0; ks < 4; ks++) {
            uint32_t aPh[4] = {ph01[2*ks], ph23[2*ks], ph01[2*ks+1], ph23[2*ks+1]};
            uint32_t aPl[4] = {pl01[2*ks], pl23[2*ks], pl01[2*ks+1], pl23[2*ks+1]};
#pragma unroll
            for (int dfp = 0; dfp < 4; dfp++) {
                int g = lane >> 3;
                int row = ks * 16 + ((g & 1) ? 8 : 0) + (lane & 7);
                int col = dfp * 16 + ((g >= 2) ? 8 : 0);
                uint32_t off = (uint32_t)(row * 144 + col * 2);
                uint32_t bv[4], bvl[4];
                ldm4t(bv,  sVh + off);
                ldm4t(bvl, sVl + off);
                mma16816(o[2*dfp],   aPh, bv);
                mma16816(o[2*dfp+1], aPh, bv + 2);
                mma16816(o[2*dfp],   aPh, bvl);
                mma16816(o[2*dfp+1], aPh, bvl + 2);
                mma16816(o[2*dfp],   aPl, bv);
                mma16816(o[2*dfp+1], aPl, bv + 2);
            }
        }
    }

    // ---- finalize: normalize, split, store to GEMM-A hi/lo ----
    l0 += __shfl_xor_sync(0xFFFFFFFFu, l0, 1);
    l0 += __shfl_xor_sync(0xFFFFFFFFu, l0, 2);
    l1 += __shfl_xor_sync(0xFFFFFFFFu, l1, 1);
    l1 += __shfl_xor_sync(0xFFFFFFFFu, l1, 2);
    float inv0 = 1.0f / l0;
    float inv1 = 1.0f / l1;

#pragma unroll
    for (int df = 0; df < 8; df++) {
        int col = h * HD + df * 8 + (lane & 3) * 2;
        size_t r0 = (size_t)(b * SSQ + qi0) * DIM + col;
        size_t r1 = (size_t)(b * SSQ + qi1) * DIM + col;
        float v0 = o[df][0] * inv0, v1 = o[df][1] * inv0;
        float v2 = o[df][2] * inv1, v3 = o[df][3] * inv1;
        float h0 = __bfloat162float(__float2bfloat16(v0));
        float h1 = __bfloat162float(__float2bfloat16(v1));
        float h2 = __bfloat162float(__float2bfloat16(v2));
        float h3 = __bfloat162float(__float2bfloat16(v3));
        *(uint32_t*)(g_ahi + r0) = pack_bf16x2(h0, h1);
        *(uint32_t*)(g_alo + r0) = pack_bf16x2(v0 - h0, v1 - h1);
        *(uint32_t*)(g_ahi + r1) = pack_bf16x2(h2, h3);
        *(uint32_t*)(g_alo + r1) = pack_bf16x2(v2 - h2, v3 - h3);
    }
}

// ---------------------------------------------------------------------------
extern "C" void kernel_launch(void* const* d_in, const int* in_sizes, int n_in,
                              void* d_out, int out_size)
{
    const float* x = nullptr;
    const float* wqkv = nullptr;
    const float* wout = nullptr;
    for (int i = 0; i < n_in; i++) {
        long long n = in_sizes[i];
        if (n == (long long)MROWS * DIM)      x    = (const float*)d_in[i];
        else if (n == (long long)NQKV * DIM)  wqkv = (const float*)d_in[i];
        else if (n == (long long)DIM * DIM)   wout = (const float*)d_in[i];
    }
    if (!x || !wqkv || !wout) return;

    float* qkv = nullptr;
    __nv_bfloat16 *ahi, *alo, *whi, *wlo, *vhi, *vlo;
    cudaGetSymbolAddress((void**)&qkv, g_qkv);
    cudaGetSymbolAddress((void**)&ahi, g_ahi);
    cudaGetSymbolAddress((void**)&alo, g_alo);
    cudaGetSymbolAddress((void**)&whi, g_whi);
    cudaGetSymbolAddress((void**)&wlo, g_wlo);
    cudaGetSymbolAddress((void**)&vhi, g_vhi);
    cudaGetSymbolAddress((void**)&vlo, g_vlo);

    cudaFuncSetAttribute(hgemm_s3, cudaFuncAttributeMaxDynamicSharedMemorySize,
                         GEMM_SMEM);
    cudaFuncSetAttribute(attn_tc, cudaFuncAttributeMaxDynamicSharedMemorySize,
                         ATTN_SMEM);

    // 0) bf16 hi/lo splits of inputs
    cvt_split<<<(MROWS * DIM / 4 + 255) / 256, 256>>>(x, ahi, alo, MROWS * DIM / 4);
    cvt_split<<<(NQKV * DIM / 4 + 255) / 256, 256>>>(wqkv, whi, wlo, NQKV * DIM / 4);
    cvt_split<<<(DIM * DIM / 4 + 255) / 256, 256>>>(wout, vhi, vlo, DIM * DIM / 4);

    // 1) qkv = x @ Wqkv^T
    dim3 g1(NQKV / 256, MROWS / 128);
    hgemm_s3<<<g1, 256, GEMM_SMEM>>>(ahi, alo, whi, wlo, qkv, NQKV, DIM);

    // 2) RoPE + split + relayout
    rope_tables<<<(SSQ * 32) / 256, 256>>>();
    dim3 gr(SSQ, BB);
    rope_split<<<gr, 512>>>();

    // 3) flash attention (writes g_ahi/g_alo directly)
    dim3 ga(SSQ / 128, NH, BB);
    attn_tc<<<ga, 256, ATTN_SMEM>>>();

    // 4) out = att @ Wout^T
    dim3 g2(DIM / 256, MROWS / 128);
    hgemm_s3<<<g2, 256, GEMM_SMEM>>>(ahi, alo, vhi, vlo, (float*)d_out, DIM, DIM);
}

// round 10
// speedup vs baseline: 4.4473x; 1.1990x over previous
#include <cuda_runtime.h>
#include <cuda_bf16.h>
#include <cuda_fp16.h>
#include <math.h>
#include <stdint.h>

#define BB 4
#define SSQ 2048
#define DIM 1024
#define NH 16
#define HD 64
#define MROWS (BB*SSQ)       // 8192
#define NQKV (3*DIM)         // 3072
#define HEADS_ELEMS ((size_t)BB * NH * SSQ * HD)   // 8.4M

// ---------------- scratch (device globals; allocation-free) ----------------
__device__ float g_qkv[(size_t)MROWS * NQKV];   // fp32 qkv after GEMM1
__device__ float g_cos[SSQ * 32];
__device__ float g_sin[SSQ * 32];
// GEMM operands (fp16 2-term scheme): A split-2, B single
__device__ __half g_ahi[(size_t)MROWS * DIM];
__device__ __half g_alo[(size_t)MROWS * DIM];
__device__ __half g_wh[(size_t)NQKV * DIM];
__device__ __half g_vh2[(size_t)DIM * DIM];
// attention operands: pre-split bf16 (unchanged path)
__device__ __nv_bfloat16 g_qh[HEADS_ELEMS], g_ql[HEADS_ELEMS];
__device__ __nv_bfloat16 g_kh[HEADS_ELEMS], g_kl[HEADS_ELEMS];
__device__ __nv_bfloat16 g_vh[HEADS_ELEMS], g_vl[HEADS_ELEMS];

// ---------------- PTX helpers (plain sm_103-safe) ---------------------------
__device__ __forceinline__ uint32_t smem_u32(const void* p) {
    uint32_t a;
    asm("{ .reg .u64 t; cvta.to.shared.u64 t, %1; cvt.u32.u64 %0, t; }"
        : "=r"(a) : "l"(p));
    return a;
}
// bf16 mma (attention)
__device__ __forceinline__ void mma16816(float* c, const uint32_t* a, const uint32_t* b) {
    asm volatile(
        "mma.sync.aligned.m16n8k16.row.col.f32.bf16.bf16.f32 "
        "{%0,%1,%2,%3}, {%4,%5,%6,%7}, {%8,%9}, {%0,%1,%2,%3};"
        : "+f"(c[0]), "+f"(c[1]), "+f"(c[2]), "+f"(c[3])
        : "r"(a[0]), "r"(a[1]), "r"(a[2]), "r"(a[3]), "r"(b[0]), "r"(b[1]));
}
// fp16 mma (projections)
__device__ __forceinline__ void mma16816f(float* c, const uint32_t* a, const uint32_t* b) {
    asm volatile(
        "mma.sync.aligned.m16n8k16.row.col.f32.f16.f16.f32 "
        "{%0,%1,%2,%3}, {%4,%5,%6,%7}, {%8,%9}, {%0,%1,%2,%3};"
        : "+f"(c[0]), "+f"(c[1]), "+f"(c[2]), "+f"(c[3])
        : "r"(a[0]), "r"(a[1]), "r"(a[2]), "r"(a[3]), "r"(b[0]), "r"(b[1]));
}
__device__ __forceinline__ void ldm4(uint32_t* r, uint32_t addr) {
    asm volatile("ldmatrix.sync.aligned.m8n8.x4.shared.b16 {%0,%1,%2,%3}, [%4];"
                 : "=r"(r[0]), "=r"(r[1]), "=r"(r[2]), "=r"(r[3]) : "r"(addr));
}
__device__ __forceinline__ void ldm4t(uint32_t* r, uint32_t addr) {
    asm volatile("ldmatrix.sync.aligned.m8n8.x4.trans.shared.b16 {%0,%1,%2,%3}, [%4];"
                 : "=r"(r[0]), "=r"(r[1]), "=r"(r[2]), "=r"(r[3]) : "r"(addr));
}
__device__ __forceinline__ uint32_t pack_bf16x2(float lo, float hi) {
    uint32_t d;
    asm("cvt.rn.bf16x2.f32 %0, %1, %2;" : "=r"(d) : "f"(hi), "f"(lo));
    return d;
}
__device__ __forceinline__ void cpa16(uint32_t dst, const void* src) {
    asm volatile("cp.async.cg.shared.global [%0], [%1], 16;"
                 :: "r"(dst), "l"(src) : "memory");
}
__device__ __forceinline__ void cpa_commit() {
    asm volatile("cp.async.commit_group;" ::: "memory");
}
template <int N>
__device__ __forceinline__ void cpa_wait() {
    asm volatile("cp.async.wait_group %0;" :: "n"(N) : "memory");
}

// ---------------------------------------------------------------------------
// fp32 -> fp16 split-2 (A operands; exact to ~2^-22)
// ---------------------------------------------------------------------------
__global__ void cvt_split_f16(const float* __restrict__ in,
                              __half* __restrict__ hi,
                              __half* __restrict__ lo, int n4)
{
    int i = blockIdx.x * blockDim.x + threadIdx.x;
    if (i >= n4) return;
    float4 v = ((const float4*)in)[i];
    __half hx = __float2half(v.x);
    __half hy = __float2half(v.y);
    __half hz = __float2half(v.z);
    __half hw = __float2half(v.w);
    __half2* hp = reinterpret_cast<__half2*>(hi);
    __half2* lp = reinterpret_cast<__half2*>(lo);
    hp[2*i]   = __halves2half2(hx, hy);
    hp[2*i+1] = __halves2half2(hz, hw);
    lp[2*i]   = __floats2half2_rn(v.x - __half2float(hx), v.y - __half2float(hy));
    lp[2*i+1] = __floats2half2_rn(v.z - __half2float(hz), v.w - __half2float(hw));
}

// fp32 -> fp16 single (B operands / weights)
__global__ void cvt_f16(const float* __restrict__ in,
                        __half* __restrict__ out, int n4)
{
    int i = blockIdx.x * blockDim.x + threadIdx.x;
    if (i >= n4) return;
    float4 v = ((const float4*)in)[i];
    __half2* op = reinterpret_cast<__half2*>(out);
    op[2*i]   = __floats2half2_rn(v.x, v.y);
    op[2*i+1] = __floats2half2_rn(v.z, v.w);
}

// ---------------------------------------------------------------------------
// HMMA fp16 2-term GEMM: C[M,N] = (Ahi+Alo)[M,K] @ Bh[N,K]^T (fp32 accum)
// 128x256 tile, 256 threads (8 fat warps: 2 M x 4 N, 64x64 each).
// K-chunk 32, 2-stage cp.async. Stage = Ahi|Alo (128x40 h) + Bh (256x40 h)
// = 40960 B; 2048 cp.async ops/chunk (vs 3072 in split-3 bf16).
// ---------------------------------------------------------------------------
#define GST 40960   // stage stride bytes
#define GEMM_SMEM (2 * GST)

__global__ __launch_bounds__(256, 1) void hgemm_f16(
    const __half* __restrict__ Ahi, const __half* __restrict__ Alo,
    const __half* __restrict__ Bh,
    float* __restrict__ C, int N, int K)
{
    extern __shared__ __align__(16) char dsm[];
    const uint32_t sb = smem_u32(dsm);
    const int tid = threadIdx.x;
    const int lane = tid & 31;
    const int wid = tid >> 5;
    const int wm = wid & 1;          // 2 M-groups x 64 rows
    const int wn = wid >> 1;         // 4 N-groups x 64 cols
    const int bm = blockIdx.y * 128;
    const int bn = blockIdx.x * 256;

    float c[4][8][4];
#pragma unroll
    for (int i = 0; i < 4; i++)
#pragma unroll
        for (int nf = 0; nf < 8; nf++)
#pragma unroll
            for (int e = 0; e < 4; e++) c[i][nf][e] = 0.f;

    const int nch = K / 32;

    // stage layout: Ahi @0 (10240B), Alo @10240, Bh @20480 (20480B)
#define GEMM_STAGE_LOAD(stbase, kk)                                            \
    {                                                                          \
        const uint32_t _b = (stbase);                                          \
        const int _k8 = (kk) * 32;                                             \
        _Pragma("unroll")                                                      \
        for (int it = 0; it < 2; it++) {                                       \
            int idx = it * 256 + tid;                                          \
            int row = idx >> 2, c8 = (idx & 3) * 8;                            \
            cpa16(_b + row * 80 + c8 * 2,                                      \
                  Ahi + (size_t)(bm + row) * K + _k8 + c8);                    \
            cpa16(_b + 10240 + row * 80 + c8 * 2,                              \
                  Alo + (size_t)(bm + row) * K + _k8 + c8);                    \
        }                                                                      \
        _Pragma("unroll")                                                      \
        for (int it = 0; it < 4; it++) {                                       \
            int idx = it * 256 + tid;                                          \
            int row = idx >> 2, c8 = (idx & 3) * 8;                            \
            cpa16(_b + 20480 + row * 80 + c8 * 2,                              \
                  Bh + (size_t)(bn + row) * K + _k8 + c8);                     \
        }                                                                      \
    }

    GEMM_STAGE_LOAD(sb, 0);
    cpa_commit();

    for (int ck = 0; ck < nch; ck++) {
        cpa_wait<0>();
        __syncthreads();
        if (ck + 1 < nch) {
            GEMM_STAGE_LOAD(sb + ((ck + 1) & 1) * GST, ck + 1);
            cpa_commit();
        }

        const uint32_t st = sb + (ck & 1) * GST;
        const uint32_t sAh = st, sAl = st + 10240, sBh = st + 20480;
#pragma unroll
        for (int ks = 0; ks < 2; ks++) {
            uint32_t ah[4][4], al[4][4];
#pragma unroll
            for (int i = 0; i < 4; i++) {
                int row = wm * 64 + i * 16 + (lane & 15);
                int col = ks * 16 + (lane >> 4) * 8;
                uint32_t off = (uint32_t)(row * 80 + col * 2);
                ldm4(ah[i], sAh + off);
                ldm4(al[i], sAl + off);
            }
#pragma unroll
            for (int nfp = 0; nfp < 4; nfp++) {
                int g = lane >> 3;
                int row = wn * 64 + nfp * 16 + ((g >= 2) ? 8 : 0) + (lane & 7);
                int col = ks * 16 + ((g & 1) ? 8 : 0);
                uint32_t off = (uint32_t)(row * 80 + col * 2);
                uint32_t bh[4];
                ldm4(bh, sBh + off);
                // term hi*B across 8 independent accumulators
#pragma unroll
                for (int i = 0; i < 4; i++) {
                    mma16816f(c[i][2*nfp],   ah[i], bh);
                    mma16816f(c[i][2*nfp+1], ah[i], bh + 2);
                }
                // term lo*B
#pragma unroll
                for (int i = 0; i < 4; i++) {
                    mma16816f(c[i][2*nfp],   al[i], bh);
                    mma16816f(c[i][2*nfp+1], al[i], bh + 2);
                }
            }
        }
    }

#pragma unroll
    for (int i = 0; i < 4; i++) {
#pragma unroll
        for (int nf = 0; nf < 8; nf++) {
            int row = bm + wm * 64 + i * 16 + (lane >> 2);
            int col = bn + wn * 64 + nf * 8 + (lane & 3) * 2;
            *(float2*)(C + (size_t)row * N + col) = make_float2(c[i][nf][0], c[i][nf][1]);
            *(float2*)(C + (size_t)(row + 8) * N + col) = make_float2(c[i][nf][2], c[i][nf][3]);
        }
    }
}

// ---------------------------------------------------------------------------
// RoPE tables (verified)
// ---------------------------------------------------------------------------
__global__ void rope_tables()
{
    int idx = blockIdx.x * blockDim.x + threadIdx.x;
    if (idx >= SSQ * 32) return;
    int s = idx >> 5;
    int i = idx & 31;
    double inv_d = exp(-(double)i * (9.210340371976184 / 32.0));
    float  ang_f = (float)s * (float)inv_d;
    double c, sn;
    sincos((double)ang_f, &sn, &c);
    g_cos[idx] = (float)c;
    g_sin[idx] = (float)sn;
}

__device__ __forceinline__ void split_store(__nv_bfloat16* hi, __nv_bfloat16* lo,
                                            size_t idx, float v)
{
    __nv_bfloat16 h = __float2bfloat16(v);
    hi[idx] = h;
    lo[idx] = __float2bfloat16(v - __bfloat162float(h));
}

// RoPE + split + relayout to [b,h,s,d]. q pre-scaled by 1/sqrt(64).
__global__ __launch_bounds__(512) void rope_split()
{
    int s = blockIdx.x;
    int b = blockIdx.y;
    int h = threadIdx.x >> 5;
    int i = threadIdx.x & 31;

    float c  = g_cos[s * 32 + i];
    float sn = g_sin[s * 32 + i];

    size_t row  = ((size_t)(b * SSQ + s)) * NQKV + (size_t)h * HD;
    size_t orow = ((size_t)((b * NH + h) * SSQ) + s) * HD;

    float q1 = g_qkv[row + i];
    float q2 = g_qkv[row + 32 + i];
    split_store(g_qh, g_ql, orow + i,      (q1 * c - q2 * sn) * 0.125f);
    split_store(g_qh, g_ql, orow + 32 + i, (q1 * sn + q2 * c) * 0.125f);

    float k1 = g_qkv[row + DIM + i];
    float k2 = g_qkv[row + DIM + 32 + i];
    split_store(g_kh, g_kl, orow + i,      k1 * c - k2 * sn);
    split_store(g_kh, g_kl, orow + 32 + i, k1 * sn + k2 * c);

    split_store(g_vh, g_vl, orow + i,      g_qkv[row + 2 * DIM + i]);
    split_store(g_vh, g_vl, orow + 32 + i, g_qkv[row + 2 * DIM + 32 + i]);
}

// ---------------------------------------------------------------------------
// HMMA flash attention (causal), pre-split bf16 inputs, cp.async 2-stage KV,
// single sync per KV tile. LPT: heavy (high-qb) blocks launch first.
// Block = 128 queries of one (b,h), 256 threads (8 warps x 16 query rows).
// Internals UNCHANGED from R6/R7 (verified); epilogue writes fp16 A-split.
// ---------------------------------------------------------------------------
#define KVST 36864    // KV stage stride bytes
#define ATTN_SMEM (2 * KVST)

__global__ __launch_bounds__(256, 1) void attn_tc()
{
    extern __shared__ __align__(16) char dsm[];
    const uint32_t sb = smem_u32(dsm);

    const int tid  = threadIdx.x;
    const int lane = tid & 31;
    const int wid  = tid >> 5;
    const int qb   = (int)(gridDim.x - 1 - blockIdx.x);   // LPT: big blocks first
    const int h    = blockIdx.y;
    const int b    = blockIdx.z;

    const size_t head = (size_t)(b * NH + h) * SSQ * HD;
    const __nv_bfloat16* qhg = g_qh + head + (size_t)qb * 128 * HD;
    const __nv_bfloat16* qlg = g_ql + head + (size_t)qb * 128 * HD;

    // ---- stage Q (Qh @ sb, Ql @ sb+18432) ----
#pragma unroll
    for (int i = 0; i < 8; i++) {
        int g = i * 256 + tid;
        int mat = g >> 10;
        int idx = g & 1023;
        int row = idx >> 3;
        int c8 = (idx & 7) * 8;
        cpa16(sb + mat * 18432 + row * 144 + c8 * 2,
              (mat ? qlg : qhg) + row * HD + c8);
    }
    cpa_commit();
    cpa_wait<0>();
    __syncthreads();

    // ---- extract Q fragments ----
    uint32_t qh[4][4], ql[4][4];
#pragma unroll
    for (int ks = 0; ks < 4; ks++) {
        int row = wid * 16 + (lane & 15);
        int col = ks * 16 + (lane >> 4) * 8;
        uint32_t off = (uint32_t)(row * 144 + col * 2);
        ldm4(qh[ks], sb + off);
        ldm4(ql[ks], sb + 18432 + off);
    }
    __syncthreads();   // Q reads done; stage-0 region reusable for KV

    float m0 = -1e30f, m1 = -1e30f, l0 = 0.f, l1 = 0.f;
    float o[8][4];
#pragma unroll
    for (int df = 0; df < 8; df++)
#pragma unroll
        for (int e = 0; e < 4; e++) o[df][e] = 0.f;

    const int qi0 = qb * 128 + wid * 16 + (lane >> 2);
    const int qi1 = qi0 + 8;
    const int ntiles = 2 * qb + 2;

    const __nv_bfloat16* kvg[4] = {g_kh + head, g_kl + head, g_vh + head, g_vl + head};

    // ---- prologue: KV tile 0 into stage 0 ----
#pragma unroll
    for (int i = 0; i < 8; i++) {
        int g = i * 256 + tid;
        int mat = g >> 9;
        int idx = g & 511;
        int row = idx >> 3;
        int c8 = (idx & 7) * 8;
        cpa16(sb + mat * 9216 + row * 144 + c8 * 2, kvg[mat] + row * HD + c8);
    }
    cpa_commit();

    for (int kt = 0; kt < ntiles; kt++) {
        cpa_wait<0>();
        __syncthreads();
        if (kt + 1 < ntiles) {
            const uint32_t base = sb + ((kt + 1) & 1) * KVST;
            const size_t koff = (size_t)(kt + 1) * 64 * HD;
#pragma unroll
            for (int i = 0; i < 8; i++) {
                int g = i * 256 + tid;
                int mat = g >> 9;
                int idx = g & 511;
                int row = idx >> 3;
                int c8 = (idx & 7) * 8;
                cpa16(base + mat * 9216 + row * 144 + c8 * 2,
                      kvg[mat] + koff + row * HD + c8);
            }
            cpa_commit();
        }

        const uint32_t st = sb + (kt & 1) * KVST;
        const uint32_t sKh = st, sKl = st + 9216, sVh = st + 18432, sVl = st + 27648;

        // ---- scores: S(16x64) = Q @ K^T, split-3 ----
        float s[8][4];
#pragma unroll
        for (int nf = 0; nf < 8; nf++)
#pragma unroll
            for (int e = 0; e < 4; e++) s[nf][e] = 0.f;

#pragma unroll
        for (int ks = 0; ks < 4; ks++) {
#pragma unroll
            for (int nfp = 0; nfp < 4; nfp++) {
                int g = lane >> 3;
                int row = nfp * 16 + ((g >= 2) ? 8 : 0) + (lane & 7);
                int col = ks * 16 + ((g & 1) ? 8 : 0);
                uint32_t off = (uint32_t)(row * 144 + col * 2);
                uint32_t bh[4], bl[4];
                ldm4(bh, sKh + off);
                ldm4(bl, sKl + off);
                mma16816(s[2*nfp],   qh[ks], bh);
                mma16816(s[2*nfp+1], qh[ks], bh + 2);
                mma16816(s[2*nfp],   qh[ks], bl);
                mma16816(s[2*nfp+1], qh[ks], bl + 2);
                mma16816(s[2*nfp],   ql[ks], bh);
                mma16816(s[2*nfp+1], ql[ks], bh + 2);
            }
        }

        // ---- causal mask ----
        if (kt >= 2 * qb) {
            int kbase = kt * 64 + (lane & 3) * 2;
#pragma unroll
            for (int nf = 0; nf < 8; nf++) {
                int kj = kbase + nf * 8;
                if (kj     > qi0) s[nf][0] = -1e30f;
                if (kj + 1 > qi0) s[nf][1] = -1e30f;
                if (kj     > qi1) s[nf][2] = -1e30f;
                if (kj + 1 > qi1) s[nf][3] = -1e30f;
            }
        }

        // ---- online softmax ----
        float rmax0 = -1e30f, rmax1 = -1e30f;
#pragma unroll
        for (int nf = 0; nf < 8; nf++) {
            rmax0 = fmaxf(rmax0, fmaxf(s[nf][0], s[nf][1]));
            rmax1 = fmaxf(rmax1, fmaxf(s[nf][2], s[nf][3]));
        }
        rmax0 = fmaxf(rmax0, __shfl_xor_sync(0xFFFFFFFFu, rmax0, 1));
        rmax0 = fmaxf(rmax0, __shfl_xor_sync(0xFFFFFFFFu, rmax0, 2));
        rmax1 = fmaxf(rmax1, __shfl_xor_sync(0xFFFFFFFFu, rmax1, 1));
        rmax1 = fmaxf(rmax1, __shfl_xor_sync(0xFFFFFFFFu, rmax1, 2));

        float mn0 = fmaxf(m0, rmax0);
        float mn1 = fmaxf(m1, rmax1);
        float corr0 = __expf(m0 - mn0);
        float corr1 = __expf(m1 - mn1);
        m0 = mn0; m1 = mn1;
        l0 *= corr0; l1 *= corr1;
#pragma unroll
        for (int df = 0; df < 8; df++) {
            o[df][0] *= corr0; o[df][1] *= corr0;
            o[df][2] *= corr1; o[df][3] *= corr1;
        }

        uint32_t ph01[8], ph23[8], pl01[8], pl23[8];
#pragma unroll
        for (int nf = 0; nf < 8; nf++) {
            float p0 = __expf(s[nf][0] - m0);
            float p1 = __expf(s[nf][1] - m0);
            float p2 = __expf(s[nf][2] - m1);
            float p3 = __expf(s[nf][3] - m1);
            l0 += p0 + p1;
            l1 += p2 + p3;
            float h0 = __bfloat162float(__float2bfloat16(p0));
            float h1 = __bfloat162float(__float2bfloat16(p1));
            float h2 = __bfloat162float(__float2bfloat16(p2));
            float h3 = __bfloat162float(__float2bfloat16(p3));
            ph01[nf] = pack_bf16x2(h0, h1);
            ph23[nf] = pack_bf16x2(h2, h3);
            pl01[nf] = pack_bf16x2(p0 - h0, p1 - h1);
            pl23[nf] = pack_bf16x2(p2 - h2, p3 - h3);
        }

        // ---- O += P @ V : split-2 x split-2 (drop plo*vlo) ----
#pragma unroll
        for (int ks = 0; ks < 4; ks++) {
            uint32_t aPh[4] = {ph01[2*ks], ph23[2*ks], ph01[2*ks+1], ph23[2*ks+1]};
            uint32_t aPl[4] = {pl01[2*ks], pl23[2*ks], pl01[2*ks+1], pl23[2*ks+1]};
#pragma unroll
            for (int dfp = 0; dfp < 4; dfp++) {
                int g = lane >> 3;
                int row = ks * 16 + ((g & 1) ? 8 : 0) + (lane & 7);
                int col = dfp * 16 + ((g >= 2) ? 8 : 0);
                uint32_t off = (uint32_t)(row * 144 + col * 2);
                uint32_t bv[4], bvl[4];
                ldm4t(bv,  sVh + off);
                ldm4t(bvl, sVl + off);
                mma16816(o[2*dfp],   aPh, bv);
                mma16816(o[2*dfp+1], aPh, bv + 2);
                mma16816(o[2*dfp],   aPh, bvl);
                mma16816(o[2*dfp+1], aPh, bvl + 2);
                mma16816(o[2*dfp],   aPl, bv);
                mma16816(o[2*dfp+1], aPl, bv + 2);
            }
        }
    }

    // ---- finalize: normalize, fp16-split, store as GEMM2's A operand ----
    l0 += __shfl_xor_sync(0xFFFFFFFFu, l0, 1);
    l0 += __shfl_xor_sync(0xFFFFFFFFu, l0, 2);
    l1 += __shfl_xor_sync(0xFFFFFFFFu, l1, 1);
    l1 += __shfl_xor_sync(0xFFFFFFFFu, l1, 2);
    float inv0 = 1.0f / l0;
    float inv1 = 1.0f / l1;

#pragma unroll
    for (int df = 0; df < 8; df++) {
        int col = h * HD + df * 8 + (lane & 3) * 2;
        size_t r0 = (size_t)(b * SSQ + qi0) * DIM + col;
        size_t r1 = (size_t)(b * SSQ + qi1) * DIM + col;
        float v0 = o[df][0] * inv0, v1 = o[df][1] * inv0;
        float v2 = o[df][2] * inv1, v3 = o[df][3] * inv1;
        __half h0 = __float2half(v0), h1 = __float2half(v1);
        __half h2 = __float2half(v2), h3 = __float2half(v3);
        *(__half2*)(g_ahi + r0) = __halves2half2(h0, h1);
        *(__half2*)(g_alo + r0) = __floats2half2_rn(v0 - __half2float(h0),
                                                    v1 - __half2float(h1));
        *(__half2*)(g_ahi + r1) = __halves2half2(h2, h3);
        *(__half2*)(g_alo + r1) = __floats2half2_rn(v2 - __half2float(h2),
                                                    v3 - __half2float(h3));
    }
}

// ---------------------------------------------------------------------------
extern "C" void kernel_launch(void* const* d_in, const int* in_sizes, int n_in,
                              void* d_out, int out_size)
{
    const float* x = nullptr;
    const float* wqkv = nullptr;
    const float* wout = nullptr;
    for (int i = 0; i < n_in; i++) {
        long long n = in_sizes[i];
        if (n == (long long)MROWS * DIM)      x    = (const float*)d_in[i];
        else if (n == (long long)NQKV * DIM)  wqkv = (const float*)d_in[i];
        else if (n == (long long)DIM * DIM)   wout = (const float*)d_in[i];
    }
    if (!x || !wqkv || !wout) return;

    float* qkv = nullptr;
    __half *ahi, *alo, *wh, *vh2;
    cudaGetSymbolAddress((void**)&qkv, g_qkv);
    cudaGetSymbolAddress((void**)&ahi, g_ahi);
    cudaGetSymbolAddress((void**)&alo, g_alo);
    cudaGetSymbolAddress((void**)&wh,  g_wh);
    cudaGetSymbolAddress((void**)&vh2, g_vh2);

    cudaFuncSetAttribute(hgemm_f16, cudaFuncAttributeMaxDynamicSharedMemorySize,
                         GEMM_SMEM);
    cudaFuncSetAttribute(attn_tc, cudaFuncAttributeMaxDynamicSharedMemorySize,
                         ATTN_SMEM);

    // 0) fp16 operand prep: x split-2 (exact), weights single
    cvt_split_f16<<<(MROWS * DIM / 4 + 255) / 256, 256>>>(x, ahi, alo, MROWS * DIM / 4);
    cvt_f16<<<(NQKV * DIM / 4 + 255) / 256, 256>>>(wqkv, wh, NQKV * DIM / 4);
    cvt_f16<<<(DIM * DIM / 4 + 255) / 256, 256>>>(wout, vh2, DIM * DIM / 4);

    // 1) qkv = x @ Wqkv^T  (fp16 2-term)
    dim3 g1(NQKV / 256, MROWS / 128);
    hgemm_f16<<<g1, 256, GEMM_SMEM>>>(ahi, alo, wh, qkv, NQKV, DIM);

    // 2) RoPE + split + relayout (bf16, unchanged)
    rope_tables<<<(SSQ * 32) / 256, 256>>>();
    dim3 gr(SSQ, BB);
    rope_split<<<gr, 512>>>();

    // 3) flash attention (bf16 split-3, unchanged; writes fp16 A-split)
    dim3 ga(SSQ / 128, NH, BB);
    attn_tc<<<ga, 256, ATTN_SMEM>>>();

    // 4) out = att @ Wout^T  (fp16 2-term)
    dim3 g2(DIM / 256, MROWS / 128);
    hgemm_f16<<<g2, 256, GEMM_SMEM>>>(ahi, alo, vh2, (float*)d_out, DIM, DIM);
}

// round 11
// speedup vs baseline: 5.3429x; 1.2014x over previous
#include <cuda_runtime.h>
#include <cuda_bf16.h>
#include <cuda_fp16.h>
#include <math.h>
#include <stdint.h>

#define BB 4
#define SSQ 2048
#define DIM 1024
#define NH 16
#define HD 64
#define MROWS (BB*SSQ)       // 8192
#define NQKV (3*DIM)         // 3072
#define HEADS_ELEMS ((size_t)BB * NH * SSQ * HD)   // 8.4M

// ---------------- scratch (device globals; allocation-free) ----------------
__device__ float g_qkv[(size_t)MROWS * NQKV];   // fp32 qkv after GEMM1
__device__ float g_cos[SSQ * 32];
__device__ float g_sin[SSQ * 32];
// GEMM operands (fp16 2-term scheme): A split-2, B single
__device__ __half g_ahi[(size_t)MROWS * DIM];
__device__ __half g_alo[(size_t)MROWS * DIM];
__device__ __half g_wh[(size_t)NQKV * DIM];
__device__ __half g_vh2[(size_t)DIM * DIM];
// attention operands (fp16): Q split-2, K single, V single, [b,h,s,d]
__device__ __half g_aqh[HEADS_ELEMS], g_aql[HEADS_ELEMS];
__device__ __half g_ak[HEADS_ELEMS];
__device__ __half g_av[HEADS_ELEMS];

// ---------------- PTX helpers (plain sm_103-safe) ---------------------------
__device__ __forceinline__ uint32_t smem_u32(const void* p) {
    uint32_t a;
    asm("{ .reg .u64 t; cvta.to.shared.u64 t, %1; cvt.u32.u64 %0, t; }"
        : "=r"(a) : "l"(p));
    return a;
}
// fp16 mma (everything now)
__device__ __forceinline__ void mma16816f(float* c, const uint32_t* a, const uint32_t* b) {
    asm volatile(
        "mma.sync.aligned.m16n8k16.row.col.f32.f16.f16.f32 "
        "{%0,%1,%2,%3}, {%4,%5,%6,%7}, {%8,%9}, {%0,%1,%2,%3};"
        : "+f"(c[0]), "+f"(c[1]), "+f"(c[2]), "+f"(c[3])
        : "r"(a[0]), "r"(a[1]), "r"(a[2]), "r"(a[3]), "r"(b[0]), "r"(b[1]));
}
__device__ __forceinline__ void ldm4(uint32_t* r, uint32_t addr) {
    asm volatile("ldmatrix.sync.aligned.m8n8.x4.shared.b16 {%0,%1,%2,%3}, [%4];"
                 : "=r"(r[0]), "=r"(r[1]), "=r"(r[2]), "=r"(r[3]) : "r"(addr));
}
__device__ __forceinline__ void ldm4t(uint32_t* r, uint32_t addr) {
    asm volatile("ldmatrix.sync.aligned.m8n8.x4.trans.shared.b16 {%0,%1,%2,%3}, [%4];"
                 : "=r"(r[0]), "=r"(r[1]), "=r"(r[2]), "=r"(r[3]) : "r"(addr));
}
// packs (lo,hi) floats into fp16x2 register: low 16 bits = lo
__device__ __forceinline__ uint32_t pack_f16x2(float lo, float hi) {
    uint32_t d;
    asm("cvt.rn.f16x2.f32 %0, %1, %2;" : "=r"(d) : "f"(hi), "f"(lo));
    return d;
}
__device__ __forceinline__ void cpa16(uint32_t dst, const void* src) {
    asm volatile("cp.async.cg.shared.global [%0], [%1], 16;"
                 :: "r"(dst), "l"(src) : "memory");
}
__device__ __forceinline__ void cpa_commit() {
    asm volatile("cp.async.commit_group;" ::: "memory");
}
template <int N>
__device__ __forceinline__ void cpa_wait() {
    asm volatile("cp.async.wait_group %0;" :: "n"(N) : "memory");
}

// ---------------------------------------------------------------------------
// fp32 -> fp16 split-2 (A operands; exact to ~2^-22)
// ---------------------------------------------------------------------------
__global__ void cvt_split_f16(const float* __restrict__ in,
                              __half* __restrict__ hi,
                              __half* __restrict__ lo, int n4)
{
    int i = blockIdx.x * blockDim.x + threadIdx.x;
    if (i >= n4) return;
    float4 v = ((const float4*)in)[i];
    __half hx = __float2half(v.x);
    __half hy = __float2half(v.y);
    __half hz = __float2half(v.z);
    __half hw = __float2half(v.w);
    __half2* hp = reinterpret_cast<__half2*>(hi);
    __half2* lp = reinterpret_cast<__half2*>(lo);
    hp[2*i]   = __halves2half2(hx, hy);
    hp[2*i+1] = __halves2half2(hz, hw);
    lp[2*i]   = __floats2half2_rn(v.x - __half2float(hx), v.y - __half2float(hy));
    lp[2*i+1] = __floats2half2_rn(v.z - __half2float(hz), v.w - __half2float(hw));
}

// fp32 -> fp16 single (B operands / weights)
__global__ void cvt_f16(const float* __restrict__ in,
                        __half* __restrict__ out, int n4)
{
    int i = blockIdx.x * blockDim.x + threadIdx.x;
    if (i >= n4) return;
    float4 v = ((const float4*)in)[i];
    __half2* op = reinterpret_cast<__half2*>(out);
    op[2*i]   = __floats2half2_rn(v.x, v.y);
    op[2*i+1] = __floats2half2_rn(v.z, v.w);
}

// ---------------------------------------------------------------------------
// HMMA fp16 2-term GEMM: C[M,N] = (Ahi+Alo)[M,K] @ Bh[N,K]^T (fp32 accum)
// 128x256 tile, 256 threads (8 fat warps: 2 M x 4 N, 64x64 each).
// K-chunk 32, 2-stage cp.async. (verified R9, unchanged)
// ---------------------------------------------------------------------------
#define GST 40960   // stage stride bytes
#define GEMM_SMEM (2 * GST)

__global__ __launch_bounds__(256, 1) void hgemm_f16(
    const __half* __restrict__ Ahi, const __half* __restrict__ Alo,
    const __half* __restrict__ Bh,
    float* __restrict__ C, int N, int K)
{
    extern __shared__ __align__(16) char dsm[];
    const uint32_t sb = smem_u32(dsm);
    const int tid = threadIdx.x;
    const int lane = tid & 31;
    const int wid = tid >> 5;
    const int wm = wid & 1;          // 2 M-groups x 64 rows
    const int wn = wid >> 1;         // 4 N-groups x 64 cols
    const int bm = blockIdx.y * 128;
    const int bn = blockIdx.x * 256;

    float c[4][8][4];
#pragma unroll
    for (int i = 0; i < 4; i++)
#pragma unroll
        for (int nf = 0; nf < 8; nf++)
#pragma unroll
            for (int e = 0; e < 4; e++) c[i][nf][e] = 0.f;

    const int nch = K / 32;

#define GEMM_STAGE_LOAD(stbase, kk)                                            \
    {                                                                          \
        const uint32_t _b = (stbase);                                          \
        const int _k8 = (kk) * 32;                                             \
        _Pragma("unroll")                                                      \
        for (int it = 0; it < 2; it++) {                                       \
            int idx = it * 256 + tid;                                          \
            int row = idx >> 2, c8 = (idx & 3) * 8;                            \
            cpa16(_b + row * 80 + c8 * 2,                                      \
                  Ahi + (size_t)(bm + row) * K + _k8 + c8);                    \
            cpa16(_b + 10240 + row * 80 + c8 * 2,                              \
                  Alo + (size_t)(bm + row) * K + _k8 + c8);                    \
        }                                                                      \
        _Pragma("unroll")                                                      \
        for (int it = 0; it < 4; it++) {                                       \
            int idx = it * 256 + tid;                                          \
            int row = idx >> 2, c8 = (idx & 3) * 8;                            \
            cpa16(_b + 20480 + row * 80 + c8 * 2,                              \
                  Bh + (size_t)(bn + row) * K + _k8 + c8);                     \
        }                                                                      \
    }

    GEMM_STAGE_LOAD(sb, 0);
    cpa_commit();

    for (int ck = 0; ck < nch; ck++) {
        cpa_wait<0>();
        __syncthreads();
        if (ck + 1 < nch) {
            GEMM_STAGE_LOAD(sb + ((ck + 1) & 1) * GST, ck + 1);
            cpa_commit();
        }

        const uint32_t st = sb + (ck & 1) * GST;
        const uint32_t sAh = st, sAl = st + 10240, sBh = st + 20480;
#pragma unroll
        for (int ks = 0; ks < 2; ks++) {
            uint32_t ah[4][4], al[4][4];
#pragma unroll
            for (int i = 0; i < 4; i++) {
                int row = wm * 64 + i * 16 + (lane & 15);
                int col = ks * 16 + (lane >> 4) * 8;
                uint32_t off = (uint32_t)(row * 80 + col * 2);
                ldm4(ah[i], sAh + off);
                ldm4(al[i], sAl + off);
            }
#pragma unroll
            for (int nfp = 0; nfp < 4; nfp++) {
                int g = lane >> 3;
                int row = wn * 64 + nfp * 16 + ((g >= 2) ? 8 : 0) + (lane & 7);
                int col = ks * 16 + ((g & 1) ? 8 : 0);
                uint32_t off = (uint32_t)(row * 80 + col * 2);
                uint32_t bh[4];
                ldm4(bh, sBh + off);
#pragma unroll
                for (int i = 0; i < 4; i++) {
                    mma16816f(c[i][2*nfp],   ah[i], bh);
                    mma16816f(c[i][2*nfp+1], ah[i], bh + 2);
                }
#pragma unroll
                for (int i = 0; i < 4; i++) {
                    mma16816f(c[i][2*nfp],   al[i], bh);
                    mma16816f(c[i][2*nfp+1], al[i], bh + 2);
                }
            }
        }
    }

#pragma unroll
    for (int i = 0; i < 4; i++) {
#pragma unroll
        for (int nf = 0; nf < 8; nf++) {
            int row = bm + wm * 64 + i * 16 + (lane >> 2);
            int col = bn + wn * 64 + nf * 8 + (lane & 3) * 2;
            *(float2*)(C + (size_t)row * N + col) = make_float2(c[i][nf][0], c[i][nf][1]);
            *(float2*)(C + (size_t)(row + 8) * N + col) = make_float2(c[i][nf][2], c[i][nf][3]);
        }
    }
}

// ---------------------------------------------------------------------------
// RoPE tables (verified)
// ---------------------------------------------------------------------------
__global__ void rope_tables()
{
    int idx = blockIdx.x * blockDim.x + threadIdx.x;
    if (idx >= SSQ * 32) return;
    int s = idx >> 5;
    int i = idx & 31;
    double inv_d = exp(-(double)i * (9.210340371976184 / 32.0));
    float  ang_f = (float)s * (float)inv_d;
    double c, sn;
    sincos((double)ang_f, &sn, &c);
    g_cos[idx] = (float)c;
    g_sin[idx] = (float)sn;
}

__device__ __forceinline__ void split_store_h(__half* hi, __half* lo,
                                              size_t idx, float v)
{
    __half h = __float2half(v);
    hi[idx] = h;
    lo[idx] = __float2half(v - __half2float(h));
}

// RoPE + fp16 convert + relayout to [b,h,s,d]. q split-2 (pre-scaled), k,v single.
__global__ __launch_bounds__(512) void rope_split()
{
    int s = blockIdx.x;
    int b = blockIdx.y;
    int h = threadIdx.x >> 5;
    int i = threadIdx.x & 31;

    float c  = g_cos[s * 32 + i];
    float sn = g_sin[s * 32 + i];

    size_t row  = ((size_t)(b * SSQ + s)) * NQKV + (size_t)h * HD;
    size_t orow = ((size_t)((b * NH + h) * SSQ) + s) * HD;

    float q1 = g_qkv[row + i];
    float q2 = g_qkv[row + 32 + i];
    split_store_h(g_aqh, g_aql, orow + i,      (q1 * c - q2 * sn) * 0.125f);
    split_store_h(g_aqh, g_aql, orow + 32 + i, (q1 * sn + q2 * c) * 0.125f);

    float k1 = g_qkv[row + DIM + i];
    float k2 = g_qkv[row + DIM + 32 + i];
    g_ak[orow + i]      = __float2half(k1 * c - k2 * sn);
    g_ak[orow + 32 + i] = __float2half(k1 * sn + k2 * c);

    g_av[orow + i]      = __float2half(g_qkv[row + 2 * DIM + i]);
    g_av[orow + 32 + i] = __float2half(g_qkv[row + 2 * DIM + 32 + i]);
}

// ---------------------------------------------------------------------------
// HMMA fp16 flash attention (causal).
// Q split-2 fp16 x K single (2 QK terms); P single fp16 x V single (1 PV term).
// cp.async 2-stage KV (2 matrices/tile = 1024 ops), single sync per tile.
// Block = 128 queries of one (b,h), 256 threads (8 warps x 16 query rows).
// LPT: heavy (high-qb) blocks launch first.
// ---------------------------------------------------------------------------
#define KVST 18432    // KV stage stride bytes (K 9216 + V 9216)
#define ATTN_SMEM (2 * KVST)

__global__ __launch_bounds__(256, 1) void attn_tc()
{
    extern __shared__ __align__(16) char dsm[];
    const uint32_t sb = smem_u32(dsm);

    const int tid  = threadIdx.x;
    const int lane = tid & 31;
    const int wid  = tid >> 5;
    const int qb   = (int)(gridDim.x - 1 - blockIdx.x);   // LPT
    const int h    = blockIdx.y;
    const int b    = blockIdx.z;

    const size_t head = (size_t)(b * NH + h) * SSQ * HD;
    const __half* qhg = g_aqh + head + (size_t)qb * 128 * HD;
    const __half* qlg = g_aql + head + (size_t)qb * 128 * HD;

    // ---- stage Q (Qh @ sb, Ql @ sb+18432; rows 144 B) ----
#pragma unroll
    for (int i = 0; i < 8; i++) {
        int g = i * 256 + tid;
        int mat = g >> 10;
        int idx = g & 1023;
        int row = idx >> 3;
        int c8 = (idx & 7) * 8;
        cpa16(sb + mat * 18432 + row * 144 + c8 * 2,
              (mat ? qlg : qhg) + row * HD + c8);
    }
    cpa_commit();
    cpa_wait<0>();
    __syncthreads();

    // ---- extract Q fragments ----
    uint32_t qh[4][4], ql[4][4];
#pragma unroll
    for (int ks = 0; ks < 4; ks++) {
        int row = wid * 16 + (lane & 15);
        int col = ks * 16 + (lane >> 4) * 8;
        uint32_t off = (uint32_t)(row * 144 + col * 2);
        ldm4(qh[ks], sb + off);
        ldm4(ql[ks], sb + 18432 + off);
    }
    __syncthreads();   // Q reads done; region reusable for KV stages

    float m0 = -1e30f, m1 = -1e30f, l0 = 0.f, l1 = 0.f;
    float o[8][4];
#pragma unroll
    for (int df = 0; df < 8; df++)
#pragma unroll
        for (int e = 0; e < 4; e++) o[df][e] = 0.f;

    const int qi0 = qb * 128 + wid * 16 + (lane >> 2);
    const int qi1 = qi0 + 8;
    const int ntiles = 2 * qb + 2;

    const __half* kvg[2] = {g_ak + head, g_av + head};

    // ---- prologue: KV tile 0 into stage 0 (1024 x 16B) ----
#pragma unroll
    for (int i = 0; i < 4; i++) {
        int g = i * 256 + tid;
        int mat = g >> 9;
        int idx = g & 511;
        int row = idx >> 3;
        int c8 = (idx & 7) * 8;
        cpa16(sb + mat * 9216 + row * 144 + c8 * 2, kvg[mat] + row * HD + c8);
    }
    cpa_commit();

    for (int kt = 0; kt < ntiles; kt++) {
        cpa_wait<0>();
        __syncthreads();
        if (kt + 1 < ntiles) {
            const uint32_t base = sb + ((kt + 1) & 1) * KVST;
            const size_t koff = (size_t)(kt + 1) * 64 * HD;
#pragma unroll
            for (int i = 0; i < 4; i++) {
                int g = i * 256 + tid;
                int mat = g >> 9;
                int idx = g & 511;
                int row = idx >> 3;
                int c8 = (idx & 7) * 8;
                cpa16(base + mat * 9216 + row * 144 + c8 * 2,
                      kvg[mat] + koff + row * HD + c8);
            }
            cpa_commit();
        }

        const uint32_t st = sb + (kt & 1) * KVST;
        const uint32_t sK = st, sV = st + 9216;

        // ---- scores: S(16x64) = (Qh+Ql) @ K^T ----
        float s[8][4];
#pragma unroll
        for (int nf = 0; nf < 8; nf++)
#pragma unroll
            for (int e = 0; e < 4; e++) s[nf][e] = 0.f;

#pragma unroll
        for (int ks = 0; ks < 4; ks++) {
#pragma unroll
            for (int nfp = 0; nfp < 4; nfp++) {
                int g = lane >> 3;
                int row = nfp * 16 + ((g >= 2) ? 8 : 0) + (lane & 7);
                int col = ks * 16 + ((g & 1) ? 8 : 0);
                uint32_t off = (uint32_t)(row * 144 + col * 2);
                uint32_t bk[4];
                ldm4(bk, sK + off);
                mma16816f(s[2*nfp],   qh[ks], bk);
                mma16816f(s[2*nfp+1], qh[ks], bk + 2);
                mma16816f(s[2*nfp],   ql[ks], bk);
                mma16816f(s[2*nfp+1], ql[ks], bk + 2);
            }
        }

        // ---- causal mask ----
        if (kt >= 2 * qb) {
            int kbase = kt * 64 + (lane & 3) * 2;
#pragma unroll
            for (int nf = 0; nf < 8; nf++) {
                int kj = kbase + nf * 8;
                if (kj     > qi0) s[nf][0] = -1e30f;
                if (kj + 1 > qi0) s[nf][1] = -1e30f;
                if (kj     > qi1) s[nf][2] = -1e30f;
                if (kj + 1 > qi1) s[nf][3] = -1e30f;
            }
        }

        // ---- online softmax ----
        float rmax0 = -1e30f, rmax1 = -1e30f;
#pragma unroll
        for (int nf = 0; nf < 8; nf++) {
            rmax0 = fmaxf(rmax0, fmaxf(s[nf][0], s[nf][1]));
            rmax1 = fmaxf(rmax1, fmaxf(s[nf][2], s[nf][3]));
        }
        rmax0 = fmaxf(rmax0, __shfl_xor_sync(0xFFFFFFFFu, rmax0, 1));
        rmax0 = fmaxf(rmax0, __shfl_xor_sync(0xFFFFFFFFu, rmax0, 2));
        rmax1 = fmaxf(rmax1, __shfl_xor_sync(0xFFFFFFFFu, rmax1, 1));
        rmax1 = fmaxf(rmax1, __shfl_xor_sync(0xFFFFFFFFu, rmax1, 2));

        float mn0 = fmaxf(m0, rmax0);
        float mn1 = fmaxf(m1, rmax1);
        float corr0 = __expf(m0 - mn0);
        float corr1 = __expf(m1 - mn1);
        m0 = mn0; m1 = mn1;
        l0 *= corr0; l1 *= corr1;
#pragma unroll
        for (int df = 0; df < 8; df++) {
            o[df][0] *= corr0; o[df][1] *= corr0;
            o[df][2] *= corr1; o[df][3] *= corr1;
        }

        // p = exp(s - m) packed single fp16
        uint32_t p01[8], p23[8];
#pragma unroll
        for (int nf = 0; nf < 8; nf++) {
            float p0 = __expf(s[nf][0] - m0);
            float p1 = __expf(s[nf][1] - m0);
            float p2 = __expf(s[nf][2] - m1);
            float p3 = __expf(s[nf][3] - m1);
            l0 += p0 + p1;
            l1 += p2 + p3;
            p01[nf] = pack_f16x2(p0, p1);
            p23[nf] = pack_f16x2(p2, p3);
        }

        // ---- O += P @ V (single term) ----
#pragma unroll
        for (int ks = 0; ks < 4; ks++) {
            uint32_t aP[4] = {p01[2*ks], p23[2*ks], p01[2*ks+1], p23[2*ks+1]};
#pragma unroll
            for (int dfp = 0; dfp < 4; dfp++) {
                int g = lane >> 3;
                int row = ks * 16 + ((g & 1) ? 8 : 0) + (lane & 7);
                int col = dfp * 16 + ((g >= 2) ? 8 : 0);
                uint32_t off = (uint32_t)(row * 144 + col * 2);
                uint32_t bv[4];
                ldm4t(bv, sV + off);
                mma16816f(o[2*dfp],   aP, bv);
                mma16816f(o[2*dfp+1], aP, bv + 2);
            }
        }
    }

    // ---- finalize: normalize, fp16-split, store as GEMM2's A operand ----
    l0 += __shfl_xor_sync(0xFFFFFFFFu, l0, 1);
    l0 += __shfl_xor_sync(0xFFFFFFFFu, l0, 2);
    l1 += __shfl_xor_sync(0xFFFFFFFFu, l1, 1);
    l1 += __shfl_xor_sync(0xFFFFFFFFu, l1, 2);
    float inv0 = 1.0f / l0;
    float inv1 = 1.0f / l1;

#pragma unroll
    for (int df = 0; df < 8; df++) {
        int col = h * HD + df * 8 + (lane & 3) * 2;
        size_t r0 = (size_t)(b * SSQ + qi0) * DIM + col;
        size_t r1 = (size_t)(b * SSQ + qi1) * DIM + col;
        float v0 = o[df][0] * inv0, v1 = o[df][1] * inv0;
        float v2 = o[df][2] * inv1, v3 = o[df][3] * inv1;
        __half h0 = __float2half(v0), h1 = __float2half(v1);
        __half h2 = __float2half(v2), h3 = __float2half(v3);
        *(__half2*)(g_ahi + r0) = __halves2half2(h0, h1);
        *(__half2*)(g_alo + r0) = __floats2half2_rn(v0 - __half2float(h0),
                                                    v1 - __half2float(h1));
        *(__half2*)(g_ahi + r1) = __halves2half2(h2, h3);
        *(__half2*)(g_alo + r1) = __floats2half2_rn(v2 - __half2float(h2),
                                                    v3 - __half2float(h3));
    }
}

// ---------------------------------------------------------------------------
extern "C" void kernel_launch(void* const* d_in, const int* in_sizes, int n_in,
                              void* d_out, int out_size)
{
    const float* x = nullptr;
    const float* wqkv = nullptr;
    const float* wout = nullptr;
    for (int i = 0; i < n_in; i++) {
        long long n = in_sizes[i];
        if (n == (long long)MROWS * DIM)      x    = (const float*)d_in[i];
        else if (n == (long long)NQKV * DIM)  wqkv = (const float*)d_in[i];
        else if (n == (long long)DIM * DIM)   wout = (const float*)d_in[i];
    }
    if (!x || !wqkv || !wout) return;

    float* qkv = nullptr;
    __half *ahi, *alo, *wh, *vh2;
    cudaGetSymbolAddress((void**)&qkv, g_qkv);
    cudaGetSymbolAddress((void**)&ahi, g_ahi);
    cudaGetSymbolAddress((void**)&alo, g_alo);
    cudaGetSymbolAddress((void**)&wh,  g_wh);
    cudaGetSymbolAddress((void**)&vh2, g_vh2);

    cudaFuncSetAttribute(hgemm_f16, cudaFuncAttributeMaxDynamicSharedMemorySize,
                         GEMM_SMEM);
    cudaFuncSetAttribute(attn_tc, cudaFuncAttributeMaxDynamicSharedMemorySize,
                         ATTN_SMEM);

    // 0) fp16 operand prep
    cvt_split_f16<<<(MROWS * DIM / 4 + 255) / 256, 256>>>(x, ahi, alo, MROWS * DIM / 4);
    cvt_f16<<<(NQKV * DIM / 4 + 255) / 256, 256>>>(wqkv, wh, NQKV * DIM / 4);
    cvt_f16<<<(DIM * DIM / 4 + 255) / 256, 256>>>(wout, vh2, DIM * DIM / 4);

    // 1) qkv = x @ Wqkv^T  (fp16 2-term)
    dim3 g1(NQKV / 256, MROWS / 128);
    hgemm_f16<<<g1, 256, GEMM_SMEM>>>(ahi, alo, wh, qkv, NQKV, DIM);

    // 2) RoPE + fp16 convert + relayout
    rope_tables<<<(SSQ * 32) / 256, 256>>>();
    dim3 gr(SSQ, BB);
    rope_split<<<gr, 512>>>();

    // 3) fp16 flash attention (writes fp16 A-split for GEMM2)
    dim3 ga(SSQ / 128, NH, BB);
    attn_tc<<<ga, 256, ATTN_SMEM>>>();

    // 4) out = att @ Wout^T  (fp16 2-term)
    dim3 g2(DIM / 256, MROWS / 128);
    hgemm_f16<<<g2, 256, GEMM_SMEM>>>(ahi, alo, vh2, (float*)d_out, DIM, DIM);
}

// round 12
// speedup vs baseline: 6.6190x; 1.2388x over previous
#include <cuda_runtime.h>
#include <cuda.h>
#include <cuda_bf16.h>
#include <cuda_fp16.h>
#include <math.h>
#include <stdint.h>

#define BB 4
#define SSQ 2048
#define DIM 1024
#define NH 16
#define HD 64
#define MROWS (BB*SSQ)       // 8192
#define NQKV (3*DIM)         // 3072
#define HEADS_ELEMS ((size_t)BB * NH * SSQ * HD)   // 8.4M
#define HEADROWS ((size_t)BB * NH * SSQ)           // 131072

// ---------------- scratch (device globals; allocation-free) ----------------
__device__ float g_qkv[(size_t)MROWS * NQKV];   // fp32 qkv after GEMM1
__device__ float g_cos[SSQ * 32];
__device__ float g_sin[SSQ * 32];
// GEMM operands (fp16 2-term scheme): A split-2, B single
__device__ __half g_ahi[(size_t)MROWS * DIM];
__device__ __half g_alo[(size_t)MROWS * DIM];
__device__ __half g_wh[(size_t)NQKV * DIM];
__device__ __half g_vh2[(size_t)DIM * DIM];
// attention operands (fp16): Q split-2, K single, V single, [b,h,s,d]
__device__ __half g_aqh[HEADS_ELEMS], g_aql[HEADS_ELEMS];
__device__ __half g_ak[HEADS_ELEMS];
__device__ __half g_av[HEADS_ELEMS];

// ---------------- PTX helpers (plain sm_103-safe) ---------------------------
__device__ __forceinline__ uint32_t smem_u32(const void* p) {
    uint32_t a;
    asm("{ .reg .u64 t; cvta.to.shared.u64 t, %1; cvt.u32.u64 %0, t; }"
        : "=r"(a) : "l"(p));
    return a;
}
__device__ __forceinline__ uint32_t sw128(uint32_t off) {
    return off ^ ((off >> 3) & 0x70);
}
__device__ __forceinline__ void mma16816f(float* c, const uint32_t* a, const uint32_t* b) {
    asm volatile(
        "mma.sync.aligned.m16n8k16.row.col.f32.f16.f16.f32 "
        "{%0,%1,%2,%3}, {%4,%5,%6,%7}, {%8,%9}, {%0,%1,%2,%3};"
        : "+f"(c[0]), "+f"(c[1]), "+f"(c[2]), "+f"(c[3])
        : "r"(a[0]), "r"(a[1]), "r"(a[2]), "r"(a[3]), "r"(b[0]), "r"(b[1]));
}
__device__ __forceinline__ void ldm4(uint32_t* r, uint32_t addr) {
    asm volatile("ldmatrix.sync.aligned.m8n8.x4.shared.b16 {%0,%1,%2,%3}, [%4];"
                 : "=r"(r[0]), "=r"(r[1]), "=r"(r[2]), "=r"(r[3]) : "r"(addr));
}
__device__ __forceinline__ void ldm4t(uint32_t* r, uint32_t addr) {
    asm volatile("ldmatrix.sync.aligned.m8n8.x4.trans.shared.b16 {%0,%1,%2,%3}, [%4];"
                 : "=r"(r[0]), "=r"(r[1]), "=r"(r[2]), "=r"(r[3]) : "r"(addr));
}
__device__ __forceinline__ uint32_t pack_f16x2(float lo, float hi) {
    uint32_t d;
    asm("cvt.rn.f16x2.f32 %0, %1, %2;" : "=r"(d) : "f"(hi), "f"(lo));
    return d;
}
__device__ __forceinline__ void mbar_init(uint32_t mbar, uint32_t cnt) {
    asm volatile("mbarrier.init.shared.b64 [%0], %1;" :: "r"(mbar), "r"(cnt) : "memory");
}
__device__ __forceinline__ void mbar_expect(uint32_t mbar, uint32_t bytes) {
    asm volatile("mbarrier.arrive.expect_tx.shared.b64 _, [%0], %1;"
                 :: "r"(mbar), "r"(bytes) : "memory");
}
__device__ __forceinline__ void mbar_wait(uint32_t mbar, uint32_t parity) {
    uint32_t done;
    asm volatile(
        "{\n\t.reg .pred p;\n\t"
        "mbarrier.try_wait.parity.acquire.cta.shared::cta.b64 p, [%1], %2;\n\t"
        "selp.b32 %0, 1, 0, p;\n\t}"
        : "=r"(done) : "r"(mbar), "r"(parity) : "memory");
    if (!done) {
        asm volatile(
            "{\n\t.reg .pred P1;\n\t"
            "W_%=:\n\t"
            "mbarrier.try_wait.parity.acquire.cta.shared::cta.b64 P1, [%0], %1, 0x989680;\n\t"
            "@P1 bra.uni D_%=;\n\t"
            "bra.uni W_%=;\n\t"
            "D_%=:\n\t}"
            :: "r"(mbar), "r"(parity) : "memory");
    }
}
__device__ __forceinline__ void tma2d(uint32_t dst, const CUtensorMap* tm,
                                      int x, int y, uint32_t mbar) {
    asm volatile(
        "cp.async.bulk.tensor.2d.shared::cta.global.tile.mbarrier::complete_tx::bytes "
        "[%0], [%1, {%2, %3}], [%4];"
        :: "r"(dst), "l"(tm), "r"(x), "r"(y), "r"(mbar) : "memory");
}

// ---------------------------------------------------------------------------
// fp32 -> fp16 split-2 / single converts (verified)
// ---------------------------------------------------------------------------
__global__ void cvt_split_f16(const float* __restrict__ in,
                              __half* __restrict__ hi,
                              __half* __restrict__ lo, int n4)
{
    int i = blockIdx.x * blockDim.x + threadIdx.x;
    if (i >= n4) return;
    float4 v = ((const float4*)in)[i];
    __half hx = __float2half(v.x);
    __half hy = __float2half(v.y);
    __half hz = __float2half(v.z);
    __half hw = __float2half(v.w);
    __half2* hp = reinterpret_cast<__half2*>(hi);
    __half2* lp = reinterpret_cast<__half2*>(lo);
    hp[2*i]   = __halves2half2(hx, hy);
    hp[2*i+1] = __halves2half2(hz, hw);
    lp[2*i]   = __floats2half2_rn(v.x - __half2float(hx), v.y - __half2float(hy));
    lp[2*i+1] = __floats2half2_rn(v.z - __half2float(hz), v.w - __half2float(hw));
}

__global__ void cvt_f16(const float* __restrict__ in,
                        __half* __restrict__ out, int n4)
{
    int i = blockIdx.x * blockDim.x + threadIdx.x;
    if (i >= n4) return;
    float4 v = ((const float4*)in)[i];
    __half2* op = reinterpret_cast<__half2*>(out);
    op[2*i]   = __floats2half2_rn(v.x, v.y);
    op[2*i+1] = __floats2half2_rn(v.z, v.w);
}

// ---------------------------------------------------------------------------
// TMA fp16 2-term GEMM: C[M,N] = (Ahi+Alo)[M,K] @ Bh[N,K]^T (fp32 accum)
// 128x256 tile, 256 threads (8 fat warps: 2 M x 4 N, 64x64 each).
// K-chunk 64 (128B rows, SW128), 2-stage TMA + mbarrier.
// Stage: Ahi 16KB | Alo 16KB | B 32KB = 64KB.
// ---------------------------------------------------------------------------
#define GSTG 65536
#define GEMM_SMEM (2 * GSTG + 2048)

__global__ __launch_bounds__(256, 1) void hgemm_tma(
    const __grid_constant__ CUtensorMap tmAhi,
    const __grid_constant__ CUtensorMap tmAlo,
    const __grid_constant__ CUtensorMap tmB,
    float* __restrict__ C, int N, int K)
{
    extern __shared__ char dsm[];
    const uint32_t sraw = smem_u32(dsm);
    const uint32_t mb = sraw;                             // 2 mbarriers @ sraw
    const uint32_t sb = (sraw + 32 + 1023) & ~1023u;      // 1024-aligned tiles

    const int tid = threadIdx.x;
    const int lane = tid & 31;
    const int wid = tid >> 5;
    const int wm = wid & 1;          // 2 M-groups x 64 rows
    const int wn = wid >> 1;         // 4 N-groups x 64 cols
    const int bm = blockIdx.y * 128;
    const int bn = blockIdx.x * 256;

    float c[4][8][4];
#pragma unroll
    for (int i = 0; i < 4; i++)
#pragma unroll
        for (int nf = 0; nf < 8; nf++)
#pragma unroll
            for (int e = 0; e < 4; e++) c[i][nf][e] = 0.f;

    if (tid == 0) {
        mbar_init(mb, 1);
        mbar_init(mb + 8, 1);
    }
    __syncthreads();

    const int nch = K / 64;
    if (tid == 0) {
        mbar_expect(mb, 65536);
        tma2d(sb,         &tmAhi, 0, bm, mb);
        tma2d(sb + 16384, &tmAlo, 0, bm, mb);
        tma2d(sb + 32768, &tmB,   0, bn, mb);
    }

    for (int ck = 0; ck < nch; ck++) {
        mbar_wait(mb + (ck & 1) * 8, (ck >> 1) & 1);
        if (ck + 1 < nch && tid == 0) {
            const uint32_t st2 = sb + ((ck + 1) & 1) * GSTG;
            const uint32_t m2 = mb + ((ck + 1) & 1) * 8;
            mbar_expect(m2, 65536);
            tma2d(st2,         &tmAhi, (ck + 1) * 64, bm, m2);
            tma2d(st2 + 16384, &tmAlo, (ck + 1) * 64, bm, m2);
            tma2d(st2 + 32768, &tmB,   (ck + 1) * 64, bn, m2);
        }

        const uint32_t st = sb + (ck & 1) * GSTG;
#pragma unroll
        for (int ks = 0; ks < 4; ks++) {
            uint32_t ah[4][4], al[4][4];
#pragma unroll
            for (int i = 0; i < 4; i++) {
                int row = wm * 64 + i * 16 + (lane & 15);
                int col = ks * 16 + (lane >> 4) * 8;
                uint32_t off = sw128((uint32_t)(row * 128 + col * 2));
                ldm4(ah[i], st + off);
                ldm4(al[i], st + 16384 + off);
            }
#pragma unroll
            for (int nfp = 0; nfp < 4; nfp++) {
                int g = lane >> 3;
                int row = wn * 64 + nfp * 16 + ((g >= 2) ? 8 : 0) + (lane & 7);
                int col = ks * 16 + ((g & 1) ? 8 : 0);
                uint32_t off = sw128((uint32_t)(row * 128 + col * 2));
                uint32_t bh[4];
                ldm4(bh, st + 32768 + off);
#pragma unroll
                for (int i = 0; i < 4; i++) {
                    mma16816f(c[i][2*nfp],   ah[i], bh);
                    mma16816f(c[i][2*nfp+1], ah[i], bh + 2);
                }
#pragma unroll
                for (int i = 0; i < 4; i++) {
                    mma16816f(c[i][2*nfp],   al[i], bh);
                    mma16816f(c[i][2*nfp+1], al[i], bh + 2);
                }
            }
        }
        __syncthreads();   // seal stage reads before it is reused
    }

#pragma unroll
    for (int i = 0; i < 4; i++) {
#pragma unroll
        for (int nf = 0; nf < 8; nf++) {
            int row = bm + wm * 64 + i * 16 + (lane >> 2);
            int col = bn + wn * 64 + nf * 8 + (lane & 3) * 2;
            *(float2*)(C + (size_t)row * N + col) = make_float2(c[i][nf][0], c[i][nf][1]);
            *(float2*)(C + (size_t)(row + 8) * N + col) = make_float2(c[i][nf][2], c[i][nf][3]);
        }
    }
}

// ---------------------------------------------------------------------------
// RoPE tables (verified)
// ---------------------------------------------------------------------------
__global__ void rope_tables()
{
    int idx = blockIdx.x * blockDim.x + threadIdx.x;
    if (idx >= SSQ * 32) return;
    int s = idx >> 5;
    int i = idx & 31;
    double inv_d = exp(-(double)i * (9.210340371976184 / 32.0));
    float  ang_f = (float)s * (float)inv_d;
    double c, sn;
    sincos((double)ang_f, &sn, &c);
    g_cos[idx] = (float)c;
    g_sin[idx] = (float)sn;
}

__device__ __forceinline__ void split_store_h(__half* hi, __half* lo,
                                              size_t idx, float v)
{
    __half h = __float2half(v);
    hi[idx] = h;
    lo[idx] = __float2half(v - __half2float(h));
}

// RoPE + fp16 convert + relayout to [b,h,s,d]. q split-2 (pre-scaled), k,v single.
__global__ __launch_bounds__(512) void rope_split()
{
    int s = blockIdx.x;
    int b = blockIdx.y;
    int h = threadIdx.x >> 5;
    int i = threadIdx.x & 31;

    float c  = g_cos[s * 32 + i];
    float sn = g_sin[s * 32 + i];

    size_t row  = ((size_t)(b * SSQ + s)) * NQKV + (size_t)h * HD;
    size_t orow = ((size_t)((b * NH + h) * SSQ) + s) * HD;

    float q1 = g_qkv[row + i];
    float q2 = g_qkv[row + 32 + i];
    split_store_h(g_aqh, g_aql, orow + i,      (q1 * c - q2 * sn) * 0.125f);
    split_store_h(g_aqh, g_aql, orow + 32 + i, (q1 * sn + q2 * c) * 0.125f);

    float k1 = g_qkv[row + DIM + i];
    float k2 = g_qkv[row + DIM + 32 + i];
    g_ak[orow + i]      = __float2half(k1 * c - k2 * sn);
    g_ak[orow + 32 + i] = __float2half(k1 * sn + k2 * c);

    g_av[orow + i]      = __float2half(g_qkv[row + 2 * DIM + i]);
    g_av[orow + 32 + i] = __float2half(g_qkv[row + 2 * DIM + 32 + i]);
}

// ---------------------------------------------------------------------------
// TMA fp16 flash attention (causal).
// Q split-2 x K single (2 QK terms); P single x V single (1 PV term).
// Q via TMA once; K/V 2-stage TMA per 64-key tile. LPT block order.
// smem: Qh 16K | Ql 16K | stage0 (K 8K | V 8K) | stage1 = 64KB (+align slack).
// ---------------------------------------------------------------------------
#define AQH 0
#define AQL 16384
#define AKV 32768
#define ATTN_SMEM (65536 + 2048)

__global__ __launch_bounds__(256, 1) void attn_tma(
    const __grid_constant__ CUtensorMap tmQh,
    const __grid_constant__ CUtensorMap tmQl,
    const __grid_constant__ CUtensorMap tmK,
    const __grid_constant__ CUtensorMap tmV)
{
    extern __shared__ char dsm[];
    const uint32_t sraw = smem_u32(dsm);
    const uint32_t mb = sraw;                        // 3 mbarriers: q, s0, s1
    const uint32_t sb = (sraw + 32 + 1023) & ~1023u;

    const int tid  = threadIdx.x;
    const int lane = tid & 31;
    const int wid  = tid >> 5;
    const int qb   = (int)(gridDim.x - 1 - blockIdx.x);   // LPT
    const int h    = blockIdx.y;
    const int b    = blockIdx.z;

    const int headrow = (b * NH + h) * SSQ;

    if (tid == 0) {
        mbar_init(mb, 1);
        mbar_init(mb + 8, 1);
        mbar_init(mb + 16, 1);
    }
    __syncthreads();

    if (tid == 0) {
        mbar_expect(mb, 32768);
        tma2d(sb + AQH, &tmQh, 0, headrow + qb * 128, mb);
        tma2d(sb + AQL, &tmQl, 0, headrow + qb * 128, mb);
        mbar_expect(mb + 8, 16384);
        tma2d(sb + AKV,        &tmK, 0, headrow, mb + 8);
        tma2d(sb + AKV + 8192, &tmV, 0, headrow, mb + 8);
    }
    mbar_wait(mb, 0);

    // ---- extract Q fragments ----
    uint32_t qh[4][4], ql[4][4];
#pragma unroll
    for (int ks = 0; ks < 4; ks++) {
        int row = wid * 16 + (lane & 15);
        int col = ks * 16 + (lane >> 4) * 8;
        uint32_t off = sw128((uint32_t)(row * 128 + col * 2));
        ldm4(qh[ks], sb + AQH + off);
        ldm4(ql[ks], sb + AQL + off);
    }

    float m0 = -1e30f, m1 = -1e30f, l0 = 0.f, l1 = 0.f;
    float o[8][4];
#pragma unroll
    for (int df = 0; df < 8; df++)
#pragma unroll
        for (int e = 0; e < 4; e++) o[df][e] = 0.f;

    const int qi0 = qb * 128 + wid * 16 + (lane >> 2);
    const int qi1 = qi0 + 8;
    const int ntiles = 2 * qb + 2;

    for (int kt = 0; kt < ntiles; kt++) {
        mbar_wait(mb + 8 + (kt & 1) * 8, (kt >> 1) & 1);
        if (kt + 1 < ntiles && tid == 0) {
            const uint32_t st2 = sb + AKV + ((kt + 1) & 1) * 16384;
            const uint32_t m2 = mb + 8 + ((kt + 1) & 1) * 8;
            mbar_expect(m2, 16384);
            tma2d(st2,        &tmK, 0, headrow + (kt + 1) * 64, m2);
            tma2d(st2 + 8192, &tmV, 0, headrow + (kt + 1) * 64, m2);
        }

        const uint32_t sK = sb + AKV + (kt & 1) * 16384;
        const uint32_t sV = sK + 8192;

        // ---- scores: S(16x64) = (Qh+Ql) @ K^T ----
        float s[8][4];
#pragma unroll
        for (int nf = 0; nf < 8; nf++)
#pragma unroll
            for (int e = 0; e < 4; e++) s[nf][e] = 0.f;

#pragma unroll
        for (int ks = 0; ks < 4; ks++) {
#pragma unroll
            for (int nfp = 0; nfp < 4; nfp++) {
                int g = lane >> 3;
                int row = nfp * 16 + ((g >= 2) ? 8 : 0) + (lane & 7);
                int col = ks * 16 + ((g & 1) ? 8 : 0);
                uint32_t off = sw128((uint32_t)(row * 128 + col * 2));
                uint32_t bk[4];
                ldm4(bk, sK + off);
                mma16816f(s[2*nfp],   qh[ks], bk);
                mma16816f(s[2*nfp+1], qh[ks], bk + 2);
                mma16816f(s[2*nfp],   ql[ks], bk);
                mma16816f(s[2*nfp+1], ql[ks], bk + 2);
            }
        }

        // ---- causal mask ----
        if (kt >= 2 * qb) {
            int kbase = kt * 64 + (lane & 3) * 2;
#pragma unroll
            for (int nf = 0; nf < 8; nf++) {
                int kj = kbase + nf * 8;
                if (kj     > qi0) s[nf][0] = -1e30f;
                if (kj + 1 > qi0) s[nf][1] = -1e30f;
                if (kj     > qi1) s[nf][2] = -1e30f;
                if (kj + 1 > qi1) s[nf][3] = -1e30f;
            }
        }

        // ---- online softmax ----
        float rmax0 = -1e30f, rmax1 = -1e30f;
#pragma unroll
        for (int nf = 0; nf < 8; nf++) {
            rmax0 = fmaxf(rmax0, fmaxf(s[nf][0], s[nf][1]));
            rmax1 = fmaxf(rmax1, fmaxf(s[nf][2], s[nf][3]));
        }
        rmax0 = fmaxf(rmax0, __shfl_xor_sync(0xFFFFFFFFu, rmax0, 1));
        rmax0 = fmaxf(rmax0, __shfl_xor_sync(0xFFFFFFFFu, rmax0, 2));
        rmax1 = fmaxf(rmax1, __shfl_xor_sync(0xFFFFFFFFu, rmax1, 1));
        rmax1 = fmaxf(rmax1, __shfl_xor_sync(0xFFFFFFFFu, rmax1, 2));

        float mn0 = fmaxf(m0, rmax0);
        float mn1 = fmaxf(m1, rmax1);
        float corr0 = __expf(m0 - mn0);
        float corr1 = __expf(m1 - mn1);
        m0 = mn0; m1 = mn1;
        l0 *= corr0; l1 *= corr1;
#pragma unroll
        for (int df = 0; df < 8; df++) {
            o[df][0] *= corr0; o[df][1] *= corr0;
            o[df][2] *= corr1; o[df][3] *= corr1;
        }

        uint32_t p01[8], p23[8];
#pragma unroll
        for (int nf = 0; nf < 8; nf++) {
            float p0 = __expf(s[nf][0] - m0);
            float p1 = __expf(s[nf][1] - m0);
            float p2 = __expf(s[nf][2] - m1);
            float p3 = __expf(s[nf][3] - m1);
            l0 += p0 + p1;
            l1 += p2 + p3;
            p01[nf] = pack_f16x2(p0, p1);
            p23[nf] = pack_f16x2(p2, p3);
        }

        // ---- O += P @ V (single term) ----
#pragma unroll
        for (int ks = 0; ks < 4; ks++) {
            uint32_t aP[4] = {p01[2*ks], p23[2*ks], p01[2*ks+1], p23[2*ks+1]};
#pragma unroll
            for (int dfp = 0; dfp < 4; dfp++) {
                int g = lane >> 3;
                int row = ks * 16 + ((g & 1) ? 8 : 0) + (lane & 7);
                int col = dfp * 16 + ((g >= 2) ? 8 : 0);
                uint32_t off = sw128((uint32_t)(row * 128 + col * 2));
                uint32_t bv[4];
                ldm4t(bv, sV + off);
                mma16816f(o[2*dfp],   aP, bv);
                mma16816f(o[2*dfp+1], aP, bv + 2);
            }
        }
        __syncthreads();   // seal stage reads before reuse
    }

    // ---- finalize: normalize, fp16-split, store as GEMM2's A operand ----
    l0 += __shfl_xor_sync(0xFFFFFFFFu, l0, 1);
    l0 += __shfl_xor_sync(0xFFFFFFFFu, l0, 2);
    l1 += __shfl_xor_sync(0xFFFFFFFFu, l1, 1);
    l1 += __shfl_xor_sync(0xFFFFFFFFu, l1, 2);
    float inv0 = 1.0f / l0;
    float inv1 = 1.0f / l1;

#pragma unroll
    for (int df = 0; df < 8; df++) {
        int col = h * HD + df * 8 + (lane & 3) * 2;
        size_t r0 = (size_t)(b * SSQ + qi0) * DIM + col;
        size_t r1 = (size_t)(b * SSQ + qi1) * DIM + col;
        float v0 = o[df][0] * inv0, v1 = o[df][1] * inv0;
        float v2 = o[df][2] * inv1, v3 = o[df][3] * inv1;
        __half h0 = __float2half(v0), h1 = __float2half(v1);
        __half h2 = __float2half(v2), h3 = __float2half(v3);
        *(__half2*)(g_ahi + r0) = __halves2half2(h0, h1);
        *(__half2*)(g_alo + r0) = __floats2half2_rn(v0 - __half2float(h0),
                                                    v1 - __half2float(h1));
        *(__half2*)(g_ahi + r1) = __halves2half2(h2, h3);
        *(__half2*)(g_alo + r1) = __floats2half2_rn(v2 - __half2float(h2),
                                                    v3 - __half2float(h3));
    }
}

// ---------------------------------------------------------------------------
// Host: tensor-map encoding via driver entry point (no -lcuda needed)
// ---------------------------------------------------------------------------
typedef CUresult (*EncodeFn)(
    CUtensorMap*, CUtensorMapDataType, cuuint32_t, void*,
    const cuuint64_t*, const cuuint64_t*, const cuuint32_t*, const cuuint32_t*,
    CUtensorMapInterleave, CUtensorMapSwizzle, CUtensorMapL2promotion,
    CUtensorMapFloatOOBfill);

static void enc2d(EncodeFn f, CUtensorMap* tm, void* p,
                  unsigned long long d0, unsigned long long d1,
                  unsigned long long strideB,
                  unsigned b0, unsigned b1)
{
    cuuint64_t dims[2] = {d0, d1};
    cuuint64_t st[1]   = {strideB};
    cuuint32_t box[2]  = {b0, b1};
    cuuint32_t es[2]   = {1, 1};
    f(tm, CU_TENSOR_MAP_DATA_TYPE_FLOAT16, 2, p, dims, st, box, es,
      CU_TENSOR_MAP_INTERLEAVE_NONE, CU_TENSOR_MAP_SWIZZLE_128B,
      CU_TENSOR_MAP_L2_PROMOTION_L2_128B, CU_TENSOR_MAP_FLOAT_OOB_FILL_NONE);
}

extern "C" void kernel_launch(void* const* d_in, const int* in_sizes, int n_in,
                              void* d_out, int out_size)
{
    const float* x = nullptr;
    const float* wqkv = nullptr;
    const float* wout = nullptr;
    for (int i = 0; i < n_in; i++) {
        long long n = in_sizes[i];
        if (n == (long long)MROWS * DIM)      x    = (const float*)d_in[i];
        else if (n == (long long)NQKV * DIM)  wqkv = (const float*)d_in[i];
        else if (n == (long long)DIM * DIM)   wout = (const float*)d_in[i];
    }
    if (!x || !wqkv || !wout) return;

    float* qkv = nullptr;
    __half *ahi, *alo, *wh, *vh2, *aqh, *aql, *ak, *av;
    cudaGetSymbolAddress((void**)&qkv, g_qkv);
    cudaGetSymbolAddress((void**)&ahi, g_ahi);
    cudaGetSymbolAddress((void**)&alo, g_alo);
    cudaGetSymbolAddress((void**)&wh,  g_wh);
    cudaGetSymbolAddress((void**)&vh2, g_vh2);
    cudaGetSymbolAddress((void**)&aqh, g_aqh);
    cudaGetSymbolAddress((void**)&aql, g_aql);
    cudaGetSymbolAddress((void**)&ak,  g_ak);
    cudaGetSymbolAddress((void**)&av,  g_av);

    // driver entry point for tensor-map encoding
    EncodeFn enc = nullptr;
    {
        void* fn = nullptr;
        cudaDriverEntryPointQueryResult qr;
        cudaGetDriverEntryPoint("cuTensorMapEncodeTiled", &fn,
                                cudaEnableDefault, &qr);
        enc = (EncodeFn)fn;
    }
    if (!enc) return;

    CUtensorMap tmAhi, tmAlo, tmW, tmV2, tmQh, tmQl, tmK, tmV;
    enc2d(enc, &tmAhi, ahi, DIM, MROWS, DIM * 2, 64, 128);
    enc2d(enc, &tmAlo, alo, DIM, MROWS, DIM * 2, 64, 128);
    enc2d(enc, &tmW,   wh,  DIM, NQKV,  DIM * 2, 64, 256);
    enc2d(enc, &tmV2,  vh2, DIM, DIM,   DIM * 2, 64, 256);
    enc2d(enc, &tmQh,  aqh, HD, HEADROWS, HD * 2, 64, 128);
    enc2d(enc, &tmQl,  aql, HD, HEADROWS, HD * 2, 64, 128);
    enc2d(enc, &tmK,   ak,  HD, HEADROWS, HD * 2, 64, 64);
    enc2d(enc, &tmV,   av,  HD, HEADROWS, HD * 2, 64, 64);

    cudaFuncSetAttribute(hgemm_tma, cudaFuncAttributeMaxDynamicSharedMemorySize,
                         GEMM_SMEM);
    cudaFuncSetAttribute(attn_tma, cudaFuncAttributeMaxDynamicSharedMemorySize,
                         ATTN_SMEM);

    // 0) fp16 operand prep
    cvt_split_f16<<<(MROWS * DIM / 4 + 255) / 256, 256>>>(x, ahi, alo, MROWS * DIM / 4);
    cvt_f16<<<(NQKV * DIM / 4 + 255) / 256, 256>>>(wqkv, wh, NQKV * DIM / 4);
    cvt_f16<<<(DIM * DIM / 4 + 255) / 256, 256>>>(wout, vh2, DIM * DIM / 4);

    // 1) qkv = x @ Wqkv^T  (fp16 2-term, TMA)
    dim3 g1(NQKV / 256, MROWS / 128);
    hgemm_tma<<<g1, 256, GEMM_SMEM>>>(tmAhi, tmAlo, tmW, qkv, NQKV, DIM);

    // 2) RoPE + fp16 convert + relayout
    rope_tables<<<(SSQ * 32) / 256, 256>>>();
    dim3 gr(SSQ, BB);
    rope_split<<<gr, 512>>>();

    // 3) fp16 flash attention (TMA; writes fp16 A-split for GEMM2)
    dim3 ga(SSQ / 128, NH, BB);
    attn_tma<<<ga, 256, ATTN_SMEM>>>(tmQh, tmQl, tmK, tmV);

    // 4) out = att @ Wout^T  (fp16 2-term, TMA)
    dim3 g2(DIM / 256, MROWS / 128);
    hgemm_tma<<<g2, 256, GEMM_SMEM>>>(tmAhi, tmAlo, tmV2, (float*)d_out, DIM, DIM);
}

// round 13
// speedup vs baseline: 8.7451x; 1.3212x over previous
#include <cuda_runtime.h>
#include <cuda.h>
#include <cuda_bf16.h>
#include <cuda_fp16.h>
#include <math.h>
#include <stdint.h>

#define BB 4
#define SSQ 2048
#define DIM 1024
#define NH 16
#define HD 64
#define MROWS (BB*SSQ)       // 8192
#define NQKV (3*DIM)         // 3072
#define HEADS_ELEMS ((size_t)BB * NH * SSQ * HD)   // 8.4M
#define HEADROWS ((size_t)BB * NH * SSQ)           // 131072

// ---------------- scratch (device globals; allocation-free) ----------------
__device__ float g_qkv[(size_t)MROWS * NQKV];   // fp32 qkv after GEMM1
__device__ float g_cos[SSQ * 32];
__device__ float g_sin[SSQ * 32];
// GEMM operands (single fp16 A x single fp16 B)
__device__ __half g_ah[(size_t)MROWS * DIM];    // x, later attention output
__device__ __half g_wh[(size_t)NQKV * DIM];
__device__ __half g_vh2[(size_t)DIM * DIM];
// attention operands (fp16): Q split-2, K single, V single, [b,h,s,d]
__device__ __half g_aqh[HEADS_ELEMS], g_aql[HEADS_ELEMS];
__device__ __half g_ak[HEADS_ELEMS];
__device__ __half g_av[HEADS_ELEMS];

// ---------------- PTX helpers (plain sm_103-safe) ---------------------------
__device__ __forceinline__ uint32_t smem_u32(const void* p) {
    uint32_t a;
    asm("{ .reg .u64 t; cvta.to.shared.u64 t, %1; cvt.u32.u64 %0, t; }"
        : "=r"(a) : "l"(p));
    return a;
}
__device__ __forceinline__ uint32_t sw128(uint32_t off) {
    return off ^ ((off >> 3) & 0x70);
}
__device__ __forceinline__ void mma16816f(float* c, const uint32_t* a, const uint32_t* b) {
    asm volatile(
        "mma.sync.aligned.m16n8k16.row.col.f32.f16.f16.f32 "
        "{%0,%1,%2,%3}, {%4,%5,%6,%7}, {%8,%9}, {%0,%1,%2,%3};"
        : "+f"(c[0]), "+f"(c[1]), "+f"(c[2]), "+f"(c[3])
        : "r"(a[0]), "r"(a[1]), "r"(a[2]), "r"(a[3]), "r"(b[0]), "r"(b[1]));
}
__device__ __forceinline__ void ldm4(uint32_t* r, uint32_t addr) {
    asm volatile("ldmatrix.sync.aligned.m8n8.x4.shared.b16 {%0,%1,%2,%3}, [%4];"
                 : "=r"(r[0]), "=r"(r[1]), "=r"(r[2]), "=r"(r[3]) : "r"(addr));
}
__device__ __forceinline__ void ldm4t(uint32_t* r, uint32_t addr) {
    asm volatile("ldmatrix.sync.aligned.m8n8.x4.trans.shared.b16 {%0,%1,%2,%3}, [%4];"
                 : "=r"(r[0]), "=r"(r[1]), "=r"(r[2]), "=r"(r[3]) : "r"(addr));
}
__device__ __forceinline__ uint32_t pack_f16x2(float lo, float hi) {
    uint32_t d;
    asm("cvt.rn.f16x2.f32 %0, %1, %2;" : "=r"(d) : "f"(hi), "f"(lo));
    return d;
}
__device__ __forceinline__ void mbar_init(uint32_t mbar, uint32_t cnt) {
    asm volatile("mbarrier.init.shared.b64 [%0], %1;" :: "r"(mbar), "r"(cnt) : "memory");
}
__device__ __forceinline__ void mbar_expect(uint32_t mbar, uint32_t bytes) {
    asm volatile("mbarrier.arrive.expect_tx.shared.b64 _, [%0], %1;"
                 :: "r"(mbar), "r"(bytes) : "memory");
}
__device__ __forceinline__ void mbar_wait(uint32_t mbar, uint32_t parity) {
    uint32_t done;
    asm volatile(
        "{\n\t.reg .pred p;\n\t"
        "mbarrier.try_wait.parity.acquire.cta.shared::cta.b64 p, [%1], %2;\n\t"
        "selp.b32 %0, 1, 0, p;\n\t}"
        : "=r"(done) : "r"(mbar), "r"(parity) : "memory");
    if (!done) {
        asm volatile(
            "{\n\t.reg .pred P1;\n\t"
            "W_%=:\n\t"
            "mbarrier.try_wait.parity.acquire.cta.shared::cta.b64 P1, [%0], %1, 0x989680;\n\t"
            "@P1 bra.uni D_%=;\n\t"
            "bra.uni W_%=;\n\t"
            "D_%=:\n\t}"
            :: "r"(mbar), "r"(parity) : "memory");
    }
}
__device__ __forceinline__ void tma2d(uint32_t dst, const CUtensorMap* tm,
                                      int x, int y, uint32_t mbar) {
    asm volatile(
        "cp.async.bulk.tensor.2d.shared::cta.global.tile.mbarrier::complete_tx::bytes "
        "[%0], [%1, {%2, %3}], [%4];"
        :: "r"(dst), "l"(tm), "r"(x), "r"(y), "r"(mbar) : "memory");
}

// ---------------------------------------------------------------------------
// fp32 -> fp16 converts
// ---------------------------------------------------------------------------
__global__ void cvt_f16(const float* __restrict__ in,
                        __half* __restrict__ out, int n4)
{
    int i = blockIdx.x * blockDim.x + threadIdx.x;
    if (i >= n4) return;
    float4 v = ((const float4*)in)[i];
    __half2* op = reinterpret_cast<__half2*>(out);
    op[2*i]   = __floats2half2_rn(v.x, v.y);
    op[2*i+1] = __floats2half2_rn(v.z, v.w);
}

// ---------------------------------------------------------------------------
// TMA fp16 GEMM: C[M,N] = A[M,K] @ B[N,K]^T (fp32 accum), single-term.
// 128x256 tile, 256 threads (8 fat warps: 2 M x 4 N, 64x64 each).
// K-chunk 64 (128B rows, SW128), 3-stage TMA + mbarrier.
// Stage: A 16KB | B 32KB = 48KB; 3 stages = 144KB.
// ---------------------------------------------------------------------------
#define GSTG 49152
#define GEMM_SMEM (3 * GSTG + 2048)

__global__ __launch_bounds__(256, 1) void hgemm_tma(
    const __grid_constant__ CUtensorMap tmA,
    const __grid_constant__ CUtensorMap tmB,
    float* __restrict__ C, int N, int K)
{
    extern __shared__ char dsm[];
    const uint32_t sraw = smem_u32(dsm);
    const uint32_t mb = sraw;                             // 3 mbarriers
    const uint32_t sb = (sraw + 32 + 1023) & ~1023u;      // 1024-aligned tiles

    const int tid = threadIdx.x;
    const int lane = tid & 31;
    const int wid = tid >> 5;
    const int wm = wid & 1;          // 2 M-groups x 64 rows
    const int wn = wid >> 1;         // 4 N-groups x 64 cols
    const int bm = blockIdx.y * 128;
    const int bn = blockIdx.x * 256;

    float c[4][8][4];
#pragma unroll
    for (int i = 0; i < 4; i++)
#pragma unroll
        for (int nf = 0; nf < 8; nf++)
#pragma unroll
            for (int e = 0; e < 4; e++) c[i][nf][e] = 0.f;

    if (tid == 0) {
        mbar_init(mb, 1);
        mbar_init(mb + 8, 1);
        mbar_init(mb + 16, 1);
    }
    __syncthreads();

    const int nch = K / 64;
    // prologue: stages 0 and 1
    if (tid == 0) {
#pragma unroll
        for (int p = 0; p < 2; p++) {
            const uint32_t st = sb + p * GSTG;
            mbar_expect(mb + p * 8, GSTG);
            tma2d(st,         &tmA, p * 64, bm, mb + p * 8);
            tma2d(st + 16384, &tmB, p * 64, bn, mb + p * 8);
        }
    }

    for (int ck = 0; ck < nch; ck++) {
        const int slot = ck % 3;
        mbar_wait(mb + slot * 8, (uint32_t)((ck / 3) & 1));
        if (ck + 2 < nch && tid == 0) {
            const int s2 = (ck + 2) % 3;
            const uint32_t st2 = sb + s2 * GSTG;
            mbar_expect(mb + s2 * 8, GSTG);
            tma2d(st2,         &tmA, (ck + 2) * 64, bm, mb + s2 * 8);
            tma2d(st2 + 16384, &tmB, (ck + 2) * 64, bn, mb + s2 * 8);
        }

        const uint32_t st = sb + slot * GSTG;
#pragma unroll
        for (int ks = 0; ks < 4; ks++) {
            uint32_t ah[4][4];
#pragma unroll
            for (int i = 0; i < 4; i++) {
                int row = wm * 64 + i * 16 + (lane & 15);
                int col = ks * 16 + (lane >> 4) * 8;
                uint32_t off = sw128((uint32_t)(row * 128 + col * 2));
                ldm4(ah[i], st + off);
            }
#pragma unroll
            for (int nfp = 0; nfp < 4; nfp++) {
                int g = lane >> 3;
                int row = wn * 64 + nfp * 16 + ((g >= 2) ? 8 : 0) + (lane & 7);
                int col = ks * 16 + ((g & 1) ? 8 : 0);
                uint32_t off = sw128((uint32_t)(row * 128 + col * 2));
                uint32_t bh[4];
                ldm4(bh, st + 16384 + off);
#pragma unroll
                for (int i = 0; i < 4; i++) {
                    mma16816f(c[i][2*nfp],   ah[i], bh);
                    mma16816f(c[i][2*nfp+1], ah[i], bh + 2);
                }
            }
        }
        __syncthreads();   // seal stage reads before reuse
    }

#pragma unroll
    for (int i = 0; i < 4; i++) {
#pragma unroll
        for (int nf = 0; nf < 8; nf++) {
            int row = bm + wm * 64 + i * 16 + (lane >> 2);
            int col = bn + wn * 64 + nf * 8 + (lane & 3) * 2;
            *(float2*)(C + (size_t)row * N + col) = make_float2(c[i][nf][0], c[i][nf][1]);
            *(float2*)(C + (size_t)(row + 8) * N + col) = make_float2(c[i][nf][2], c[i][nf][3]);
        }
    }
}

// ---------------------------------------------------------------------------
// RoPE tables (verified)
// ---------------------------------------------------------------------------
__global__ void rope_tables()
{
    int idx = blockIdx.x * blockDim.x + threadIdx.x;
    if (idx >= SSQ * 32) return;
    int s = idx >> 5;
    int i = idx & 31;
    double inv_d = exp(-(double)i * (9.210340371976184 / 32.0));
    float  ang_f = (float)s * (float)inv_d;
    double c, sn;
    sincos((double)ang_f, &sn, &c);
    g_cos[idx] = (float)c;
    g_sin[idx] = (float)sn;
}

__device__ __forceinline__ void split_store_h(__half* hi, __half* lo,
                                              size_t idx, float v)
{
    __half h = __float2half(v);
    hi[idx] = h;
    lo[idx] = __float2half(v - __half2float(h));
}

// RoPE + fp16 convert + relayout to [b,h,s,d]. q split-2 (pre-scaled), k,v single.
__global__ __launch_bounds__(512) void rope_split()
{
    int s = blockIdx.x;
    int b = blockIdx.y;
    int h = threadIdx.x >> 5;
    int i = threadIdx.x & 31;

    float c  = g_cos[s * 32 + i];
    float sn = g_sin[s * 32 + i];

    size_t row  = ((size_t)(b * SSQ + s)) * NQKV + (size_t)h * HD;
    size_t orow = ((size_t)((b * NH + h) * SSQ) + s) * HD;

    float q1 = g_qkv[row + i];
    float q2 = g_qkv[row + 32 + i];
    split_store_h(g_aqh, g_aql, orow + i,      (q1 * c - q2 * sn) * 0.125f);
    split_store_h(g_aqh, g_aql, orow + 32 + i, (q1 * sn + q2 * c) * 0.125f);

    float k1 = g_qkv[row + DIM + i];
    float k2 = g_qkv[row + DIM + 32 + i];
    g_ak[orow + i]      = __float2half(k1 * c - k2 * sn);
    g_ak[orow + 32 + i] = __float2half(k1 * sn + k2 * c);

    g_av[orow + i]      = __float2half(g_qkv[row + 2 * DIM + i]);
    g_av[orow + 32 + i] = __float2half(g_qkv[row + 2 * DIM + 32 + i]);
}

// ---------------------------------------------------------------------------
// TMA fp16 flash attention (causal). (verified R11; epilogue stores single fp16)
// Q split-2 x K single (2 QK terms); P single x V single (1 PV term).
// ---------------------------------------------------------------------------
#define AQH 0
#define AQL 16384
#define AKV 32768
#define ATTN_SMEM (65536 + 2048)

__global__ __launch_bounds__(256, 1) void attn_tma(
    const __grid_constant__ CUtensorMap tmQh,
    const __grid_constant__ CUtensorMap tmQl,
    const __grid_constant__ CUtensorMap tmK,
    const __grid_constant__ CUtensorMap tmV)
{
    extern __shared__ char dsm[];
    const uint32_t sraw = smem_u32(dsm);
    const uint32_t mb = sraw;                        // 3 mbarriers: q, s0, s1
    const uint32_t sb = (sraw + 32 + 1023) & ~1023u;

    const int tid  = threadIdx.x;
    const int lane = tid & 31;
    const int wid  = tid >> 5;
    const int qb   = (int)(gridDim.x - 1 - blockIdx.x);   // LPT
    const int h    = blockIdx.y;
    const int b    = blockIdx.z;

    const int headrow = (b * NH + h) * SSQ;

    if (tid == 0) {
        mbar_init(mb, 1);
        mbar_init(mb + 8, 1);
        mbar_init(mb + 16, 1);
    }
    __syncthreads();

    if (tid == 0) {
        mbar_expect(mb, 32768);
        tma2d(sb + AQH, &tmQh, 0, headrow + qb * 128, mb);
        tma2d(sb + AQL, &tmQl, 0, headrow + qb * 128, mb);
        mbar_expect(mb + 8, 16384);
        tma2d(sb + AKV,        &tmK, 0, headrow, mb + 8);
        tma2d(sb + AKV + 8192, &tmV, 0, headrow, mb + 8);
    }
    mbar_wait(mb, 0);

    // ---- extract Q fragments ----
    uint32_t qh[4][4], ql[4][4];
#pragma unroll
    for (int ks = 0; ks < 4; ks++) {
        int row = wid * 16 + (lane & 15);
        int col = ks * 16 + (lane >> 4) * 8;
        uint32_t off = sw128((uint32_t)(row * 128 + col * 2));
        ldm4(qh[ks], sb + AQH + off);
        ldm4(ql[ks], sb + AQL + off);
    }

    float m0 = -1e30f, m1 = -1e30f, l0 = 0.f, l1 = 0.f;
    float o[8][4];
#pragma unroll
    for (int df = 0; df < 8; df++)
#pragma unroll
        for (int e = 0; e < 4; e++) o[df][e] = 0.f;

    const int qi0 = qb * 128 + wid * 16 + (lane >> 2);
    const int qi1 = qi0 + 8;
    const int ntiles = 2 * qb + 2;

    for (int kt = 0; kt < ntiles; kt++) {
        mbar_wait(mb + 8 + (kt & 1) * 8, (kt >> 1) & 1);
        if (kt + 1 < ntiles && tid == 0) {
            const uint32_t st2 = sb + AKV + ((kt + 1) & 1) * 16384;
            const uint32_t m2 = mb + 8 + ((kt + 1) & 1) * 8;
            mbar_expect(m2, 16384);
            tma2d(st2,        &tmK, 0, headrow + (kt + 1) * 64, m2);
            tma2d(st2 + 8192, &tmV, 0, headrow + (kt + 1) * 64, m2);
        }

        const uint32_t sK = sb + AKV + (kt & 1) * 16384;
        const uint32_t sV = sK + 8192;

        // ---- scores: S(16x64) = (Qh+Ql) @ K^T ----
        float s[8][4];
#pragma unroll
        for (int nf = 0; nf < 8; nf++)
#pragma unroll
            for (int e = 0; e < 4; e++) s[nf][e] = 0.f;

#pragma unroll
        for (int ks = 0; ks < 4; ks++) {
#pragma unroll
            for (int nfp = 0; nfp < 4; nfp++) {
                int g = lane >> 3;
                int row = nfp * 16 + ((g >= 2) ? 8 : 0) + (lane & 7);
                int col = ks * 16 + ((g & 1) ? 8 : 0);
                uint32_t off = sw128((uint32_t)(row * 128 + col * 2));
                uint32_t bk[4];
                ldm4(bk, sK + off);
                mma16816f(s[2*nfp],   qh[ks], bk);
                mma16816f(s[2*nfp+1], qh[ks], bk + 2);
                mma16816f(s[2*nfp],   ql[ks], bk);
                mma16816f(s[2*nfp+1], ql[ks], bk + 2);
            }
        }

        // ---- causal mask ----
        if (kt >= 2 * qb) {
            int kbase = kt * 64 + (lane & 3) * 2;
#pragma unroll
            for (int nf = 0; nf < 8; nf++) {
                int kj = kbase + nf * 8;
                if (kj     > qi0) s[nf][0] = -1e30f;
                if (kj + 1 > qi0) s[nf][1] = -1e30f;
                if (kj     > qi1) s[nf][2] = -1e30f;
                if (kj + 1 > qi1) s[nf][3] = -1e30f;
            }
        }

        // ---- online softmax ----
        float rmax0 = -1e30f, rmax1 = -1e30f;
#pragma unroll
        for (int nf = 0; nf < 8; nf++) {
            rmax0 = fmaxf(rmax0, fmaxf(s[nf][0], s[nf][1]));
            rmax1 = fmaxf(rmax1, fmaxf(s[nf][2], s[nf][3]));
        }
        rmax0 = fmaxf(rmax0, __shfl_xor_sync(0xFFFFFFFFu, rmax0, 1));
        rmax0 = fmaxf(rmax0, __shfl_xor_sync(0xFFFFFFFFu, rmax0, 2));
        rmax1 = fmaxf(rmax1, __shfl_xor_sync(0xFFFFFFFFu, rmax1, 1));
        rmax1 = fmaxf(rmax1, __shfl_xor_sync(0xFFFFFFFFu, rmax1, 2));

        float mn0 = fmaxf(m0, rmax0);
        float mn1 = fmaxf(m1, rmax1);
        float corr0 = __expf(m0 - mn0);
        float corr1 = __expf(m1 - mn1);
        m0 = mn0; m1 = mn1;
        l0 *= corr0; l1 *= corr1;
#pragma unroll
        for (int df = 0; df < 8; df++) {
            o[df][0] *= corr0; o[df][1] *= corr0;
            o[df][2] *= corr1; o[df][3] *= corr1;
        }

        uint32_t p01[8], p23[8];
#pragma unroll
        for (int nf = 0; nf < 8; nf++) {
            float p0 = __expf(s[nf][0] - m0);
            float p1 = __expf(s[nf][1] - m0);
            float p2 = __expf(s[nf][2] - m1);
            float p3 = __expf(s[nf][3] - m1);
            l0 += p0 + p1;
            l1 += p2 + p3;
            p01[nf] = pack_f16x2(p0, p1);
            p23[nf] = pack_f16x2(p2, p3);
        }

        // ---- O += P @ V (single term) ----
#pragma unroll
        for (int ks = 0; ks < 4; ks++) {
            uint32_t aP[4] = {p01[2*ks], p23[2*ks], p01[2*ks+1], p23[2*ks+1]};
#pragma unroll
            for (int dfp = 0; dfp < 4; dfp++) {
                int g = lane >> 3;
                int row = ks * 16 + ((g & 1) ? 8 : 0) + (lane & 7);
                int col = dfp * 16 + ((g >= 2) ? 8 : 0);
                uint32_t off = sw128((uint32_t)(row * 128 + col * 2));
                uint32_t bv[4];
                ldm4t(bv, sV + off);
                mma16816f(o[2*dfp],   aP, bv);
                mma16816f(o[2*dfp+1], aP, bv + 2);
            }
        }
        __syncthreads();   // seal stage reads before reuse
    }

    // ---- finalize: normalize, store single fp16 as GEMM2's A operand ----
    l0 += __shfl_xor_sync(0xFFFFFFFFu, l0, 1);
    l0 += __shfl_xor_sync(0xFFFFFFFFu, l0, 2);
    l1 += __shfl_xor_sync(0xFFFFFFFFu, l1, 1);
    l1 += __shfl_xor_sync(0xFFFFFFFFu, l1, 2);
    float inv0 = 1.0f / l0;
    float inv1 = 1.0f / l1;

#pragma unroll
    for (int df = 0; df < 8; df++) {
        int col = h * HD + df * 8 + (lane & 3) * 2;
        size_t r0 = (size_t)(b * SSQ + qi0) * DIM + col;
        size_t r1 = (size_t)(b * SSQ + qi1) * DIM + col;
        *(__half2*)(g_ah + r0) = __floats2half2_rn(o[df][0] * inv0, o[df][1] * inv0);
        *(__half2*)(g_ah + r1) = __floats2half2_rn(o[df][2] * inv1, o[df][3] * inv1);
    }
}

// ---------------------------------------------------------------------------
// Host: tensor-map encoding via driver entry point (no -lcuda needed)
// ---------------------------------------------------------------------------
typedef CUresult (*EncodeFn)(
    CUtensorMap*, CUtensorMapDataType, cuuint32_t, void*,
    const cuuint64_t*, const cuuint64_t*, const cuuint32_t*, const cuuint32_t*,
    CUtensorMapInterleave, CUtensorMapSwizzle, CUtensorMapL2promotion,
    CUtensorMapFloatOOBfill);

static void enc2d(EncodeFn f, CUtensorMap* tm, void* p,
                  unsigned long long d0, unsigned long long d1,
                  unsigned long long strideB,
                  unsigned b0, unsigned b1)
{
    cuuint64_t dims[2] = {d0, d1};
    cuuint64_t st[1]   = {strideB};
    cuuint32_t box[2]  = {b0, b1};
    cuuint32_t es[2]   = {1, 1};
    f(tm, CU_TENSOR_MAP_DATA_TYPE_FLOAT16, 2, p, dims, st, box, es,
      CU_TENSOR_MAP_INTERLEAVE_NONE, CU_TENSOR_MAP_SWIZZLE_128B,
      CU_TENSOR_MAP_L2_PROMOTION_L2_128B, CU_TENSOR_MAP_FLOAT_OOB_FILL_NONE);
}

extern "C" void kernel_launch(void* const* d_in, const int* in_sizes, int n_in,
                              void* d_out, int out_size)
{
    const float* x = nullptr;
    const float* wqkv = nullptr;
    const float* wout = nullptr;
    for (int i = 0; i < n_in; i++) {
        long long n = in_sizes[i];
        if (n == (long long)MROWS * DIM)      x    = (const float*)d_in[i];
        else if (n == (long long)NQKV * DIM)  wqkv = (const float*)d_in[i];
        else if (n == (long long)DIM * DIM)   wout = (const float*)d_in[i];
    }
    if (!x || !wqkv || !wout) return;

    float* qkv = nullptr;
    __half *ah, *wh, *vh2, *aqh, *aql, *ak, *av;
    cudaGetSymbolAddress((void**)&qkv, g_qkv);
    cudaGetSymbolAddress((void**)&ah,  g_ah);
    cudaGetSymbolAddress((void**)&wh,  g_wh);
    cudaGetSymbolAddress((void**)&vh2, g_vh2);
    cudaGetSymbolAddress((void**)&aqh, g_aqh);
    cudaGetSymbolAddress((void**)&aql, g_aql);
    cudaGetSymbolAddress((void**)&ak,  g_ak);
    cudaGetSymbolAddress((void**)&av,  g_av);

    EncodeFn enc = nullptr;
    {
        void* fn = nullptr;
        cudaDriverEntryPointQueryResult qr;
        cudaGetDriverEntryPoint("cuTensorMapEncodeTiled", &fn,
                                cudaEnableDefault, &qr);
        enc = (EncodeFn)fn;
    }
    if (!enc) return;

    CUtensorMap tmA, tmW, tmV2, tmQh, tmQl, tmK, tmV;
    enc2d(enc, &tmA,  ah,  DIM, MROWS, DIM * 2, 64, 128);
    enc2d(enc, &tmW,  wh,  DIM, NQKV,  DIM * 2, 64, 256);
    enc2d(enc, &tmV2, vh2, DIM, DIM,   DIM * 2, 64, 256);
    enc2d(enc, &tmQh, aqh, HD, HEADROWS, HD * 2, 64, 128);
    enc2d(enc, &tmQl, aql, HD, HEADROWS, HD * 2, 64, 128);
    enc2d(enc, &tmK,  ak,  HD, HEADROWS, HD * 2, 64, 64);
    enc2d(enc, &tmV,  av,  HD, HEADROWS, HD * 2, 64, 64);

    cudaFuncSetAttribute(hgemm_tma, cudaFuncAttributeMaxDynamicSharedMemorySize,
                         GEMM_SMEM);
    cudaFuncSetAttribute(attn_tma, cudaFuncAttributeMaxDynamicSharedMemorySize,
                         ATTN_SMEM);

    // 0) fp16 operand prep (x and weights single fp16)
    cvt_f16<<<(MROWS * DIM / 4 + 255) / 256, 256>>>(x, ah, MROWS * DIM / 4);
    cvt_f16<<<(NQKV * DIM / 4 + 255) / 256, 256>>>(wqkv, wh, NQKV * DIM / 4);
    cvt_f16<<<(DIM * DIM / 4 + 255) / 256, 256>>>(wout, vh2, DIM * DIM / 4);

    // 1) qkv = x @ Wqkv^T  (fp16 single-term, 3-stage TMA)
    dim3 g1(NQKV / 256, MROWS / 128);
    hgemm_tma<<<g1, 256, GEMM_SMEM>>>(tmA, tmW, qkv, NQKV, DIM);

    // 2) RoPE + fp16 convert + relayout
    rope_tables<<<(SSQ * 32) / 256, 256>>>();
    dim3 gr(SSQ, BB);
    rope_split<<<gr, 512>>>();

    // 3) fp16 flash attention (TMA; writes fp16 A for GEMM2)
    dim3 ga(SSQ / 128, NH, BB);
    attn_tma<<<ga, 256, ATTN_SMEM>>>(tmQh, tmQl, tmK, tmV);

    // 4) out = att @ Wout^T  (fp16 single-term, 3-stage TMA)
    dim3 g2(DIM / 256, MROWS / 128);
    hgemm_tma<<<g2, 256, GEMM_SMEM>>>(tmA, tmV2, (float*)d_out, DIM, DIM);
}

// round 14
// speedup vs baseline: 9.3358x; 1.0675x over previous
#include <cuda_runtime.h>
#include <cuda.h>
#include <cuda_bf16.h>
#include <cuda_fp16.h>
#include <math.h>
#include <stdint.h>

#define BB 4
#define SSQ 2048
#define DIM 1024
#define NH 16
#define HD 64
#define MROWS (BB*SSQ)       // 8192
#define NQKV (3*DIM)         // 3072
#define HEADS_ELEMS ((size_t)BB * NH * SSQ * HD)   // 8.4M
#define HEADROWS ((size_t)BB * NH * SSQ)           // 131072

// ---------------- scratch (device globals; allocation-free) ----------------
__device__ float g_qkv[(size_t)MROWS * NQKV];   // fp32 qkv after GEMM1
__device__ float g_cos[SSQ * 32];
__device__ float g_sin[SSQ * 32];
// GEMM operands (single fp16 A x single fp16 B)
__device__ __half g_ah[(size_t)MROWS * DIM];    // x, later attention output
__device__ __half g_wh[(size_t)NQKV * DIM];
__device__ __half g_vh2[(size_t)DIM * DIM];
// attention operands (fp16, all single): Q (pre-scaled), K, V in [b,h,s,d]
__device__ __half g_aq[HEADS_ELEMS];
__device__ __half g_ak[HEADS_ELEMS];
__device__ __half g_av[HEADS_ELEMS];

// ---------------- PTX helpers (plain sm_103-safe) ---------------------------
__device__ __forceinline__ uint32_t smem_u32(const void* p) {
    uint32_t a;
    asm("{ .reg .u64 t; cvta.to.shared.u64 t, %1; cvt.u32.u64 %0, t; }"
        : "=r"(a) : "l"(p));
    return a;
}
__device__ __forceinline__ uint32_t sw128(uint32_t off) {
    return off ^ ((off >> 3) & 0x70);
}
__device__ __forceinline__ void mma16816f(float* c, const uint32_t* a, const uint32_t* b) {
    asm volatile(
        "mma.sync.aligned.m16n8k16.row.col.f32.f16.f16.f32 "
        "{%0,%1,%2,%3}, {%4,%5,%6,%7}, {%8,%9}, {%0,%1,%2,%3};"
        : "+f"(c[0]), "+f"(c[1]), "+f"(c[2]), "+f"(c[3])
        : "r"(a[0]), "r"(a[1]), "r"(a[2]), "r"(a[3]), "r"(b[0]), "r"(b[1]));
}
__device__ __forceinline__ void ldm4(uint32_t* r, uint32_t addr) {
    asm volatile("ldmatrix.sync.aligned.m8n8.x4.shared.b16 {%0,%1,%2,%3}, [%4];"
                 : "=r"(r[0]), "=r"(r[1]), "=r"(r[2]), "=r"(r[3]) : "r"(addr));
}
__device__ __forceinline__ void ldm4t(uint32_t* r, uint32_t addr) {
    asm volatile("ldmatrix.sync.aligned.m8n8.x4.trans.shared.b16 {%0,%1,%2,%3}, [%4];"
                 : "=r"(r[0]), "=r"(r[1]), "=r"(r[2]), "=r"(r[3]) : "r"(addr));
}
__device__ __forceinline__ uint32_t pack_f16x2(float lo, float hi) {
    uint32_t d;
    asm("cvt.rn.f16x2.f32 %0, %1, %2;" : "=r"(d) : "f"(hi), "f"(lo));
    return d;
}
__device__ __forceinline__ void mbar_init(uint32_t mbar, uint32_t cnt) {
    asm volatile("mbarrier.init.shared.b64 [%0], %1;" :: "r"(mbar), "r"(cnt) : "memory");
}
__device__ __forceinline__ void mbar_expect(uint32_t mbar, uint32_t bytes) {
    asm volatile("mbarrier.arrive.expect_tx.shared.b64 _, [%0], %1;"
                 :: "r"(mbar), "r"(bytes) : "memory");
}
__device__ __forceinline__ void mbar_wait(uint32_t mbar, uint32_t parity) {
    uint32_t done;
    asm volatile(
        "{\n\t.reg .pred p;\n\t"
        "mbarrier.try_wait.parity.acquire.cta.shared::cta.b64 p, [%1], %2;\n\t"
        "selp.b32 %0, 1, 0, p;\n\t}"
        : "=r"(done) : "r"(mbar), "r"(parity) : "memory");
    if (!done) {
        asm volatile(
            "{\n\t.reg .pred P1;\n\t"
            "W_%=:\n\t"
            "mbarrier.try_wait.parity.acquire.cta.shared::cta.b64 P1, [%0], %1, 0x989680;\n\t"
            "@P1 bra.uni D_%=;\n\t"
            "bra.uni W_%=;\n\t"
            "D_%=:\n\t}"
            :: "r"(mbar), "r"(parity) : "memory");
    }
}
__device__ __forceinline__ void tma2d(uint32_t dst, const CUtensorMap* tm,
                                      int x, int y, uint32_t mbar) {
    asm volatile(
        "cp.async.bulk.tensor.2d.shared::cta.global.tile.mbarrier::complete_tx::bytes "
        "[%0], [%1, {%2, %3}], [%4];"
        :: "r"(dst), "l"(tm), "r"(x), "r"(y), "r"(mbar) : "memory");
}

// ---------------------------------------------------------------------------
// fp32 -> fp16 converts
// ---------------------------------------------------------------------------
__global__ void cvt_f16(const float* __restrict__ in,
                        __half* __restrict__ out, int n4)
{
    int i = blockIdx.x * blockDim.x + threadIdx.x;
    if (i >= n4) return;
    float4 v = ((const float4*)in)[i];
    __half2* op = reinterpret_cast<__half2*>(out);
    op[2*i]   = __floats2half2_rn(v.x, v.y);
    op[2*i+1] = __floats2half2_rn(v.z, v.w);
}

// ---------------------------------------------------------------------------
// TMA fp16 GEMM: C[M,N] = A[M,K] @ B[N,K]^T (fp32 accum), single-term.
// 128x256 tile, 256 threads (8 fat warps: 2 M x 4 N, 64x64 each).
// K-chunk 64 (128B rows, SW128), 3-stage TMA + mbarrier. (verified R12)
// ---------------------------------------------------------------------------
#define GSTG 49152
#define GEMM_SMEM (3 * GSTG + 2048)

__global__ __launch_bounds__(256, 1) void hgemm_tma(
    const __grid_constant__ CUtensorMap tmA,
    const __grid_constant__ CUtensorMap tmB,
    float* __restrict__ C, int N, int K)
{
    extern __shared__ char dsm[];
    const uint32_t sraw = smem_u32(dsm);
    const uint32_t mb = sraw;                             // 3 mbarriers
    const uint32_t sb = (sraw + 32 + 1023) & ~1023u;      // 1024-aligned tiles

    const int tid = threadIdx.x;
    const int lane = tid & 31;
    const int wid = tid >> 5;
    const int wm = wid & 1;          // 2 M-groups x 64 rows
    const int wn = wid >> 1;         // 4 N-groups x 64 cols
    const int bm = blockIdx.y * 128;
    const int bn = blockIdx.x * 256;

    float c[4][8][4];
#pragma unroll
    for (int i = 0; i < 4; i++)
#pragma unroll
        for (int nf = 0; nf < 8; nf++)
#pragma unroll
            for (int e = 0; e < 4; e++) c[i][nf][e] = 0.f;

    if (tid == 0) {
        mbar_init(mb, 1);
        mbar_init(mb + 8, 1);
        mbar_init(mb + 16, 1);
    }
    __syncthreads();

    const int nch = K / 64;
    if (tid == 0) {
#pragma unroll
        for (int p = 0; p < 2; p++) {
            const uint32_t st = sb + p * GSTG;
            mbar_expect(mb + p * 8, GSTG);
            tma2d(st,         &tmA, p * 64, bm, mb + p * 8);
            tma2d(st + 16384, &tmB, p * 64, bn, mb + p * 8);
        }
    }

    for (int ck = 0; ck < nch; ck++) {
        const int slot = ck % 3;
        mbar_wait(mb + slot * 8, (uint32_t)((ck / 3) & 1));
        if (ck + 2 < nch && tid == 0) {
            const int s2 = (ck + 2) % 3;
            const uint32_t st2 = sb + s2 * GSTG;
            mbar_expect(mb + s2 * 8, GSTG);
            tma2d(st2,         &tmA, (ck + 2) * 64, bm, mb + s2 * 8);
            tma2d(st2 + 16384, &tmB, (ck + 2) * 64, bn, mb + s2 * 8);
        }

        const uint32_t st = sb + slot * GSTG;
#pragma unroll
        for (int ks = 0; ks < 4; ks++) {
            uint32_t ah[4][4];
#pragma unroll
            for (int i = 0; i < 4; i++) {
                int row = wm * 64 + i * 16 + (lane & 15);
                int col = ks * 16 + (lane >> 4) * 8;
                uint32_t off = sw128((uint32_t)(row * 128 + col * 2));
                ldm4(ah[i], st + off);
            }
#pragma unroll
            for (int nfp = 0; nfp < 4; nfp++) {
                int g = lane >> 3;
                int row = wn * 64 + nfp * 16 + ((g >= 2) ? 8 : 0) + (lane & 7);
                int col = ks * 16 + ((g & 1) ? 8 : 0);
                uint32_t off = sw128((uint32_t)(row * 128 + col * 2));
                uint32_t bh[4];
                ldm4(bh, st + 16384 + off);
#pragma unroll
                for (int i = 0; i < 4; i++) {
                    mma16816f(c[i][2*nfp],   ah[i], bh);
                    mma16816f(c[i][2*nfp+1], ah[i], bh + 2);
                }
            }
        }
        __syncthreads();   // seal stage reads before reuse
    }

#pragma unroll
    for (int i = 0; i < 4; i++) {
#pragma unroll
        for (int nf = 0; nf < 8; nf++) {
            int row = bm + wm * 64 + i * 16 + (lane >> 2);
            int col = bn + wn * 64 + nf * 8 + (lane & 3) * 2;
            *(float2*)(C + (size_t)row * N + col) = make_float2(c[i][nf][0], c[i][nf][1]);
            *(float2*)(C + (size_t)(row + 8) * N + col) = make_float2(c[i][nf][2], c[i][nf][3]);
        }
    }
}

// ---------------------------------------------------------------------------
// RoPE tables (verified)
// ---------------------------------------------------------------------------
__global__ void rope_tables()
{
    int idx = blockIdx.x * blockDim.x + threadIdx.x;
    if (idx >= SSQ * 32) return;
    int s = idx >> 5;
    int i = idx & 31;
    double inv_d = exp(-(double)i * (9.210340371976184 / 32.0));
    float  ang_f = (float)s * (float)inv_d;
    double c, sn;
    sincos((double)ang_f, &sn, &c);
    g_cos[idx] = (float)c;
    g_sin[idx] = (float)sn;
}

// RoPE + fp16 convert + relayout to [b,h,s,d]. q single (pre-scaled), k,v single.
__global__ __launch_bounds__(512) void rope_split()
{
    int s = blockIdx.x;
    int b = blockIdx.y;
    int h = threadIdx.x >> 5;
    int i = threadIdx.x & 31;

    float c  = g_cos[s * 32 + i];
    float sn = g_sin[s * 32 + i];

    size_t row  = ((size_t)(b * SSQ + s)) * NQKV + (size_t)h * HD;
    size_t orow = ((size_t)((b * NH + h) * SSQ) + s) * HD;

    float q1 = g_qkv[row + i];
    float q2 = g_qkv[row + 32 + i];
    g_aq[orow + i]      = __float2half((q1 * c - q2 * sn) * 0.125f);
    g_aq[orow + 32 + i] = __float2half((q1 * sn + q2 * c) * 0.125f);

    float k1 = g_qkv[row + DIM + i];
    float k2 = g_qkv[row + DIM + 32 + i];
    g_ak[orow + i]      = __float2half(k1 * c - k2 * sn);
    g_ak[orow + 32 + i] = __float2half(k1 * sn + k2 * c);

    g_av[orow + i]      = __float2half(g_qkv[row + 2 * DIM + i]);
    g_av[orow + 32 + i] = __float2half(g_qkv[row + 2 * DIM + 32 + i]);
}

// ---------------------------------------------------------------------------
// TMA fp16 flash attention (causal), all-single-fp16 operands.
// Q single x K single (1 QK term); P single x V single (1 PV term).
// Q via TMA once; K/V 2-stage TMA per 64-key tile. LPT block order.
// smem: Q 16K | stage0 (K 8K | V 8K) | stage1 = 48KB (+align slack).
// ---------------------------------------------------------------------------
#define AQ  0
#define AKV 16384
#define ATTN_SMEM (49152 + 2048)

__global__ __launch_bounds__(256, 1) void attn_tma(
    const __grid_constant__ CUtensorMap tmQ,
    const __grid_constant__ CUtensorMap tmK,
    const __grid_constant__ CUtensorMap tmV)
{
    extern __shared__ char dsm[];
    const uint32_t sraw = smem_u32(dsm);
    const uint32_t mb = sraw;                        // 3 mbarriers: q, s0, s1
    const uint32_t sb = (sraw + 32 + 1023) & ~1023u;

    const int tid  = threadIdx.x;
    const int lane = tid & 31;
    const int wid  = tid >> 5;
    const int qb   = (int)(gridDim.x - 1 - blockIdx.x);   // LPT
    const int h    = blockIdx.y;
    const int b    = blockIdx.z;

    const int headrow = (b * NH + h) * SSQ;

    if (tid == 0) {
        mbar_init(mb, 1);
        mbar_init(mb + 8, 1);
        mbar_init(mb + 16, 1);
    }
    __syncthreads();

    if (tid == 0) {
        mbar_expect(mb, 16384);
        tma2d(sb + AQ, &tmQ, 0, headrow + qb * 128, mb);
        mbar_expect(mb + 8, 16384);
        tma2d(sb + AKV,        &tmK, 0, headrow, mb + 8);
        tma2d(sb + AKV + 8192, &tmV, 0, headrow, mb + 8);
    }
    mbar_wait(mb, 0);

    // ---- extract Q fragments ----
    uint32_t qf[4][4];
#pragma unroll
    for (int ks = 0; ks < 4; ks++) {
        int row = wid * 16 + (lane & 15);
        int col = ks * 16 + (lane >> 4) * 8;
        uint32_t off = sw128((uint32_t)(row * 128 + col * 2));
        ldm4(qf[ks], sb + AQ + off);
    }

    float m0 = -1e30f, m1 = -1e30f, l0 = 0.f, l1 = 0.f;
    float o[8][4];
#pragma unroll
    for (int df = 0; df < 8; df++)
#pragma unroll
        for (int e = 0; e < 4; e++) o[df][e] = 0.f;

    const int qi0 = qb * 128 + wid * 16 + (lane >> 2);
    const int qi1 = qi0 + 8;
    const int ntiles = 2 * qb + 2;

    for (int kt = 0; kt < ntiles; kt++) {
        mbar_wait(mb + 8 + (kt & 1) * 8, (kt >> 1) & 1);
        if (kt + 1 < ntiles && tid == 0) {
            const uint32_t st2 = sb + AKV + ((kt + 1) & 1) * 16384;
            const uint32_t m2 = mb + 8 + ((kt + 1) & 1) * 8;
            mbar_expect(m2, 16384);
            tma2d(st2,        &tmK, 0, headrow + (kt + 1) * 64, m2);
            tma2d(st2 + 8192, &tmV, 0, headrow + (kt + 1) * 64, m2);
        }

        const uint32_t sK = sb + AKV + (kt & 1) * 16384;
        const uint32_t sV = sK + 8192;

        // ---- scores: S(16x64) = Q @ K^T (single term) ----
        float s[8][4];
#pragma unroll
        for (int nf = 0; nf < 8; nf++)
#pragma unroll
            for (int e = 0; e < 4; e++) s[nf][e] = 0.f;

#pragma unroll
        for (int ks = 0; ks < 4; ks++) {
#pragma unroll
            for (int nfp = 0; nfp < 4; nfp++) {
                int g = lane >> 3;
                int row = nfp * 16 + ((g >= 2) ? 8 : 0) + (lane & 7);
                int col = ks * 16 + ((g & 1) ? 8 : 0);
                uint32_t off = sw128((uint32_t)(row * 128 + col * 2));
                uint32_t bk[4];
                ldm4(bk, sK + off);
                mma16816f(s[2*nfp],   qf[ks], bk);
                mma16816f(s[2*nfp+1], qf[ks], bk + 2);
            }
        }

        // ---- causal mask ----
        if (kt >= 2 * qb) {
            int kbase = kt * 64 + (lane & 3) * 2;
#pragma unroll
            for (int nf = 0; nf < 8; nf++) {
                int kj = kbase + nf * 8;
                if (kj     > qi0) s[nf][0] = -1e30f;
                if (kj + 1 > qi0) s[nf][1] = -1e30f;
                if (kj     > qi1) s[nf][2] = -1e30f;
                if (kj + 1 > qi1) s[nf][3] = -1e30f;
            }
        }

        // ---- online softmax ----
        float rmax0 = -1e30f, rmax1 = -1e30f;
#pragma unroll
        for (int nf = 0; nf < 8; nf++) {
            rmax0 = fmaxf(rmax0, fmaxf(s[nf][0], s[nf][1]));
            rmax1 = fmaxf(rmax1, fmaxf(s[nf][2], s[nf][3]));
        }
        rmax0 = fmaxf(rmax0, __shfl_xor_sync(0xFFFFFFFFu, rmax0, 1));
        rmax0 = fmaxf(rmax0, __shfl_xor_sync(0xFFFFFFFFu, rmax0, 2));
        rmax1 = fmaxf(rmax1, __shfl_xor_sync(0xFFFFFFFFu, rmax1, 1));
        rmax1 = fmaxf(rmax1, __shfl_xor_sync(0xFFFFFFFFu, rmax1, 2));

        float mn0 = fmaxf(m0, rmax0);
        float mn1 = fmaxf(m1, rmax1);
        float corr0 = __expf(m0 - mn0);
        float corr1 = __expf(m1 - mn1);
        m0 = mn0; m1 = mn1;
        l0 *= corr0; l1 *= corr1;
#pragma unroll
        for (int df = 0; df < 8; df++) {
            o[df][0] *= corr0; o[df][1] *= corr0;
            o[df][2] *= corr1; o[df][3] *= corr1;
        }

        uint32_t p01[8], p23[8];
#pragma unroll
        for (int nf = 0; nf < 8; nf++) {
            float p0 = __expf(s[nf][0] - m0);
            float p1 = __expf(s[nf][1] - m0);
            float p2 = __expf(s[nf][2] - m1);
            float p3 = __expf(s[nf][3] - m1);
            l0 += p0 + p1;
            l1 += p2 + p3;
            p01[nf] = pack_f16x2(p0, p1);
            p23[nf] = pack_f16x2(p2, p3);
        }

        // ---- O += P @ V (single term) ----
#pragma unroll
        for (int ks = 0; ks < 4; ks++) {
            uint32_t aP[4] = {p01[2*ks], p23[2*ks], p01[2*ks+1], p23[2*ks+1]};
#pragma unroll
            for (int dfp = 0; dfp < 4; dfp++) {
                int g = lane >> 3;
                int row = ks * 16 + ((g & 1) ? 8 : 0) + (lane & 7);
                int col = dfp * 16 + ((g >= 2) ? 8 : 0);
                uint32_t off = sw128((uint32_t)(row * 128 + col * 2));
                uint32_t bv[4];
                ldm4t(bv, sV + off);
                mma16816f(o[2*dfp],   aP, bv);
                mma16816f(o[2*dfp+1], aP, bv + 2);
            }
        }
        __syncthreads();   // seal stage reads before reuse
    }

    // ---- finalize: normalize, store single fp16 as GEMM2's A operand ----
    l0 += __shfl_xor_sync(0xFFFFFFFFu, l0, 1);
    l0 += __shfl_xor_sync(0xFFFFFFFFu, l0, 2);
    l1 += __shfl_xor_sync(0xFFFFFFFFu, l1, 1);
    l1 += __shfl_xor_sync(0xFFFFFFFFu, l1, 2);
    float inv0 = 1.0f / l0;
    float inv1 = 1.0f / l1;

#pragma unroll
    for (int df = 0; df < 8; df++) {
        int col = h * HD + df * 8 + (lane & 3) * 2;
        size_t r0 = (size_t)(b * SSQ + qi0) * DIM + col;
        size_t r1 = (size_t)(b * SSQ + qi1) * DIM + col;
        *(__half2*)(g_ah + r0) = __floats2half2_rn(o[df][0] * inv0, o[df][1] * inv0);
        *(__half2*)(g_ah + r1) = __floats2half2_rn(o[df][2] * inv1, o[df][3] * inv1);
    }
}

// ---------------------------------------------------------------------------
// Host: tensor-map encoding via driver entry point (no -lcuda needed)
// ---------------------------------------------------------------------------
typedef CUresult (*EncodeFn)(
    CUtensorMap*, CUtensorMapDataType, cuuint32_t, void*,
    const cuuint64_t*, const cuuint64_t*, const cuuint32_t*, const cuuint32_t*,
    CUtensorMapInterleave, CUtensorMapSwizzle, CUtensorMapL2promotion,
    CUtensorMapFloatOOBfill);

static void enc2d(EncodeFn f, CUtensorMap* tm, void* p,
                  unsigned long long d0, unsigned long long d1,
                  unsigned long long strideB,
                  unsigned b0, unsigned b1)
{
    cuuint64_t dims[2] = {d0, d1};
    cuuint64_t st[1]   = {strideB};
    cuuint32_t box[2]  = {b0, b1};
    cuuint32_t es[2]   = {1, 1};
    f(tm, CU_TENSOR_MAP_DATA_TYPE_FLOAT16, 2, p, dims, st, box, es,
      CU_TENSOR_MAP_INTERLEAVE_NONE, CU_TENSOR_MAP_SWIZZLE_128B,
      CU_TENSOR_MAP_L2_PROMOTION_L2_128B, CU_TENSOR_MAP_FLOAT_OOB_FILL_NONE);
}

extern "C" void kernel_launch(void* const* d_in, const int* in_sizes, int n_in,
                              void* d_out, int out_size)
{
    const float* x = nullptr;
    const float* wqkv = nullptr;
    const float* wout = nullptr;
    for (int i = 0; i < n_in; i++) {
        long long n = in_sizes[i];
        if (n == (long long)MROWS * DIM)      x    = (const float*)d_in[i];
        else if (n == (long long)NQKV * DIM)  wqkv = (const float*)d_in[i];
        else if (n == (long long)DIM * DIM)   wout = (const float*)d_in[i];
    }
    if (!x || !wqkv || !wout) return;

    float* qkv = nullptr;
    __half *ah, *wh, *vh2, *aq, *ak, *av;
    cudaGetSymbolAddress((void**)&qkv, g_qkv);
    cudaGetSymbolAddress((void**)&ah,  g_ah);
    cudaGetSymbolAddress((void**)&wh,  g_wh);
    cudaGetSymbolAddress((void**)&vh2, g_vh2);
    cudaGetSymbolAddress((void**)&aq,  g_aq);
    cudaGetSymbolAddress((void**)&ak,  g_ak);
    cudaGetSymbolAddress((void**)&av,  g_av);

    EncodeFn enc = nullptr;
    {
        void* fn = nullptr;
        cudaDriverEntryPointQueryResult qr;
        cudaGetDriverEntryPoint("cuTensorMapEncodeTiled", &fn,
                                cudaEnableDefault, &qr);
        enc = (EncodeFn)fn;
    }
    if (!enc) return;

    CUtensorMap tmA, tmW, tmV2, tmQ, tmK, tmV;
    enc2d(enc, &tmA,  ah,  DIM, MROWS, DIM * 2, 64, 128);
    enc2d(enc, &tmW,  wh,  DIM, NQKV,  DIM * 2, 64, 256);
    enc2d(enc, &tmV2, vh2, DIM, DIM,   DIM * 2, 64, 256);
    enc2d(enc, &tmQ,  aq,  HD, HEADROWS, HD * 2, 64, 128);
    enc2d(enc, &tmK,  ak,  HD, HEADROWS, HD * 2, 64, 64);
    enc2d(enc, &tmV,  av,  HD, HEADROWS, HD * 2, 64, 64);

    cudaFuncSetAttribute(hgemm_tma, cudaFuncAttributeMaxDynamicSharedMemorySize,
                         GEMM_SMEM);
    cudaFuncSetAttribute(attn_tma, cudaFuncAttributeMaxDynamicSharedMemorySize,
                         ATTN_SMEM);

    // 0) fp16 operand prep
    cvt_f16<<<(MROWS * DIM / 4 + 255) / 256, 256>>>(x, ah, MROWS * DIM / 4);
    cvt_f16<<<(NQKV * DIM / 4 + 255) / 256, 256>>>(wqkv, wh, NQKV * DIM / 4);
    cvt_f16<<<(DIM * DIM / 4 + 255) / 256, 256>>>(wout, vh2, DIM * DIM / 4);

    // 1) qkv = x @ Wqkv^T  (fp16 single-term, 3-stage TMA)
    dim3 g1(NQKV / 256, MROWS / 128);
    hgemm_tma<<<g1, 256, GEMM_SMEM>>>(tmA, tmW, qkv, NQKV, DIM);

    // 2) RoPE + fp16 convert + relayout
    rope_tables<<<(SSQ * 32) / 256, 256>>>();
    dim3 gr(SSQ, BB);
    rope_split<<<gr, 512>>>();

    // 3) fp16 flash attention (TMA; single-term QK and PV)
    dim3 ga(SSQ / 128, NH, BB);
    attn_tma<<<ga, 256, ATTN_SMEM>>>(tmQ, tmK, tmV);

    // 4) out = att @ Wout^T  (fp16 single-term, 3-stage TMA)
    dim3 g2(DIM / 256, MROWS / 128);
    hgemm_tma<<<g2, 256, GEMM_SMEM>>>(tmA, tmV2, (float*)d_out, DIM, DIM);
}

// round 15
// speedup vs baseline: 11.1654x; 1.1960x over previous
#include <cuda_runtime.h>
#include <cuda.h>
#include <cuda_fp16.h>
#include <math.h>
#include <stdint.h>

#define BB 4
#define SSQ 2048
#define DIM 1024
#define NH 16
#define HD 64
#define MROWS (BB*SSQ)       // 8192
#define NQKV (3*DIM)         // 3072
#define HEADS_ELEMS ((size_t)BB * NH * SSQ * HD)   // 8.4M
#define HEADROWS ((size_t)BB * NH * SSQ)           // 131072

// ---------------- scratch (device globals; allocation-free) ----------------
__device__ float g_cos[SSQ * 32];
__device__ float g_sin[SSQ * 32];
// GEMM operands (single fp16 A x single fp16 B)
__device__ __half g_ah[(size_t)MROWS * DIM];    // x, later attention output
__device__ __half g_wh[(size_t)NQKV * DIM];
__device__ __half g_vh2[(size_t)DIM * DIM];
// attention operands (fp16, all single): Q (pre-scaled), K, V in [b,h,s,d]
__device__ __half g_aq[HEADS_ELEMS];
__device__ __half g_ak[HEADS_ELEMS];
__device__ __half g_av[HEADS_ELEMS];

// ---------------- PTX helpers (plain sm_103-safe) ---------------------------
__device__ __forceinline__ uint32_t smem_u32(const void* p) {
    uint32_t a;
    asm("{ .reg .u64 t; cvta.to.shared.u64 t, %1; cvt.u32.u64 %0, t; }"
        : "=r"(a) : "l"(p));
    return a;
}
__device__ __forceinline__ uint32_t sw128(uint32_t off) {
    return off ^ ((off >> 3) & 0x70);
}
__device__ __forceinline__ void mma16816f(float* c, const uint32_t* a, const uint32_t* b) {
    asm volatile(
        "mma.sync.aligned.m16n8k16.row.col.f32.f16.f16.f32 "
        "{%0,%1,%2,%3}, {%4,%5,%6,%7}, {%8,%9}, {%0,%1,%2,%3};"
        : "+f"(c[0]), "+f"(c[1]), "+f"(c[2]), "+f"(c[3])
        : "r"(a[0]), "r"(a[1]), "r"(a[2]), "r"(a[3]), "r"(b[0]), "r"(b[1]));
}
__device__ __forceinline__ void ldm4(uint32_t* r, uint32_t addr) {
    asm volatile("ldmatrix.sync.aligned.m8n8.x4.shared.b16 {%0,%1,%2,%3}, [%4];"
                 : "=r"(r[0]), "=r"(r[1]), "=r"(r[2]), "=r"(r[3]) : "r"(addr));
}
__device__ __forceinline__ void ldm4t(uint32_t* r, uint32_t addr) {
    asm volatile("ldmatrix.sync.aligned.m8n8.x4.trans.shared.b16 {%0,%1,%2,%3}, [%4];"
                 : "=r"(r[0]), "=r"(r[1]), "=r"(r[2]), "=r"(r[3]) : "r"(addr));
}
__device__ __forceinline__ uint32_t pack_f16x2(float lo, float hi) {
    uint32_t d;
    asm("cvt.rn.f16x2.f32 %0, %1, %2;" : "=r"(d) : "f"(hi), "f"(lo));
    return d;
}
__device__ __forceinline__ void mbar_init(uint32_t mbar, uint32_t cnt) {
    asm volatile("mbarrier.init.shared.b64 [%0], %1;" :: "r"(mbar), "r"(cnt) : "memory");
}
__device__ __forceinline__ void mbar_expect(uint32_t mbar, uint32_t bytes) {
    asm volatile("mbarrier.arrive.expect_tx.shared.b64 _, [%0], %1;"
                 :: "r"(mbar), "r"(bytes) : "memory");
}
__device__ __forceinline__ void mbar_wait(uint32_t mbar, uint32_t parity) {
    uint32_t done;
    asm volatile(
        "{\n\t.reg .pred p;\n\t"
        "mbarrier.try_wait.parity.acquire.cta.shared::cta.b64 p, [%1], %2;\n\t"
        "selp.b32 %0, 1, 0, p;\n\t}"
        : "=r"(done) : "r"(mbar), "r"(parity) : "memory");
    if (!done) {
        asm volatile(
            "{\n\t.reg .pred P1;\n\t"
            "W_%=:\n\t"
            "mbarrier.try_wait.parity.acquire.cta.shared::cta.b64 P1, [%0], %1, 0x989680;\n\t"
            "@P1 bra.uni D_%=;\n\t"
            "bra.uni W_%=;\n\t"
            "D_%=:\n\t}"
            :: "r"(mbar), "r"(parity) : "memory");
    }
}
__device__ __forceinline__ void tma2d(uint32_t dst, const CUtensorMap* tm,
                                      int x, int y, uint32_t mbar) {
    asm volatile(
        "cp.async.bulk.tensor.2d.shared::cta.global.tile.mbarrier::complete_tx::bytes "
        "[%0], [%1, {%2, %3}], [%4];"
        :: "r"(dst), "l"(tm), "r"(x), "r"(y), "r"(mbar) : "memory");
}

// ---------------------------------------------------------------------------
// fp32 -> fp16 convert
// ---------------------------------------------------------------------------
__global__ void cvt_f16(const float* __restrict__ in,
                        __half* __restrict__ out, int n4)
{
    int i = blockIdx.x * blockDim.x + threadIdx.x;
    if (i >= n4) return;
    float4 v = ((const float4*)in)[i];
    __half2* op = reinterpret_cast<__half2*>(out);
    op[2*i]   = __floats2half2_rn(v.x, v.y);
    op[2*i+1] = __floats2half2_rn(v.z, v.w);
}

// ---------------------------------------------------------------------------
// RoPE tables (verified)
// ---------------------------------------------------------------------------
__global__ void rope_tables()
{
    int idx = blockIdx.x * blockDim.x + threadIdx.x;
    if (idx >= SSQ * 32) return;
    int s = idx >> 5;
    int i = idx & 31;
    double inv_d = exp(-(double)i * (9.210340371976184 / 32.0));
    float  ang_f = (float)s * (float)inv_d;
    double c, sn;
    sincos((double)ang_f, &sn, &c);
    g_cos[idx] = (float)c;
    g_sin[idx] = (float)sn;
}

// ---------------------------------------------------------------------------
// TMA fp16 GEMM: C = A[M,K] @ B[N,K]^T (fp32 accum), single-term.
// 128x128 tile, 256 threads (8 warps: 4 M-groups x 2 N-groups, 32x64 each),
// 2 CTAs/SM (64 accum regs/thread). K-chunk 64, 2-stage TMA.
// mode 0: write fp32 C. mode 1 (qkv): fused RoPE epilogue -> g_aq/g_ak/g_av.
// ---------------------------------------------------------------------------
#define GSTG 32768
#define GEMM_SMEM (2 * GSTG + 2048)

__global__ __launch_bounds__(256, 2) void hgemm_tma(
    const __grid_constant__ CUtensorMap tmA,
    const __grid_constant__ CUtensorMap tmB,
    float* __restrict__ C, int N, int K, int mode)
{
    extern __shared__ char dsm[];
    const uint32_t sraw = smem_u32(dsm);
    const uint32_t mb = sraw;                             // 2 mbarriers
    const uint32_t sb = (sraw + 32 + 1023) & ~1023u;      // 1024-aligned tiles

    const int tid = threadIdx.x;
    const int lane = tid & 31;
    const int wid = tid >> 5;
    const int wm = wid & 3;          // 4 M-groups x 32 rows
    const int wn = wid >> 2;         // 2 N-groups x 64 cols
    const int bm = blockIdx.y * 128;
    const int bn = blockIdx.x * 128;

    float c[2][8][4];
#pragma unroll
    for (int i = 0; i < 2; i++)
#pragma unroll
        for (int nf = 0; nf < 8; nf++)
#pragma unroll
            for (int e = 0; e < 4; e++) c[i][nf][e] = 0.f;

    if (tid == 0) {
        mbar_init(mb, 1);
        mbar_init(mb + 8, 1);
    }
    __syncthreads();

    const int nch = K / 64;
    if (tid == 0) {
#pragma unroll
        for (int p = 0; p < 2; p++) {
            const uint32_t st = sb + p * GSTG;
            mbar_expect(mb + p * 8, GSTG);
            tma2d(st,         &tmA, p * 64, bm, mb + p * 8);
            tma2d(st + 16384, &tmB, p * 64, bn, mb + p * 8);
        }
    }

    for (int ck = 0; ck < nch; ck++) {
        const int slot = ck & 1;
        mbar_wait(mb + slot * 8, (uint32_t)((ck >> 1) & 1));
        if (ck + 2 < nch && tid == 0) {
            const uint32_t st2 = sb + slot * GSTG;   // will rewrite this slot
            // NOTE: must wait for consumers of this slot before refilling; the
            // __syncthreads at loop end below seals prior reads, so only issue
            // the refill after compute. (handled after compute, see below)
        }

        const uint32_t st = sb + slot * GSTG;
#pragma unroll
        for (int ks = 0; ks < 4; ks++) {
            uint32_t af[2][4];
#pragma unroll
            for (int i = 0; i < 2; i++) {
                int row = wm * 32 + i * 16 + (lane & 15);
                int col = ks * 16 + (lane >> 4) * 8;
                uint32_t off = sw128((uint32_t)(row * 128 + col * 2));
                ldm4(af[i], st + off);
            }
#pragma unroll
            for (int nfp = 0; nfp < 4; nfp++) {
                int g = lane >> 3;
                int row = wn * 64 + nfp * 16 + ((g >= 2) ? 8 : 0) + (lane & 7);
                int col = ks * 16 + ((g & 1) ? 8 : 0);
                uint32_t off = sw128((uint32_t)(row * 128 + col * 2));
                uint32_t bh[4];
                ldm4(bh, st + 16384 + off);
#pragma unroll
                for (int i = 0; i < 2; i++) {
                    mma16816f(c[i][2*nfp],   af[i], bh);
                    mma16816f(c[i][2*nfp+1], af[i], bh + 2);
                }
            }
        }
        __syncthreads();   // all reads of this slot done
        if (ck + 2 < nch && tid == 0) {
            const uint32_t st2 = sb + slot * GSTG;
            mbar_expect(mb + slot * 8, GSTG);
            tma2d(st2,         &tmA, (ck + 2) * 64, bm, mb + slot * 8);
            tma2d(st2 + 16384, &tmB, (ck + 2) * 64, bn, mb + slot * 8);
        }
    }

    if (mode == 0) {
        // plain fp32 C epilogue
#pragma unroll
        for (int i = 0; i < 2; i++) {
#pragma unroll
            for (int nf = 0; nf < 8; nf++) {
                int row = bm + wm * 32 + i * 16 + (lane >> 2);
                int col = bn + wn * 64 + nf * 8 + (lane & 3) * 2;
                *(float2*)(C + (size_t)row * N + col) =
                    make_float2(c[i][nf][0], c[i][nf][1]);
                *(float2*)(C + (size_t)(row + 8) * N + col) =
                    make_float2(c[i][nf][2], c[i][nf][3]);
            }
        }
        return;
    }

    // ---- fused RoPE epilogue (qkv GEMM): warp owns exactly one head ----
    const int sec = bn / 1024;                          // 0=q, 1=k, 2=v
    const int h = ((bn & 1023) + wn * 64) >> 6;         // head index
#pragma unroll
    for (int i = 0; i < 2; i++) {
#pragma unroll
        for (int e2 = 0; e2 < 2; e2++) {
            int r = bm + wm * 32 + i * 16 + (lane >> 2) + e2 * 8;
            int b = r >> 11;
            int s = r & 2047;
            size_t obase = ((size_t)(b * NH + h) * SSQ + s) * HD;
#pragma unroll
            for (int nf = 0; nf < 4; nf++) {
                int ci = nf * 8 + (lane & 3) * 2;
                float x1a = c[i][nf][2*e2],     x1b = c[i][nf][2*e2+1];
                float x2a = c[i][nf+4][2*e2],   x2b = c[i][nf+4][2*e2+1];
                if (sec == 2) {
                    *(__half2*)(g_av + obase + ci)      = __floats2half2_rn(x1a, x1b);
                    *(__half2*)(g_av + obase + ci + 32) = __floats2half2_rn(x2a, x2b);
                } else {
                    float2 cc = *(const float2*)(g_cos + s * 32 + ci);
                    float2 ss = *(const float2*)(g_sin + s * 32 + ci);
                    float o1a = x1a * cc.x - x2a * ss.x;
                    float o1b = x1b * cc.y - x2b * ss.y;
                    float o2a = x1a * ss.x + x2a * cc.x;
                    float o2b = x1b * ss.y + x2b * cc.y;
                    if (sec == 0) {
                        o1a *= 0.125f; o1b *= 0.125f; o2a *= 0.125f; o2b *= 0.125f;
                        *(__half2*)(g_aq + obase + ci)      = __floats2half2_rn(o1a, o1b);
                        *(__half2*)(g_aq + obase + ci + 32) = __floats2half2_rn(o2a, o2b);
                    } else {
                        *(__half2*)(g_ak + obase + ci)      = __floats2half2_rn(o1a, o1b);
                        *(__half2*)(g_ak + obase + ci + 32) = __floats2half2_rn(o2a, o2b);
                    }
                }
            }
        }
    }
}

// ---------------------------------------------------------------------------
// TMA fp16 flash attention (causal), all-single-fp16 operands. (verified R13)
// ---------------------------------------------------------------------------
#define AQ  0
#define AKV 16384
#define ATTN_SMEM (49152 + 2048)

__global__ __launch_bounds__(256, 1) void attn_tma(
    const __grid_constant__ CUtensorMap tmQ,
    const __grid_constant__ CUtensorMap tmK,
    const __grid_constant__ CUtensorMap tmV)
{
    extern __shared__ char dsm[];
    const uint32_t sraw = smem_u32(dsm);
    const uint32_t mb = sraw;                        // 3 mbarriers: q, s0, s1
    const uint32_t sb = (sraw + 32 + 1023) & ~1023u;

    const int tid  = threadIdx.x;
    const int lane = tid & 31;
    const int wid  = tid >> 5;
    const int qb   = (int)(gridDim.x - 1 - blockIdx.x);   // LPT
    const int h    = blockIdx.y;
    const int b    = blockIdx.z;

    const int headrow = (b * NH + h) * SSQ;

    if (tid == 0) {
        mbar_init(mb, 1);
        mbar_init(mb + 8, 1);
        mbar_init(mb + 16, 1);
    }
    __syncthreads();

    if (tid == 0) {
        mbar_expect(mb, 16384);
        tma2d(sb + AQ, &tmQ, 0, headrow + qb * 128, mb);
        mbar_expect(mb + 8, 16384);
        tma2d(sb + AKV,        &tmK, 0, headrow, mb + 8);
        tma2d(sb + AKV + 8192, &tmV, 0, headrow, mb + 8);
    }
    mbar_wait(mb, 0);

    uint32_t qf[4][4];
#pragma unroll
    for (int ks = 0; ks < 4; ks++) {
        int row = wid * 16 + (lane & 15);
        int col = ks * 16 + (lane >> 4) * 8;
        uint32_t off = sw128((uint32_t)(row * 128 + col * 2));
        ldm4(qf[ks], sb + AQ + off);
    }

    float m0 = -1e30f, m1 = -1e30f, l0 = 0.f, l1 = 0.f;
    float o[8][4];
#pragma unroll
    for (int df = 0; df < 8; df++)
#pragma unroll
        for (int e = 0; e < 4; e++) o[df][e] = 0.f;

    const int qi0 = qb * 128 + wid * 16 + (lane >> 2);
    const int qi1 = qi0 + 8;
    const int ntiles = 2 * qb + 2;

    for (int kt = 0; kt < ntiles; kt++) {
        mbar_wait(mb + 8 + (kt & 1) * 8, (kt >> 1) & 1);
        if (kt + 1 < ntiles && tid == 0) {
            const uint32_t st2 = sb + AKV + ((kt + 1) & 1) * 16384;
            const uint32_t m2 = mb + 8 + ((kt + 1) & 1) * 8;
            mbar_expect(m2, 16384);
            tma2d(st2,        &tmK, 0, headrow + (kt + 1) * 64, m2);
            tma2d(st2 + 8192, &tmV, 0, headrow + (kt + 1) * 64, m2);
        }

        const uint32_t sK = sb + AKV + (kt & 1) * 16384;
        const uint32_t sV = sK + 8192;

        float s[8][4];
#pragma unroll
        for (int nf = 0; nf < 8; nf++)
#pragma unroll
            for (int e = 0; e < 4; e++) s[nf][e] = 0.f;

#pragma unroll
        for (int ks = 0; ks < 4; ks++) {
#pragma unroll
            for (int nfp = 0; nfp < 4; nfp++) {
                int g = lane >> 3;
                int row = nfp * 16 + ((g >= 2) ? 8 : 0) + (lane & 7);
                int col = ks * 16 + ((g & 1) ? 8 : 0);
                uint32_t off = sw128((uint32_t)(row * 128 + col * 2));
                uint32_t bk[4];
                ldm4(bk, sK + off);
                mma16816f(s[2*nfp],   qf[ks], bk);
                mma16816f(s[2*nfp+1], qf[ks], bk + 2);
            }
        }

        if (kt >= 2 * qb) {
            int kbase = kt * 64 + (lane & 3) * 2;
#pragma unroll
            for (int nf = 0; nf < 8; nf++) {
                int kj = kbase + nf * 8;
                if (kj     > qi0) s[nf][0] = -1e30f;
                if (kj + 1 > qi0) s[nf][1] = -1e30f;
                if (kj     > qi1) s[nf][2] = -1e30f;
                if (kj + 1 > qi1) s[nf][3] = -1e30f;
            }
        }

        float rmax0 = -1e30f, rmax1 = -1e30f;
#pragma unroll
        for (int nf = 0; nf < 8; nf++) {
            rmax0 = fmaxf(rmax0, fmaxf(s[nf][0], s[nf][1]));
            rmax1 = fmaxf(rmax1, fmaxf(s[nf][2], s[nf][3]));
        }
        rmax0 = fmaxf(rmax0, __shfl_xor_sync(0xFFFFFFFFu, rmax0, 1));
        rmax0 = fmaxf(rmax0, __shfl_xor_sync(0xFFFFFFFFu, rmax0, 2));
        rmax1 = fmaxf(rmax1, __shfl_xor_sync(0xFFFFFFFFu, rmax1, 1));
        rmax1 = fmaxf(rmax1, __shfl_xor_sync(0xFFFFFFFFu, rmax1, 2));

        float mn0 = fmaxf(m0, rmax0);
        float mn1 = fmaxf(m1, rmax1);
        float corr0 = __expf(m0 - mn0);
        float corr1 = __expf(m1 - mn1);
        m0 = mn0; m1 = mn1;
        l0 *= corr0; l1 *= corr1;
#pragma unroll
        for (int df = 0; df < 8; df++) {
            o[df][0] *= corr0; o[df][1] *= corr0;
            o[df][2] *= corr1; o[df][3] *= corr1;
        }

        uint32_t p01[8], p23[8];
#pragma unroll
        for (int nf = 0; nf < 8; nf++) {
            float p0 = __expf(s[nf][0] - m0);
            float p1 = __expf(s[nf][1] - m0);
            float p2 = __expf(s[nf][2] - m1);
            float p3 = __expf(s[nf][3] - m1);
            l0 += p0 + p1;
            l1 += p2 + p3;
            p01[nf] = pack_f16x2(p0, p1);
            p23[nf] = pack_f16x2(p2, p3);
        }

#pragma unroll
        for (int ks = 0; ks < 4; ks++) {
            uint32_t aP[4] = {p01[2*ks], p23[2*ks], p01[2*ks+1], p23[2*ks+1]};
#pragma unroll
            for (int dfp = 0; dfp < 4; dfp++) {
                int g = lane >> 3;
                int row = ks * 16 + ((g & 1) ? 8 : 0) + (lane & 7);
                int col = dfp * 16 + ((g >= 2) ? 8 : 0);
                uint32_t off = sw128((uint32_t)(row * 128 + col * 2));
                uint32_t bv[4];
                ldm4t(bv, sV + off);
                mma16816f(o[2*dfp],   aP, bv);
                mma16816f(o[2*dfp+1], aP, bv + 2);
            }
        }
        __syncthreads();
    }

    l0 += __shfl_xor_sync(0xFFFFFFFFu, l0, 1);
    l0 += __shfl_xor_sync(0xFFFFFFFFu, l0, 2);
    l1 += __shfl_xor_sync(0xFFFFFFFFu, l1, 1);
    l1 += __shfl_xor_sync(0xFFFFFFFFu, l1, 2);
    float inv0 = 1.0f / l0;
    float inv1 = 1.0f / l1;

#pragma unroll
    for (int df = 0; df < 8; df++) {
        int col = h * HD + df * 8 + (lane & 3) * 2;
        size_t r0 = (size_t)(b * SSQ + qi0) * DIM + col;
        size_t r1 = (size_t)(b * SSQ + qi1) * DIM + col;
        *(__half2*)(g_ah + r0) = __floats2half2_rn(o[df][0] * inv0, o[df][1] * inv0);
        *(__half2*)(g_ah + r1) = __floats2half2_rn(o[df][2] * inv1, o[df][3] * inv1);
    }
}

// ---------------------------------------------------------------------------
// Host: tensor-map encoding via driver entry point (no -lcuda needed)
// ---------------------------------------------------------------------------
typedef CUresult (*EncodeFn)(
    CUtensorMap*, CUtensorMapDataType, cuuint32_t, void*,
    const cuuint64_t*, const cuuint64_t*, const cuuint32_t*, const cuuint32_t*,
    CUtensorMapInterleave, CUtensorMapSwizzle, CUtensorMapL2promotion,
    CUtensorMapFloatOOBfill);

static void enc2d(EncodeFn f, CUtensorMap* tm, void* p,
                  unsigned long long d0, unsigned long long d1,
                  unsigned long long strideB,
                  unsigned b0, unsigned b1)
{
    cuuint64_t dims[2] = {d0, d1};
    cuuint64_t st[1]   = {strideB};
    cuuint32_t box[2]  = {b0, b1};
    cuuint32_t es[2]   = {1, 1};
    f(tm, CU_TENSOR_MAP_DATA_TYPE_FLOAT16, 2, p, dims, st, box, es,
      CU_TENSOR_MAP_INTERLEAVE_NONE, CU_TENSOR_MAP_SWIZZLE_128B,
      CU_TENSOR_MAP_L2_PROMOTION_L2_128B, CU_TENSOR_MAP_FLOAT_OOB_FILL_NONE);
}

extern "C" void kernel_launch(void* const* d_in, const int* in_sizes, int n_in,
                              void* d_out, int out_size)
{
    const float* x = nullptr;
    const float* wqkv = nullptr;
    const float* wout = nullptr;
    for (int i = 0; i < n_in; i++) {
        long long n = in_sizes[i];
        if (n == (long long)MROWS * DIM)      x    = (const float*)d_in[i];
        else if (n == (long long)NQKV * DIM)  wqkv = (const float*)d_in[i];
        else if (n == (long long)DIM * DIM)   wout = (const float*)d_in[i];
    }
    if (!x || !wqkv || !wout) return;

    __half *ah, *wh, *vh2, *aq, *ak, *av;
    cudaGetSymbolAddress((void**)&ah,  g_ah);
    cudaGetSymbolAddress((void**)&wh,  g_wh);
    cudaGetSymbolAddress((void**)&vh2, g_vh2);
    cudaGetSymbolAddress((void**)&aq,  g_aq);
    cudaGetSymbolAddress((void**)&ak,  g_ak);
    cudaGetSymbolAddress((void**)&av,  g_av);

    EncodeFn enc = nullptr;
    {
        void* fn = nullptr;
        cudaDriverEntryPointQueryResult qr;
        cudaGetDriverEntryPoint("cuTensorMapEncodeTiled", &fn,
                                cudaEnableDefault, &qr);
        enc = (EncodeFn)fn;
    }
    if (!enc) return;

    CUtensorMap tmA, tmW, tmV2, tmQ, tmK, tmV;
    enc2d(enc, &tmA,  ah,  DIM, MROWS, DIM * 2, 64, 128);
    enc2d(enc, &tmW,  wh,  DIM, NQKV,  DIM * 2, 64, 128);
    enc2d(enc, &tmV2, vh2, DIM, DIM,   DIM * 2, 64, 128);
    enc2d(enc, &tmQ,  aq,  HD, HEADROWS, HD * 2, 64, 128);
    enc2d(enc, &tmK,  ak,  HD, HEADROWS, HD * 2, 64, 64);
    enc2d(enc, &tmV,  av,  HD, HEADROWS, HD * 2, 64, 64);

    cudaFuncSetAttribute(hgemm_tma, cudaFuncAttributeMaxDynamicSharedMemorySize,
                         GEMM_SMEM);
    cudaFuncSetAttribute(attn_tma, cudaFuncAttributeMaxDynamicSharedMemorySize,
                         ATTN_SMEM);

    // 0) fp16 operand prep + rope tables (needed by GEMM1 epilogue)
    cvt_f16<<<(MROWS * DIM / 4 + 255) / 256, 256>>>(x, ah, MROWS * DIM / 4);
    cvt_f16<<<(NQKV * DIM / 4 + 255) / 256, 256>>>(wqkv, wh, NQKV * DIM / 4);
    cvt_f16<<<(DIM * DIM / 4 + 255) / 256, 256>>>(wout, vh2, DIM * DIM / 4);
    rope_tables<<<(SSQ * 32) / 256, 256>>>();

    // 1) qkv GEMM with fused RoPE epilogue -> g_aq/g_ak/g_av
    dim3 g1(NQKV / 128, MROWS / 128);
    hgemm_tma<<<g1, 256, GEMM_SMEM>>>(tmA, tmW, nullptr, NQKV, DIM, 1);

    // 2) fp16 flash attention (TMA; writes fp16 A for GEMM2)
    dim3 ga(SSQ / 128, NH, BB);
    attn_tma<<<ga, 256, ATTN_SMEM>>>(tmQ, tmK, tmV);

    // 3) out = att @ Wout^T  (fp32 epilogue)
    dim3 g2(DIM / 128, MROWS / 128);
    hgemm_tma<<<g2, 256, GEMM_SMEM>>>(tmA, tmV2, (float*)d_out, DIM, DIM, 0);
}

// round 16
// speedup vs baseline: 11.3749x; 1.0188x over previous
#include <cuda_runtime.h>
#include <cuda.h>
#include <cuda_fp16.h>
#include <math.h>
#include <stdint.h>

#define BB 4
#define SSQ 2048
#define DIM 1024
#define NH 16
#define HD 64
#define MROWS (BB*SSQ)       // 8192
#define NQKV (3*DIM)         // 3072
#define HEADS_ELEMS ((size_t)BB * NH * SSQ * HD)   // 8.4M
#define HEADROWS ((size_t)BB * NH * SSQ)           // 131072

// ---------------- scratch (device globals; allocation-free) ----------------
__device__ float g_cos[SSQ * 32];
__device__ float g_sin[SSQ * 32];
// GEMM operands (single fp16 A x single fp16 B)
__device__ __half g_ah[(size_t)MROWS * DIM];    // x, later attention output
__device__ __half g_wh[(size_t)NQKV * DIM];
__device__ __half g_vh2[(size_t)DIM * DIM];
// attention operands (fp16, all single): Q (pre-scaled), K, V in [b,h,s,d]
__device__ __half g_aq[HEADS_ELEMS];
__device__ __half g_ak[HEADS_ELEMS];
__device__ __half g_av[HEADS_ELEMS];

// ---------------- PTX helpers (plain sm_103-safe) ---------------------------
__device__ __forceinline__ uint32_t smem_u32(const void* p) {
    uint32_t a;
    asm("{ .reg .u64 t; cvta.to.shared.u64 t, %1; cvt.u32.u64 %0, t; }"
        : "=r"(a) : "l"(p));
    return a;
}
__device__ __forceinline__ uint32_t sw128(uint32_t off) {
    return off ^ ((off >> 3) & 0x70);
}
__device__ __forceinline__ void mma16816f(float* c, const uint32_t* a, const uint32_t* b) {
    asm volatile(
        "mma.sync.aligned.m16n8k16.row.col.f32.f16.f16.f32 "
        "{%0,%1,%2,%3}, {%4,%5,%6,%7}, {%8,%9}, {%0,%1,%2,%3};"
        : "+f"(c[0]), "+f"(c[1]), "+f"(c[2]), "+f"(c[3])
        : "r"(a[0]), "r"(a[1]), "r"(a[2]), "r"(a[3]), "r"(b[0]), "r"(b[1]));
}
__device__ __forceinline__ void ldm4(uint32_t* r, uint32_t addr) {
    asm volatile("ldmatrix.sync.aligned.m8n8.x4.shared.b16 {%0,%1,%2,%3}, [%4];"
                 : "=r"(r[0]), "=r"(r[1]), "=r"(r[2]), "=r"(r[3]) : "r"(addr));
}
__device__ __forceinline__ void ldm4t(uint32_t* r, uint32_t addr) {
    asm volatile("ldmatrix.sync.aligned.m8n8.x4.trans.shared.b16 {%0,%1,%2,%3}, [%4];"
                 : "=r"(r[0]), "=r"(r[1]), "=r"(r[2]), "=r"(r[3]) : "r"(addr));
}
__device__ __forceinline__ uint32_t pack_f16x2(float lo, float hi) {
    uint32_t d;
    asm("cvt.rn.f16x2.f32 %0, %1, %2;" : "=r"(d) : "f"(hi), "f"(lo));
    return d;
}
__device__ __forceinline__ void mbar_init(uint32_t mbar, uint32_t cnt) {
    asm volatile("mbarrier.init.shared.b64 [%0], %1;" :: "r"(mbar), "r"(cnt) : "memory");
}
__device__ __forceinline__ void mbar_expect(uint32_t mbar, uint32_t bytes) {
    asm volatile("mbarrier.arrive.expect_tx.shared.b64 _, [%0], %1;"
                 :: "r"(mbar), "r"(bytes) : "memory");
}
__device__ __forceinline__ void mbar_wait(uint32_t mbar, uint32_t parity) {
    uint32_t done;
    asm volatile(
        "{\n\t.reg .pred p;\n\t"
        "mbarrier.try_wait.parity.acquire.cta.shared::cta.b64 p, [%1], %2;\n\t"
        "selp.b32 %0, 1, 0, p;\n\t}"
        : "=r"(done) : "r"(mbar), "r"(parity) : "memory");
    if (!done) {
        asm volatile(
            "{\n\t.reg .pred P1;\n\t"
            "W_%=:\n\t"
            "mbarrier.try_wait.parity.acquire.cta.shared::cta.b64 P1, [%0], %1, 0x989680;\n\t"
            "@P1 bra.uni D_%=;\n\t"
            "bra.uni W_%=;\n\t"
            "D_%=:\n\t}"
            :: "r"(mbar), "r"(parity) : "memory");
    }
}
__device__ __forceinline__ void tma2d(uint32_t dst, const CUtensorMap* tm,
                                      int x, int y, uint32_t mbar) {
    asm volatile(
        "cp.async.bulk.tensor.2d.shared::cta.global.tile.mbarrier::complete_tx::bytes "
        "[%0], [%1, {%2, %3}], [%4];"
        :: "r"(dst), "l"(tm), "r"(x), "r"(y), "r"(mbar) : "memory");
}

// ---------------------------------------------------------------------------
// fp32 -> fp16 convert
// ---------------------------------------------------------------------------
__global__ void cvt_f16(const float* __restrict__ in,
                        __half* __restrict__ out, int n4)
{
    int i = blockIdx.x * blockDim.x + threadIdx.x;
    if (i >= n4) return;
    float4 v = ((const float4*)in)[i];
    __half2* op = reinterpret_cast<__half2*>(out);
    op[2*i]   = __floats2half2_rn(v.x, v.y);
    op[2*i+1] = __floats2half2_rn(v.z, v.w);
}

// ---------------------------------------------------------------------------
// RoPE tables: fp32 sincosf of the fp32-rounded angle (error ~2 ulp, ~2e-7
// relative -- negligible vs the 6.6e-4 ledger; saves the fp64 pipe cost).
// ---------------------------------------------------------------------------
__global__ void rope_tables()
{
    int idx = blockIdx.x * blockDim.x + threadIdx.x;
    if (idx >= SSQ * 32) return;
    int s = idx >> 5;
    int i = idx & 31;
    double inv_d = exp(-(double)i * (9.210340371976184 / 32.0));
    float  ang_f = (float)s * (float)inv_d;
    float c, sn;
    sincosf(ang_f, &sn, &c);
    g_cos[idx] = c;
    g_sin[idx] = sn;
}

// ---------------------------------------------------------------------------
// TMA fp16 GEMM: C = A[M,K] @ B[N,K]^T (fp32 accum), single-term.
// 128x128 tile, 256 threads (8 warps: 4 M x 2 N, 32x64 each), 2 CTAs/SM.
// K-chunk 64, 2-stage TMA. mode 1 = fused RoPE epilogue. (verified R14)
// ---------------------------------------------------------------------------
#define GSTG 32768
#define GEMM_SMEM (2 * GSTG + 2048)

__global__ __launch_bounds__(256, 2) void hgemm_tma(
    const __grid_constant__ CUtensorMap tmA,
    const __grid_constant__ CUtensorMap tmB,
    float* __restrict__ C, int N, int K, int mode)
{
    extern __shared__ char dsm[];
    const uint32_t sraw = smem_u32(dsm);
    const uint32_t mb = sraw;
    const uint32_t sb = (sraw + 32 + 1023) & ~1023u;

    const int tid = threadIdx.x;
    const int lane = tid & 31;
    const int wid = tid >> 5;
    const int wm = wid & 3;
    const int wn = wid >> 2;
    const int bm = blockIdx.y * 128;
    const int bn = blockIdx.x * 128;

    float c[2][8][4];
#pragma unroll
    for (int i = 0; i < 2; i++)
#pragma unroll
        for (int nf = 0; nf < 8; nf++)
#pragma unroll
            for (int e = 0; e < 4; e++) c[i][nf][e] = 0.f;

    if (tid == 0) {
        mbar_init(mb, 1);
        mbar_init(mb + 8, 1);
    }
    __syncthreads();

    const int nch = K / 64;
    if (tid == 0) {
#pragma unroll
        for (int p = 0; p < 2; p++) {
            const uint32_t st = sb + p * GSTG;
            mbar_expect(mb + p * 8, GSTG);
            tma2d(st,         &tmA, p * 64, bm, mb + p * 8);
            tma2d(st + 16384, &tmB, p * 64, bn, mb + p * 8);
        }
    }

    for (int ck = 0; ck < nch; ck++) {
        const int slot = ck & 1;
        mbar_wait(mb + slot * 8, (uint32_t)((ck >> 1) & 1));

        const uint32_t st = sb + slot * GSTG;
#pragma unroll
        for (int ks = 0; ks < 4; ks++) {
            uint32_t af[2][4];
#pragma unroll
            for (int i = 0; i < 2; i++) {
                int row = wm * 32 + i * 16 + (lane & 15);
                int col = ks * 16 + (lane >> 4) * 8;
                uint32_t off = sw128((uint32_t)(row * 128 + col * 2));
                ldm4(af[i], st + off);
            }
#pragma unroll
            for (int nfp = 0; nfp < 4; nfp++) {
                int g = lane >> 3;
                int row = wn * 64 + nfp * 16 + ((g >= 2) ? 8 : 0) + (lane & 7);
                int col = ks * 16 + ((g & 1) ? 8 : 0);
                uint32_t off = sw128((uint32_t)(row * 128 + col * 2));
                uint32_t bh[4];
                ldm4(bh, st + 16384 + off);
#pragma unroll
                for (int i = 0; i < 2; i++) {
                    mma16816f(c[i][2*nfp],   af[i], bh);
                    mma16816f(c[i][2*nfp+1], af[i], bh + 2);
                }
            }
        }
        __syncthreads();
        if (ck + 2 < nch && tid == 0) {
            const uint32_t st2 = sb + slot * GSTG;
            mbar_expect(mb + slot * 8, GSTG);
            tma2d(st2,         &tmA, (ck + 2) * 64, bm, mb + slot * 8);
            tma2d(st2 + 16384, &tmB, (ck + 2) * 64, bn, mb + slot * 8);
        }
    }

    if (mode == 0) {
#pragma unroll
        for (int i = 0; i < 2; i++) {
#pragma unroll
            for (int nf = 0; nf < 8; nf++) {
                int row = bm + wm * 32 + i * 16 + (lane >> 2);
                int col = bn + wn * 64 + nf * 8 + (lane & 3) * 2;
                *(float2*)(C + (size_t)row * N + col) =
                    make_float2(c[i][nf][0], c[i][nf][1]);
                *(float2*)(C + (size_t)(row + 8) * N + col) =
                    make_float2(c[i][nf][2], c[i][nf][3]);
            }
        }
        return;
    }

    // ---- fused RoPE epilogue (qkv GEMM): warp owns exactly one head ----
    const int sec = bn / 1024;                          // 0=q, 1=k, 2=v
    const int h = ((bn & 1023) + wn * 64) >> 6;
#pragma unroll
    for (int i = 0; i < 2; i++) {
#pragma unroll
        for (int e2 = 0; e2 < 2; e2++) {
            int r = bm + wm * 32 + i * 16 + (lane >> 2) + e2 * 8;
            int b = r >> 11;
            int s = r & 2047;
            size_t obase = ((size_t)(b * NH + h) * SSQ + s) * HD;
#pragma unroll
            for (int nf = 0; nf < 4; nf++) {
                int ci = nf * 8 + (lane & 3) * 2;
                float x1a = c[i][nf][2*e2],     x1b = c[i][nf][2*e2+1];
                float x2a = c[i][nf+4][2*e2],   x2b = c[i][nf+4][2*e2+1];
                if (sec == 2) {
                    *(__half2*)(g_av + obase + ci)      = __floats2half2_rn(x1a, x1b);
                    *(__half2*)(g_av + obase + ci + 32) = __floats2half2_rn(x2a, x2b);
                } else {
                    float2 cc = *(const float2*)(g_cos + s * 32 + ci);
                    float2 ss = *(const float2*)(g_sin + s * 32 + ci);
                    float o1a = x1a * cc.x - x2a * ss.x;
                    float o1b = x1b * cc.y - x2b * ss.y;
                    float o2a = x1a * ss.x + x2a * cc.x;
                    float o2b = x1b * ss.y + x2b * cc.y;
                    if (sec == 0) {
                        o1a *= 0.125f; o1b *= 0.125f; o2a *= 0.125f; o2b *= 0.125f;
                        *(__half2*)(g_aq + obase + ci)      = __floats2half2_rn(o1a, o1b);
                        *(__half2*)(g_aq + obase + ci + 32) = __floats2half2_rn(o2a, o2b);
                    } else {
                        *(__half2*)(g_ak + obase + ci)      = __floats2half2_rn(o1a, o1b);
                        *(__half2*)(g_ak + obase + ci + 32) = __floats2half2_rn(o2a, o2b);
                    }
                }
            }
        }
    }
}

// ---------------------------------------------------------------------------
// TMA fp16 flash attention (causal), all-single-fp16 operands.
// NOW 2 CTAs/SM (__launch_bounds__(256,2)): co-resident CTAs hide each
// other's mbar_wait / softmax dependency stalls. Logic identical to R13/R14.
// ---------------------------------------------------------------------------
#define AQ  0
#define AKV 16384
#define ATTN_SMEM (49152 + 2048)

__global__ __launch_bounds__(256, 2) void attn_tma(
    const __grid_constant__ CUtensorMap tmQ,
    const __grid_constant__ CUtensorMap tmK,
    const __grid_constant__ CUtensorMap tmV)
{
    extern __shared__ char dsm[];
    const uint32_t sraw = smem_u32(dsm);
    const uint32_t mb = sraw;                        // 3 mbarriers: q, s0, s1
    const uint32_t sb = (sraw + 32 + 1023) & ~1023u;

    const int tid  = threadIdx.x;
    const int lane = tid & 31;
    const int wid  = tid >> 5;
    const int qb   = (int)(gridDim.x - 1 - blockIdx.x);   // LPT
    const int h    = blockIdx.y;
    const int b    = blockIdx.z;

    const int headrow = (b * NH + h) * SSQ;

    if (tid == 0) {
        mbar_init(mb, 1);
        mbar_init(mb + 8, 1);
        mbar_init(mb + 16, 1);
    }
    __syncthreads();

    if (tid == 0) {
        mbar_expect(mb, 16384);
        tma2d(sb + AQ, &tmQ, 0, headrow + qb * 128, mb);
        mbar_expect(mb + 8, 16384);
        tma2d(sb + AKV,        &tmK, 0, headrow, mb + 8);
        tma2d(sb + AKV + 8192, &tmV, 0, headrow, mb + 8);
    }
    mbar_wait(mb, 0);

    uint32_t qf[4][4];
#pragma unroll
    for (int ks = 0; ks < 4; ks++) {
        int row = wid * 16 + (lane & 15);
        int col = ks * 16 + (lane >> 4) * 8;
        uint32_t off = sw128((uint32_t)(row * 128 + col * 2));
        ldm4(qf[ks], sb + AQ + off);
    }

    float m0 = -1e30f, m1 = -1e30f, l0 = 0.f, l1 = 0.f;
    float o[8][4];
#pragma unroll
    for (int df = 0; df < 8; df++)
#pragma unroll
        for (int e = 0; e < 4; e++) o[df][e] = 0.f;

    const int qi0 = qb * 128 + wid * 16 + (lane >> 2);
    const int qi1 = qi0 + 8;
    const int ntiles = 2 * qb + 2;

    for (int kt = 0; kt < ntiles; kt++) {
        mbar_wait(mb + 8 + (kt & 1) * 8, (kt >> 1) & 1);
        if (kt + 1 < ntiles && tid == 0) {
            const uint32_t st2 = sb + AKV + ((kt + 1) & 1) * 16384;
            const uint32_t m2 = mb + 8 + ((kt + 1) & 1) * 8;
            mbar_expect(m2, 16384);
            tma2d(st2,        &tmK, 0, headrow + (kt + 1) * 64, m2);
            tma2d(st2 + 8192, &tmV, 0, headrow + (kt + 1) * 64, m2);
        }

        const uint32_t sK = sb + AKV + (kt & 1) * 16384;
        const uint32_t sV = sK + 8192;

        float s[8][4];
#pragma unroll
        for (int nf = 0; nf < 8; nf++)
#pragma unroll
            for (int e = 0; e < 4; e++) s[nf][e] = 0.f;

#pragma unroll
        for (int ks = 0; ks < 4; ks++) {
#pragma unroll
            for (int nfp = 0; nfp < 4; nfp++) {
                int g = lane >> 3;
                int row = nfp * 16 + ((g >= 2) ? 8 : 0) + (lane & 7);
                int col = ks * 16 + ((g & 1) ? 8 : 0);
                uint32_t off = sw128((uint32_t)(row * 128 + col * 2));
                uint32_t bk[4];
                ldm4(bk, sK + off);
                mma16816f(s[2*nfp],   qf[ks], bk);
                mma16816f(s[2*nfp+1], qf[ks], bk + 2);
            }
        }

        if (kt >= 2 * qb) {
            int kbase = kt * 64 + (lane & 3) * 2;
#pragma unroll
            for (int nf = 0; nf < 8; nf++) {
                int kj = kbase + nf * 8;
                if (kj     > qi0) s[nf][0] = -1e30f;
                if (kj + 1 > qi0) s[nf][1] = -1e30f;
                if (kj     > qi1) s[nf][2] = -1e30f;
                if (kj + 1 > qi1) s[nf][3] = -1e30f;
            }
        }

        float rmax0 = -1e30f, rmax1 = -1e30f;
#pragma unroll
        for (int nf = 0; nf < 8; nf++) {
            rmax0 = fmaxf(rmax0, fmaxf(s[nf][0], s[nf][1]));
            rmax1 = fmaxf(rmax1, fmaxf(s[nf][2], s[nf][3]));
        }
        rmax0 = fmaxf(rmax0, __shfl_xor_sync(0xFFFFFFFFu, rmax0, 1));
        rmax0 = fmaxf(rmax0, __shfl_xor_sync(0xFFFFFFFFu, rmax0, 2));
        rmax1 = fmaxf(rmax1, __shfl_xor_sync(0xFFFFFFFFu, rmax1, 1));
        rmax1 = fmaxf(rmax1, __shfl_xor_sync(0xFFFFFFFFu, rmax1, 2));

        float mn0 = fmaxf(m0, rmax0);
        float mn1 = fmaxf(m1, rmax1);
        float corr0 = __expf(m0 - mn0);
        float corr1 = __expf(m1 - mn1);
        m0 = mn0; m1 = mn1;
        l0 *= corr0; l1 *= corr1;
#pragma unroll
        for (int df = 0; df < 8; df++) {
            o[df][0] *= corr0; o[df][1] *= corr0;
            o[df][2] *= corr1; o[df][3] *= corr1;
        }

        uint32_t p01[8], p23[8];
#pragma unroll
        for (int nf = 0; nf < 8; nf++) {
            float p0 = __expf(s[nf][0] - m0);
            float p1 = __expf(s[nf][1] - m0);
            float p2 = __expf(s[nf][2] - m1);
            float p3 = __expf(s[nf][3] - m1);
            l0 += p0 + p1;
            l1 += p2 + p3;
            p01[nf] = pack_f16x2(p0, p1);
            p23[nf] = pack_f16x2(p2, p3);
        }

#pragma unroll
        for (int ks = 0; ks < 4; ks++) {
            uint32_t aP[4] = {p01[2*ks], p23[2*ks], p01[2*ks+1], p23[2*ks+1]};
#pragma unroll
            for (int dfp = 0; dfp < 4; dfp++) {
                int g = lane >> 3;
                int row = ks * 16 + ((g & 1) ? 8 : 0) + (lane & 7);
                int col = dfp * 16 + ((g >= 2) ? 8 : 0);
                uint32_t off = sw128((uint32_t)(row * 128 + col * 2));
                uint32_t bv[4];
                ldm4t(bv, sV + off);
                mma16816f(o[2*dfp],   aP, bv);
                mma16816f(o[2*dfp+1], aP, bv + 2);
            }
        }
        __syncthreads();
    }

    l0 += __shfl_xor_sync(0xFFFFFFFFu, l0, 1);
    l0 += __shfl_xor_sync(0xFFFFFFFFu, l0, 2);
    l1 += __shfl_xor_sync(0xFFFFFFFFu, l1, 1);
    l1 += __shfl_xor_sync(0xFFFFFFFFu, l1, 2);
    float inv0 = 1.0f / l0;
    float inv1 = 1.0f / l1;

#pragma unroll
    for (int df = 0; df < 8; df++) {
        int col = h * HD + df * 8 + (lane & 3) * 2;
        size_t r0 = (size_t)(b * SSQ + qi0) * DIM + col;
        size_t r1 = (size_t)(b * SSQ + qi1) * DIM + col;
        *(__half2*)(g_ah + r0) = __floats2half2_rn(o[df][0] * inv0, o[df][1] * inv0);
        *(__half2*)(g_ah + r1) = __floats2half2_rn(o[df][2] * inv1, o[df][3] * inv1);
    }
}

// ---------------------------------------------------------------------------
// Host: tensor-map encoding via driver entry point
// ---------------------------------------------------------------------------
typedef CUresult (*EncodeFn)(
    CUtensorMap*, CUtensorMapDataType, cuuint32_t, void*,
    const cuuint64_t*, const cuuint64_t*, const cuuint32_t*, const cuuint32_t*,
    CUtensorMapInterleave, CUtensorMapSwizzle, CUtensorMapL2promotion,
    CUtensorMapFloatOOBfill);

static void enc2d(EncodeFn f, CUtensorMap* tm, void* p,
                  unsigned long long d0, unsigned long long d1,
                  unsigned long long strideB,
                  unsigned b0, unsigned b1)
{
    cuuint64_t dims[2] = {d0, d1};
    cuuint64_t st[1]   = {strideB};
    cuuint32_t box[2]  = {b0, b1};
    cuuint32_t es[2]   = {1, 1};
    f(tm, CU_TENSOR_MAP_DATA_TYPE_FLOAT16, 2, p, dims, st, box, es,
      CU_TENSOR_MAP_INTERLEAVE_NONE, CU_TENSOR_MAP_SWIZZLE_128B,
      CU_TENSOR_MAP_L2_PROMOTION_L2_128B, CU_TENSOR_MAP_FLOAT_OOB_FILL_NONE);
}

extern "C" void kernel_launch(void* const* d_in, const int* in_sizes, int n_in,
                              void* d_out, int out_size)
{
    const float* x = nullptr;
    const float* wqkv = nullptr;
    const float* wout = nullptr;
    for (int i = 0; i < n_in; i++) {
        long long n = in_sizes[i];
        if (n == (long long)MROWS * DIM)      x    = (const float*)d_in[i];
        else if (n == (long long)NQKV * DIM)  wqkv = (const float*)d_in[i];
        else if (n == (long long)DIM * DIM)   wout = (const float*)d_in[i];
    }
    if (!x || !wqkv || !wout) return;

    __half *ah, *wh, *vh2, *aq, *ak, *av;
    cudaGetSymbolAddress((void**)&ah,  g_ah);
    cudaGetSymbolAddress((void**)&wh,  g_wh);
    cudaGetSymbolAddress((void**)&vh2, g_vh2);
    cudaGetSymbolAddress((void**)&aq,  g_aq);
    cudaGetSymbolAddress((void**)&ak,  g_ak);
    cudaGetSymbolAddress((void**)&av,  g_av);

    EncodeFn enc = nullptr;
    {
        void* fn = nullptr;
        cudaDriverEntryPointQueryResult qr;
        cudaGetDriverEntryPoint("cuTensorMapEncodeTiled", &fn,
                                cudaEnableDefault, &qr);
        enc = (EncodeFn)fn;
    }
    if (!enc) return;

    CUtensorMap tmA, tmW, tmV2, tmQ, tmK, tmV;
    enc2d(enc, &tmA,  ah,  DIM, MROWS, DIM * 2, 64, 128);
    enc2d(enc, &tmW,  wh,  DIM, NQKV,  DIM * 2, 64, 128);
    enc2d(enc, &tmV2, vh2, DIM, DIM,   DIM * 2, 64, 128);
    enc2d(enc, &tmQ,  aq,  HD, HEADROWS, HD * 2, 64, 128);
    enc2d(enc, &tmK,  ak,  HD, HEADROWS, HD * 2, 64, 64);
    enc2d(enc, &tmV,  av,  HD, HEADROWS, HD * 2, 64, 64);

    cudaFuncSetAttribute(hgemm_tma, cudaFuncAttributeMaxDynamicSharedMemorySize,
                         GEMM_SMEM);
    cudaFuncSetAttribute(attn_tma, cudaFuncAttributeMaxDynamicSharedMemorySize,
                         ATTN_SMEM);

    // 0) fp16 operand prep + rope tables
    cvt_f16<<<(MROWS * DIM / 4 + 255) / 256, 256>>>(x, ah, MROWS * DIM / 4);
    cvt_f16<<<(NQKV * DIM / 4 + 255) / 256, 256>>>(wqkv, wh, NQKV * DIM / 4);
    cvt_f16<<<(DIM * DIM / 4 + 255) / 256, 256>>>(wout, vh2, DIM * DIM / 4);
    rope_tables<<<(SSQ * 32) / 256, 256>>>();

    // 1) qkv GEMM with fused RoPE epilogue -> g_aq/g_ak/g_av
    dim3 g1(NQKV / 128, MROWS / 128);
    hgemm_tma<<<g1, 256, GEMM_SMEM>>>(tmA, tmW, nullptr, NQKV, DIM, 1);

    // 2) fp16 flash attention (2 CTAs/SM)
    dim3 ga(SSQ / 128, NH, BB);
    attn_tma<<<ga, 256, ATTN_SMEM>>>(tmQ, tmK, tmV);

    // 3) out = att @ Wout^T
    dim3 g2(DIM / 128, MROWS / 128);
    hgemm_tma<<<g2, 256, GEMM_SMEM>>>(tmA, tmV2, (float*)d_out, DIM, DIM, 0);
}

// round 17
// speedup vs baseline: 11.4294x; 1.0048x over previous
#include <cuda_runtime.h>
#include <cuda.h>
#include <cuda_fp16.h>
#include <math.h>
#include <stdint.h>

#define BB 4
#define SSQ 2048
#define DIM 1024
#define NH 16
#define HD 64
#define MROWS (BB*SSQ)       // 8192
#define NQKV (3*DIM)         // 3072
#define HEADS_ELEMS ((size_t)BB * NH * SSQ * HD)   // 8.4M
#define HEADROWS ((size_t)BB * NH * SSQ)           // 131072

// ---------------- scratch (device globals; allocation-free) ----------------
__device__ float g_cos[SSQ * 32];
__device__ float g_sin[SSQ * 32];
__device__ __half g_ah[(size_t)MROWS * DIM];    // x, later attention output
__device__ __half g_wh[(size_t)NQKV * DIM];
__device__ __half g_vh2[(size_t)DIM * DIM];
__device__ __half g_aq[HEADS_ELEMS];
__device__ __half g_ak[HEADS_ELEMS];
__device__ __half g_av[HEADS_ELEMS];

// ---------------- PTX helpers (plain sm_103-safe) ---------------------------
__device__ __forceinline__ uint32_t smem_u32(const void* p) {
    uint32_t a;
    asm("{ .reg .u64 t; cvta.to.shared.u64 t, %1; cvt.u32.u64 %0, t; }"
        : "=r"(a) : "l"(p));
    return a;
}
__device__ __forceinline__ uint32_t sw128(uint32_t off) {
    return off ^ ((off >> 3) & 0x70);
}
__device__ __forceinline__ void mma16816f(float* c, const uint32_t* a, const uint32_t* b) {
    asm volatile(
        "mma.sync.aligned.m16n8k16.row.col.f32.f16.f16.f32 "
        "{%0,%1,%2,%3}, {%4,%5,%6,%7}, {%8,%9}, {%0,%1,%2,%3};"
        : "+f"(c[0]), "+f"(c[1]), "+f"(c[2]), "+f"(c[3])
        : "r"(a[0]), "r"(a[1]), "r"(a[2]), "r"(a[3]), "r"(b[0]), "r"(b[1]));
}
__device__ __forceinline__ void ldm4(uint32_t* r, uint32_t addr) {
    asm volatile("ldmatrix.sync.aligned.m8n8.x4.shared.b16 {%0,%1,%2,%3}, [%4];"
                 : "=r"(r[0]), "=r"(r[1]), "=r"(r[2]), "=r"(r[3]) : "r"(addr));
}
__device__ __forceinline__ void ldm4t(uint32_t* r, uint32_t addr) {
    asm volatile("ldmatrix.sync.aligned.m8n8.x4.trans.shared.b16 {%0,%1,%2,%3}, [%4];"
                 : "=r"(r[0]), "=r"(r[1]), "=r"(r[2]), "=r"(r[3]) : "r"(addr));
}
__device__ __forceinline__ uint32_t pack_f16x2(float lo, float hi) {
    uint32_t d;
    asm("cvt.rn.f16x2.f32 %0, %1, %2;" : "=r"(d) : "f"(hi), "f"(lo));
    return d;
}
__device__ __forceinline__ void mbar_init(uint32_t mbar, uint32_t cnt) {
    asm volatile("mbarrier.init.shared.b64 [%0], %1;" :: "r"(mbar), "r"(cnt) : "memory");
}
__device__ __forceinline__ void mbar_expect(uint32_t mbar, uint32_t bytes) {
    asm volatile("mbarrier.arrive.expect_tx.shared.b64 _, [%0], %1;"
                 :: "r"(mbar), "r"(bytes) : "memory");
}
__device__ __forceinline__ void mbar_wait(uint32_t mbar, uint32_t parity) {
    uint32_t done;
    asm volatile(
        "{\n\t.reg .pred p;\n\t"
        "mbarrier.try_wait.parity.acquire.cta.shared::cta.b64 p, [%1], %2;\n\t"
        "selp.b32 %0, 1, 0, p;\n\t}"
        : "=r"(done) : "r"(mbar), "r"(parity) : "memory");
    if (!done) {
        asm volatile(
            "{\n\t.reg .pred P1;\n\t"
            "W_%=:\n\t"
            "mbarrier.try_wait.parity.acquire.cta.shared::cta.b64 P1, [%0], %1, 0x989680;\n\t"
            "@P1 bra.uni D_%=;\n\t"
            "bra.uni W_%=;\n\t"
            "D_%=:\n\t}"
            :: "r"(mbar), "r"(parity) : "memory");
    }
}
__device__ __forceinline__ void tma2d(uint32_t dst, const CUtensorMap* tm,
                                      int x, int y, uint32_t mbar) {
    asm volatile(
        "cp.async.bulk.tensor.2d.shared::cta.global.tile.mbarrier::complete_tx::bytes "
        "[%0], [%1, {%2, %3}], [%4];"
        :: "r"(dst), "l"(tm), "r"(x), "r"(y), "r"(mbar) : "memory");
}

// ---------------------------------------------------------------------------
// Fused fp32 -> fp16 convert for x, Wqkv, Wout (one launch)
// ---------------------------------------------------------------------------
#define NX4 (MROWS * DIM / 4)
#define NW4 (NQKV * DIM / 4)
#define NO4 (DIM * DIM / 4)

__global__ void cvt_all(const float* __restrict__ x,
                        const float* __restrict__ wq,
                        const float* __restrict__ wo)
{
    int i = blockIdx.x * blockDim.x + threadIdx.x;
    const float* src;
    __half* dst;
    int j;
    if (i < NX4)                { src = x;  dst = g_ah;  j = i; }
    else if (i < NX4 + NW4)     { src = wq; dst = g_wh;  j = i - NX4; }
    else if (i < NX4 + NW4 + NO4) { src = wo; dst = g_vh2; j = i - NX4 - NW4; }
    else return;
    float4 v = ((const float4*)src)[j];
    __half2* op = reinterpret_cast<__half2*>(dst);
    op[2*j]   = __floats2half2_rn(v.x, v.y);
    op[2*j+1] = __floats2half2_rn(v.z, v.w);
}

// ---------------------------------------------------------------------------
// RoPE tables (fp32 sincosf; verified R15)
// ---------------------------------------------------------------------------
__global__ void rope_tables()
{
    int idx = blockIdx.x * blockDim.x + threadIdx.x;
    if (idx >= SSQ * 32) return;
    int s = idx >> 5;
    int i = idx & 31;
    double inv_d = exp(-(double)i * (9.210340371976184 / 32.0));
    float  ang_f = (float)s * (float)inv_d;
    float c, sn;
    sincosf(ang_f, &sn, &c);
    g_cos[idx] = c;
    g_sin[idx] = sn;
}

// ---------------------------------------------------------------------------
// TMA fp16 GEMM: C = A[M,K] @ B[N,K]^T (fp32 accum), single-term.
// 128x128 tile, 256 threads (8 warps: 4 M x 2 N), 2 CTAs/SM.
// K-chunk 64, 3-stage TMA ring (prefetch distance 2).
// mode 1 = fused RoPE epilogue.
// ---------------------------------------------------------------------------
#define GSTG 32768
#define GEMM_SMEM (3 * GSTG + 1024)

__global__ __launch_bounds__(256, 2) void hgemm_tma(
    const __grid_constant__ CUtensorMap tmA,
    const __grid_constant__ CUtensorMap tmB,
    float* __restrict__ C, int N, int K, int mode)
{
    extern __shared__ char dsm[];
    const uint32_t sraw = smem_u32(dsm);
    const uint32_t mb = sraw;                             // 3 mbarriers
    const uint32_t sb = (sraw + 64 + 1023) & ~1023u;

    const int tid = threadIdx.x;
    const int lane = tid & 31;
    const int wid = tid >> 5;
    const int wm = wid & 3;
    const int wn = wid >> 2;
    const int bm = blockIdx.y * 128;
    const int bn = blockIdx.x * 128;

    float c[2][8][4];
#pragma unroll
    for (int i = 0; i < 2; i++)
#pragma unroll
        for (int nf = 0; nf < 8; nf++)
#pragma unroll
            for (int e = 0; e < 4; e++) c[i][nf][e] = 0.f;

    if (tid == 0) {
        mbar_init(mb, 1);
        mbar_init(mb + 8, 1);
        mbar_init(mb + 16, 1);
    }
    __syncthreads();

    const int nch = K / 64;
    if (tid == 0) {
#pragma unroll
        for (int p = 0; p < 2; p++) {
            const uint32_t st = sb + p * GSTG;
            mbar_expect(mb + p * 8, GSTG);
            tma2d(st,         &tmA, p * 64, bm, mb + p * 8);
            tma2d(st + 16384, &tmB, p * 64, bn, mb + p * 8);
        }
    }

    for (int ck = 0; ck < nch; ck++) {
        const int slot = ck % 3;
        mbar_wait(mb + slot * 8, (uint32_t)((ck / 3) & 1));
        // refill slot (ck+2)%3: its prior contents (chunk ck-1) were sealed
        // by the __syncthreads at the end of iteration ck-1.
        if (ck + 2 < nch && tid == 0) {
            const int s2 = (ck + 2) % 3;
            const uint32_t st2 = sb + s2 * GSTG;
            mbar_expect(mb + s2 * 8, GSTG);
            tma2d(st2,         &tmA, (ck + 2) * 64, bm, mb + s2 * 8);
            tma2d(st2 + 16384, &tmB, (ck + 2) * 64, bn, mb + s2 * 8);
        }

        const uint32_t st = sb + slot * GSTG;
#pragma unroll
        for (int ks = 0; ks < 4; ks++) {
            uint32_t af[2][4];
#pragma unroll
            for (int i = 0; i < 2; i++) {
                int row = wm * 32 + i * 16 + (lane & 15);
                int col = ks * 16 + (lane >> 4) * 8;
                uint32_t off = sw128((uint32_t)(row * 128 + col * 2));
                ldm4(af[i], st + off);
            }
#pragma unroll
            for (int nfp = 0; nfp < 4; nfp++) {
                int g = lane >> 3;
                int row = wn * 64 + nfp * 16 + ((g >= 2) ? 8 : 0) + (lane & 7);
                int col = ks * 16 + ((g & 1) ? 8 : 0);
                uint32_t off = sw128((uint32_t)(row * 128 + col * 2));
                uint32_t bh[4];
                ldm4(bh, st + 16384 + off);
#pragma unroll
                for (int i = 0; i < 2; i++) {
                    mma16816f(c[i][2*nfp],   af[i], bh);
                    mma16816f(c[i][2*nfp+1], af[i], bh + 2);
                }
            }
        }
        __syncthreads();   // seal this slot's reads before its future refill
    }

    if (mode == 0) {
#pragma unroll
        for (int i = 0; i < 2; i++) {
#pragma unroll
            for (int nf = 0; nf < 8; nf++) {
                int row = bm + wm * 32 + i * 16 + (lane >> 2);
                int col = bn + wn * 64 + nf * 8 + (lane & 3) * 2;
                *(float2*)(C + (size_t)row * N + col) =
                    make_float2(c[i][nf][0], c[i][nf][1]);
                *(float2*)(C + (size_t)(row + 8) * N + col) =
                    make_float2(c[i][nf][2], c[i][nf][3]);
            }
        }
        return;
    }

    // ---- fused RoPE epilogue (qkv GEMM): warp owns exactly one head ----
    const int sec = bn / 1024;                          // 0=q, 1=k, 2=v
    const int h = ((bn & 1023) + wn * 64) >> 6;
#pragma unroll
    for (int i = 0; i < 2; i++) {
#pragma unroll
        for (int e2 = 0; e2 < 2; e2++) {
            int r = bm + wm * 32 + i * 16 + (lane >> 2) + e2 * 8;
            int b = r >> 11;
            int s = r & 2047;
            size_t obase = ((size_t)(b * NH + h) * SSQ + s) * HD;
#pragma unroll
            for (int nf = 0; nf < 4; nf++) {
                int ci = nf * 8 + (lane & 3) * 2;
                float x1a = c[i][nf][2*e2],     x1b = c[i][nf][2*e2+1];
                float x2a = c[i][nf+4][2*e2],   x2b = c[i][nf+4][2*e2+1];
                if (sec == 2) {
                    *(__half2*)(g_av + obase + ci)      = __floats2half2_rn(x1a, x1b);
                    *(__half2*)(g_av + obase + ci + 32) = __floats2half2_rn(x2a, x2b);
                } else {
                    float2 cc = *(const float2*)(g_cos + s * 32 + ci);
                    float2 ss = *(const float2*)(g_sin + s * 32 + ci);
                    float o1a = x1a * cc.x - x2a * ss.x;
                    float o1b = x1b * cc.y - x2b * ss.y;
                    float o2a = x1a * ss.x + x2a * cc.x;
                    float o2b = x1b * ss.y + x2b * cc.y;
                    if (sec == 0) {
                        o1a *= 0.125f; o1b *= 0.125f; o2a *= 0.125f; o2b *= 0.125f;
                        *(__half2*)(g_aq + obase + ci)      = __floats2half2_rn(o1a, o1b);
                        *(__half2*)(g_aq + obase + ci + 32) = __floats2half2_rn(o2a, o2b);
                    } else {
                        *(__half2*)(g_ak + obase + ci)      = __floats2half2_rn(o1a, o1b);
                        *(__half2*)(g_ak + obase + ci + 32) = __floats2half2_rn(o2a, o2b);
                    }
                }
            }
        }
    }
}

// ---------------------------------------------------------------------------
// TMA fp16 flash attention (causal), all-single-fp16 operands, 2 CTAs/SM,
// 3-stage KV ring (prefetch distance 2). Arithmetic identical to R13-R15.
// smem: Q 16K | 3 KV stages x 16K = 64K (+align slack).
// ---------------------------------------------------------------------------
#define AQ  0
#define AKV 16384
#define ATTN_SMEM (65536 + 1024)

__global__ __launch_bounds__(256, 2) void attn_tma(
    const __grid_constant__ CUtensorMap tmQ,
    const __grid_constant__ CUtensorMap tmK,
    const __grid_constant__ CUtensorMap tmV)
{
    extern __shared__ char dsm[];
    const uint32_t sraw = smem_u32(dsm);
    const uint32_t mb = sraw;                 // mbarriers: q, kv0, kv1, kv2
    const uint32_t sb = (sraw + 64 + 1023) & ~1023u;

    const int tid  = threadIdx.x;
    const int lane = tid & 31;
    const int wid  = tid >> 5;
    const int qb   = (int)(gridDim.x - 1 - blockIdx.x);   // LPT
    const int h    = blockIdx.y;
    const int b    = blockIdx.z;

    const int headrow = (b * NH + h) * SSQ;

    if (tid == 0) {
        mbar_init(mb, 1);
        mbar_init(mb + 8, 1);
        mbar_init(mb + 16, 1);
        mbar_init(mb + 24, 1);
    }
    __syncthreads();

    const int ntiles = 2 * qb + 2;

    if (tid == 0) {
        mbar_expect(mb, 16384);
        tma2d(sb + AQ, &tmQ, 0, headrow + qb * 128, mb);
        // prologue: KV tiles 0 and 1 (ntiles >= 2 always)
#pragma unroll
        for (int p = 0; p < 2; p++) {
            const uint32_t st = sb + AKV + p * 16384;
            mbar_expect(mb + 8 + p * 8, 16384);
            tma2d(st,        &tmK, 0, headrow + p * 64, mb + 8 + p * 8);
            tma2d(st + 8192, &tmV, 0, headrow + p * 64, mb + 8 + p * 8);
        }
    }
    mbar_wait(mb, 0);

    uint32_t qf[4][4];
#pragma unroll
    for (int ks = 0; ks < 4; ks++) {
        int row = wid * 16 + (lane & 15);
        int col = ks * 16 + (lane >> 4) * 8;
        uint32_t off = sw128((uint32_t)(row * 128 + col * 2));
        ldm4(qf[ks], sb + AQ + off);
    }

    float m0 = -1e30f, m1 = -1e30f, l0 = 0.f, l1 = 0.f;
    float o[8][4];
#pragma unroll
    for (int df = 0; df < 8; df++)
#pragma unroll
        for (int e = 0; e < 4; e++) o[df][e] = 0.f;

    const int qi0 = qb * 128 + wid * 16 + (lane >> 2);
    const int qi1 = qi0 + 8;

    for (int kt = 0; kt < ntiles; kt++) {
        const int slot = kt % 3;
        mbar_wait(mb + 8 + slot * 8, (uint32_t)((kt / 3) & 1));
        if (kt + 2 < ntiles && tid == 0) {
            const int s2 = (kt + 2) % 3;
            const uint32_t st2 = sb + AKV + s2 * 16384;
            mbar_expect(mb + 8 + s2 * 8, 16384);
            tma2d(st2,        &tmK, 0, headrow + (kt + 2) * 64, mb + 8 + s2 * 8);
            tma2d(st2 + 8192, &tmV, 0, headrow + (kt + 2) * 64, mb + 8 + s2 * 8);
        }

        const uint32_t sK = sb + AKV + slot * 16384;
        const uint32_t sV = sK + 8192;

        float s[8][4];
#pragma unroll
        for (int nf = 0; nf < 8; nf++)
#pragma unroll
            for (int e = 0; e < 4; e++) s[nf][e] = 0.f;

#pragma unroll
        for (int ks = 0; ks < 4; ks++) {
#pragma unroll
            for (int nfp = 0; nfp < 4; nfp++) {
                int g = lane >> 3;
                int row = nfp * 16 + ((g >= 2) ? 8 : 0) + (lane & 7);
                int col = ks * 16 + ((g & 1) ? 8 : 0);
                uint32_t off = sw128((uint32_t)(row * 128 + col * 2));
                uint32_t bk[4];
                ldm4(bk, sK + off);
                mma16816f(s[2*nfp],   qf[ks], bk);
                mma16816f(s[2*nfp+1], qf[ks], bk + 2);
            }
        }

        if (kt >= 2 * qb) {
            int kbase = kt * 64 + (lane & 3) * 2;
#pragma unroll
            for (int nf = 0; nf < 8; nf++) {
                int kj = kbase + nf * 8;
                if (kj     > qi0) s[nf][0] = -1e30f;
                if (kj + 1 > qi0) s[nf][1] = -1e30f;
                if (kj     > qi1) s[nf][2] = -1e30f;
                if (kj + 1 > qi1) s[nf][3] = -1e30f;
            }
        }

        float rmax0 = -1e30f, rmax1 = -1e30f;
#pragma unroll
        for (int nf = 0; nf < 8; nf++) {
            rmax0 = fmaxf(rmax0, fmaxf(s[nf][0], s[nf][1]));
            rmax1 = fmaxf(rmax1, fmaxf(s[nf][2], s[nf][3]));
        }
        rmax0 = fmaxf(rmax0, __shfl_xor_sync(0xFFFFFFFFu, rmax0, 1));
        rmax0 = fmaxf(rmax0, __shfl_xor_sync(0xFFFFFFFFu, rmax0, 2));
        rmax1 = fmaxf(rmax1, __shfl_xor_sync(0xFFFFFFFFu, rmax1, 1));
        rmax1 = fmaxf(rmax1, __shfl_xor_sync(0xFFFFFFFFu, rmax1, 2));

        float mn0 = fmaxf(m0, rmax0);
        float mn1 = fmaxf(m1, rmax1);
        float corr0 = __expf(m0 - mn0);
        float corr1 = __expf(m1 - mn1);
        m0 = mn0; m1 = mn1;
        l0 *= corr0; l1 *= corr1;
#pragma unroll
        for (int df = 0; df < 8; df++) {
            o[df][0] *= corr0; o[df][1] *= corr0;
            o[df][2] *= corr1; o[df][3] *= corr1;
        }

        uint32_t p01[8], p23[8];
#pragma unroll
        for (int nf = 0; nf < 8; nf++) {
            float p0 = __expf(s[nf][0] - m0);
            float p1 = __expf(s[nf][1] - m0);
            float p2 = __expf(s[nf][2] - m1);
            float p3 = __expf(s[nf][3] - m1);
            l0 += p0 + p1;
            l1 += p2 + p3;
            p01[nf] = pack_f16x2(p0, p1);
            p23[nf] = pack_f16x2(p2, p3);
        }

#pragma unroll
        for (int ks = 0; ks < 4; ks++) {
            uint32_t aP[4] = {p01[2*ks], p23[2*ks], p01[2*ks+1], p23[2*ks+1]};
#pragma unroll
            for (int dfp = 0; dfp < 4; dfp++) {
                int g = lane >> 3;
                int row = ks * 16 + ((g & 1) ? 8 : 0) + (lane & 7);
                int col = dfp * 16 + ((g >= 2) ? 8 : 0);
                uint32_t off = sw128((uint32_t)(row * 128 + col * 2));
                uint32_t bv[4];
                ldm4t(bv, sV + off);
                mma16816f(o[2*dfp],   aP, bv);
                mma16816f(o[2*dfp+1], aP, bv + 2);
            }
        }
        __syncthreads();   // seal this slot's reads before its future refill
    }

    l0 += __shfl_xor_sync(0xFFFFFFFFu, l0, 1);
    l0 += __shfl_xor_sync(0xFFFFFFFFu, l0, 2);
    l1 += __shfl_xor_sync(0xFFFFFFFFu, l1, 1);
    l1 += __shfl_xor_sync(0xFFFFFFFFu, l1, 2);
    float inv0 = 1.0f / l0;
    float inv1 = 1.0f / l1;

#pragma unroll
    for (int df = 0; df < 8; df++) {
        int col = h * HD + df * 8 + (lane & 3) * 2;
        size_t r0 = (size_t)(b * SSQ + qi0) * DIM + col;
        size_t r1 = (size_t)(b * SSQ + qi1) * DIM + col;
        *(__half2*)(g_ah + r0) = __floats2half2_rn(o[df][0] * inv0, o[df][1] * inv0);
        *(__half2*)(g_ah + r1) = __floats2half2_rn(o[df][2] * inv1, o[df][3] * inv1);
    }
}

// ---------------------------------------------------------------------------
// Host: tensor-map encoding via driver entry point
// ---------------------------------------------------------------------------
typedef CUresult (*EncodeFn)(
    CUtensorMap*, CUtensorMapDataType, cuuint32_t, void*,
    const cuuint64_t*, const cuuint64_t*, const cuuint32_t*, const cuuint32_t*,
    CUtensorMapInterleave, CUtensorMapSwizzle, CUtensorMapL2promotion,
    CUtensorMapFloatOOBfill);

static void enc2d(EncodeFn f, CUtensorMap* tm, void* p,
                  unsigned long long d0, unsigned long long d1,
                  unsigned long long strideB,
                  unsigned b0, unsigned b1)
{
    cuuint64_t dims[2] = {d0, d1};
    cuuint64_t st[1]   = {strideB};
    cuuint32_t box[2]  = {b0, b1};
    cuuint32_t es[2]   = {1, 1};
    f(tm, CU_TENSOR_MAP_DATA_TYPE_FLOAT16, 2, p, dims, st, box, es,
      CU_TENSOR_MAP_INTERLEAVE_NONE, CU_TENSOR_MAP_SWIZZLE_128B,
      CU_TENSOR_MAP_L2_PROMOTION_L2_128B, CU_TENSOR_MAP_FLOAT_OOB_FILL_NONE);
}

extern "C" void kernel_launch(void* const* d_in, const int* in_sizes, int n_in,
                              void* d_out, int out_size)
{
    const float* x = nullptr;
    const float* wqkv = nullptr;
    const float* wout = nullptr;
    for (int i = 0; i < n_in; i++) {
        long long n = in_sizes[i];
        if (n == (long long)MROWS * DIM)      x    = (const float*)d_in[i];
        else if (n == (long long)NQKV * DIM)  wqkv = (const float*)d_in[i];
        else if (n == (long long)DIM * DIM)   wout = (const float*)d_in[i];
    }
    if (!x || !wqkv || !wout) return;

    __half *ah, *wh, *vh2, *aq, *ak, *av;
    cudaGetSymbolAddress((void**)&ah,  g_ah);
    cudaGetSymbolAddress((void**)&wh,  g_wh);
    cudaGetSymbolAddress((void**)&vh2, g_vh2);
    cudaGetSymbolAddress((void**)&aq,  g_aq);
    cudaGetSymbolAddress((void**)&ak,  g_ak);
    cudaGetSymbolAddress((void**)&av,  g_av);

    EncodeFn enc = nullptr;
    {
        void* fn = nullptr;
        cudaDriverEntryPointQueryResult qr;
        cudaGetDriverEntryPoint("cuTensorMapEncodeTiled", &fn,
                                cudaEnableDefault, &qr);
        enc = (EncodeFn)fn;
    }
    if (!enc) return;

    CUtensorMap tmA, tmW, tmV2, tmQ, tmK, tmV;
    enc2d(enc, &tmA,  ah,  DIM, MROWS, DIM * 2, 64, 128);
    enc2d(enc, &tmW,  wh,  DIM, NQKV,  DIM * 2, 64, 128);
    enc2d(enc, &tmV2, vh2, DIM, DIM,   DIM * 2, 64, 128);
    enc2d(enc, &tmQ,  aq,  HD, HEADROWS, HD * 2, 64, 128);
    enc2d(enc, &tmK,  ak,  HD, HEADROWS, HD * 2, 64, 64);
    enc2d(enc, &tmV,  av,  HD, HEADROWS, HD * 2, 64, 64);

    cudaFuncSetAttribute(hgemm_tma, cudaFuncAttributeMaxDynamicSharedMemorySize,
                         GEMM_SMEM);
    cudaFuncSetAttribute(attn_tma, cudaFuncAttributeMaxDynamicSharedMemorySize,
                         ATTN_SMEM);

    // 0) fused fp16 operand prep + rope tables
    cvt_all<<<(NX4 + NW4 + NO4 + 255) / 256, 256>>>(x, wqkv, wout);
    rope_tables<<<(SSQ * 32) / 256, 256>>>();

    // 1) qkv GEMM with fused RoPE epilogue -> g_aq/g_ak/g_av
    dim3 g1(NQKV / 128, MROWS / 128);
    hgemm_tma<<<g1, 256, GEMM_SMEM>>>(tmA, tmW, nullptr, NQKV, DIM, 1);

    // 2) fp16 flash attention (2 CTAs/SM, 3-stage KV)
    dim3 ga(SSQ / 128, NH, BB);
    attn_tma<<<ga, 256, ATTN_SMEM>>>(tmQ, tmK, tmV);

    // 3) out = att @ Wout^T
    dim3 g2(DIM / 128, MROWS / 128);
    hgemm_tma<<<g2, 256, GEMM_SMEM>>>(tmA, tmV2, (float*)d_out, DIM, DIM, 0);
}